// round 11
// baseline (speedup 1.0000x reference)
#include <cuda_runtime.h>
#include <cuda_bf16.h>
#include <math.h>
#include <stdint.h>

// ---------------- problem constants ----------------
#define BB   4
#define TT   256
#define TAA  1500
#define DD   768
#define HH   12
#define LL   12
#define VV   51865
#define DHH  64
#define BT   (BB*TT)          // 1024
#define SCALE_Q 0.125f
#define BTAD ((size_t)BB*TAA*DD)
#define NSPLIT 4

// ---------------- scratch ----------------
__device__ float g_x  [BT*DD];
__device__ float g_h  [BT*DD];
__device__ float g_q  [BT*DD];
__device__ float g_o  [BT*DD];
__device__ float g_ckall[(size_t)LL*BTAD];
__device__ float g_cvall[(size_t)LL*BTAD];
__device__ float g_hid[(size_t)BT*4*DD];
__device__ float g_opart[(size_t)NSPLIT*BT*DD];
__device__ float2 g_msum[(size_t)NSPLIT*BB*HH*TT];

// ---------------- shared helpers ----------------
__device__ __forceinline__ uint32_t pack_bf(float a, float b) {
    __nv_bfloat162 t;
    t.x = __float2bfloat16_rn(a);
    t.y = __float2bfloat16_rn(b);
    return *(uint32_t*)&t;
}

__device__ __forceinline__ void split_pair(float2 v, uint32_t& hi, uint32_t& lo) {
    __nv_bfloat16 hx = __float2bfloat16_rn(v.x);
    __nv_bfloat16 hy = __float2bfloat16_rn(v.y);
    hi = pack_bf(v.x, v.y);
    lo = pack_bf(v.x - __bfloat162float(hx), v.y - __bfloat162float(hy));
}

__device__ __forceinline__ uint32_t lo_pack(float a, float b) {
    float ra = a - __bfloat162float(__float2bfloat16_rn(a));
    float rb = b - __bfloat162float(__float2bfloat16_rn(b));
    return pack_bf(ra, rb);
}

__device__ __forceinline__ void mma_bf16(float* c, const uint32_t* a, const uint32_t* b) {
    asm volatile(
        "mma.sync.aligned.m16n8k16.row.col.f32.bf16.bf16.f32 "
        "{%0,%1,%2,%3}, {%4,%5,%6,%7}, {%8,%9}, {%0,%1,%2,%3};"
        : "+f"(c[0]), "+f"(c[1]), "+f"(c[2]), "+f"(c[3])
        : "r"(a[0]), "r"(a[1]), "r"(a[2]), "r"(a[3]), "r"(b[0]), "r"(b[1]));
}

__device__ __forceinline__ void ldsm_x4(uint32_t* r, uint32_t addr) {
    asm volatile(
        "ldmatrix.sync.aligned.m8n8.x4.shared.b16 {%0,%1,%2,%3}, [%4];"
        : "=r"(r[0]), "=r"(r[1]), "=r"(r[2]), "=r"(r[3]) : "r"(addr));
}

// ---------------- bf16 split GEMM (3-term) + split-K, ldmatrix frag loads ----------------
// BIG=0: 128x64 tile, 256 thr, TBK=32. BIG=1: 128x128 tile, 512 thr, TBK=64.
// B smem unified n-major [n][ALD] for both NN and NT.
struct GemmP {
    const float *A, *B0, *B1, *B2;
    float *C0, *C1, *C2;
    const float *bias0, *bias1, *bias2;
    int M, N, K, lda, ldb, ldc, Hd, segW, act, splitK, kc;
    long sA0, sA1, sB0, sB1, sC0, sC1, sBias;
    float s0, s1, s2;
};

template <int NT, int BIG>
__global__ __launch_bounds__(BIG ? 512 : 256, BIG ? 1 : 2) void gemm_bf3_kernel(GemmP p)
{
    constexpr int BN   = BIG ? 128 : 64;
    constexpr int NTHR = BIG ? 512 : 256;
    constexpr int TBKv = BIG ? 64 : 32;
    constexpr int KP   = TBKv / 2;            // bf16x2 pairs per row
    constexpr int ALD  = BIG ? 36 : 20;       // smem stride (u32), conflict-free for LDSM
    constexpr int AIT  = 128 * KP / NTHR;     // 8
    constexpr int BIT  = BN * KP / NTHR;      // BIG 8, small 4

    __shared__ uint32_t AH[128][ALD];
    __shared__ uint32_t AL[128][ALD];
    __shared__ uint32_t BH[BN * ALD];
    __shared__ uint32_t BL[BN * ALD];

    int z = blockIdx.z;
    int sk = z % p.splitK;
    int zz = z / p.splitK;
    int zb = zz / p.Hd, zh = zz % p.Hd;
    int bm = blockIdx.y * 128, bn = blockIdx.x * BN;
    int seg = bn / p.segW;
    int bnl = bn - seg * p.segW;

    const float* A = p.A + zb * p.sA0 + zh * p.sA1;
    const float* B = (seg == 0 ? p.B0 : seg == 1 ? p.B1 : p.B2) + zb * p.sB0 + zh * p.sB1;
    float* C = (seg == 0 ? p.C0 : seg == 1 ? p.C1 : p.C2) + zb * p.sC0 + zh * p.sC1;
    const float* bias = (seg == 0 ? p.bias0 : seg == 1 ? p.bias1 : p.bias2);
    if (bias) bias += zh * p.sBias;
    float scl = seg == 0 ? p.s0 : seg == 1 ? p.s1 : p.s2;
    bool atom = p.splitK > 1;

    int M = p.M, N = p.N;
    int lda = p.lda, ldb = p.ldb, ldc = p.ldc;
    int kstart = sk * p.kc;
    int kend = min(p.K, kstart + p.kc);

    int tid  = threadIdx.x;
    int lane = tid & 31;
    int warp = tid >> 5;
    int g    = lane >> 2;
    int tig  = lane & 3;
    int m0w  = (warp & 3) * 32;
    int n0w  = (warp >> 2) * 32;

    // ldmatrix byte offsets (warp-constant)
    uint32_t aBaseH = (uint32_t)__cvta_generic_to_shared(&AH[0][0]);
    uint32_t aBaseL = (uint32_t)__cvta_generic_to_shared(&AL[0][0]);
    uint32_t bBaseH = (uint32_t)__cvta_generic_to_shared(&BH[0]);
    uint32_t bBaseL = (uint32_t)__cvta_generic_to_shared(&BL[0]);
    uint32_t aoff = ((m0w + (lane & 15)) * ALD + ((lane >> 4) << 2)) * 4u;
    uint32_t boff = ((n0w + (lane & 7) + ((lane >> 4) << 3)) * ALD + ((lane >> 3) & 1) * 4) * 4u;
    const uint32_t MSTEP = 16u * ALD * 4u;

    float c[2][4][4];
#pragma unroll
    for (int mi = 0; mi < 2; mi++)
#pragma unroll
        for (int ni = 0; ni < 4; ni++)
#pragma unroll
            for (int e = 0; e < 4; e++) c[mi][ni][e] = 0.f;

    int iters = (kend - kstart + TBKv - 1) / TBKv;
    float2 ra[AIT], rb[BIT];

    // --- prefetch tile 0 ---
    {
        int kk = kstart;
#pragma unroll
        for (int i = 0; i < AIT; i++) {
            int pidx = i * NTHR + tid;
            int r = pidx / KP, kp = pidx % KP;
            int gr = bm + r, k0 = kk + 2 * kp;
            float2 v = {0.f, 0.f};
            if (gr < M) {
                if (k0 + 1 < kend)      v = *(const float2*)&A[(long)gr * lda + k0];
                else if (k0 < kend)     v.x = A[(long)gr * lda + k0];
            }
            ra[i] = v;
        }
#pragma unroll
        for (int i = 0; i < BIT; i++) {
            int pidx = i * NTHR + tid;
            float2 v = {0.f, 0.f};
            if (NT) {
                int n = pidx / KP, kp = pidx % KP;
                int k0 = kk + 2 * kp;
                if (bn + n < N) {
                    long base = (long)(bnl + n) * ldb;
                    if (k0 + 1 < kend)  v = *(const float2*)&B[base + k0];
                    else if (k0 < kend) v.x = B[base + k0];
                }
            } else {
                int n = pidx % BN, kp = pidx / BN;
                int k0 = kk + 2 * kp;
                if (bn + n < N) {
                    if (k0 < kend)     v.x = B[(long)k0 * ldb + bnl + n];
                    if (k0 + 1 < kend) v.y = B[(long)(k0 + 1) * ldb + bnl + n];
                }
            }
            rb[i] = v;
        }
    }

    for (int it = 0; it < iters; it++) {
#pragma unroll
        for (int i = 0; i < AIT; i++) {
            int pidx = i * NTHR + tid;
            int r = pidx / KP, kp = pidx % KP;
            split_pair(ra[i], AH[r][kp], AL[r][kp]);
        }
#pragma unroll
        for (int i = 0; i < BIT; i++) {
            int pidx = i * NTHR + tid;
            uint32_t hi, lo;
            split_pair(rb[i], hi, lo);
            int n, kp;
            if (NT) { n = pidx / KP; kp = pidx % KP; }
            else    { n = pidx % BN; kp = pidx / BN; }
            BH[n * ALD + kp] = hi;
            BL[n * ALD + kp] = lo;
        }
        __syncthreads();

        if (it + 1 < iters) {
            int kk = kstart + (it + 1) * TBKv;
#pragma unroll
            for (int i = 0; i < AIT; i++) {
                int pidx = i * NTHR + tid;
                int r = pidx / KP, kp = pidx % KP;
                int gr = bm + r, k0 = kk + 2 * kp;
                float2 v = {0.f, 0.f};
                if (gr < M) {
                    if (k0 + 1 < kend)  v = *(const float2*)&A[(long)gr * lda + k0];
                    else if (k0 < kend) v.x = A[(long)gr * lda + k0];
                }
                ra[i] = v;
            }
#pragma unroll
            for (int i = 0; i < BIT; i++) {
                int pidx = i * NTHR + tid;
                float2 v = {0.f, 0.f};
                if (NT) {
                    int n = pidx / KP, kp = pidx % KP;
                    int k0 = kk + 2 * kp;
                    if (bn + n < N) {
                        long base = (long)(bnl + n) * ldb;
                        if (k0 + 1 < kend)  v = *(const float2*)&B[base + k0];
                        else if (k0 < kend) v.x = B[base + k0];
                    }
                } else {
                    int n = pidx % BN, kp = pidx / BN;
                    int k0 = kk + 2 * kp;
                    if (bn + n < N) {
                        if (k0 < kend)     v.x = B[(long)k0 * ldb + bnl + n];
                        if (k0 + 1 < kend) v.y = B[(long)(k0 + 1) * ldb + bnl + n];
                    }
                }
                rb[i] = v;
            }
        }

#pragma unroll
        for (int h = 0; h < TBKv / 16; h++) {
            uint32_t kbb = (uint32_t)h * 32u;      // 8 pairs * 4 bytes
            uint32_t aH4[2][4], aL4[2][4];
            ldsm_x4(aH4[0], aBaseH + aoff + kbb);
            ldsm_x4(aH4[1], aBaseH + aoff + MSTEP + kbb);
            ldsm_x4(aL4[0], aBaseL + aoff + kbb);
            ldsm_x4(aL4[1], aBaseL + aoff + MSTEP + kbb);
            uint32_t bHq[2][4], bLq[2][4];
            ldsm_x4(bHq[0], bBaseH + boff + kbb);
            ldsm_x4(bHq[1], bBaseH + boff + MSTEP + kbb);
            ldsm_x4(bLq[0], bBaseL + boff + kbb);
            ldsm_x4(bLq[1], bBaseL + boff + MSTEP + kbb);
#pragma unroll
            for (int mi = 0; mi < 2; mi++)
#pragma unroll
                for (int ni = 0; ni < 4; ni++) {
                    const uint32_t* bh = &bHq[ni >> 1][(ni & 1) * 2];
                    const uint32_t* bl = &bLq[ni >> 1][(ni & 1) * 2];
                    mma_bf16(c[mi][ni], aH4[mi], bl);
                    mma_bf16(c[mi][ni], aL4[mi], bh);
                    mma_bf16(c[mi][ni], aH4[mi], bh);
                }
        }
        __syncthreads();
    }

#pragma unroll
    for (int mi = 0; mi < 2; mi++) {
#pragma unroll
        for (int ni = 0; ni < 4; ni++) {
#pragma unroll
            for (int e = 0; e < 4; e++) {
                int row = bm + m0w + mi * 16 + g + ((e >= 2) ? 8 : 0);
                int gcol = bn + n0w + ni * 8 + tig * 2 + (e & 1);
                if (row >= M || gcol >= N) continue;
                int lc = gcol - seg * p.segW;
                float v = c[mi][ni][e];
                if (bias && (!atom || sk == 0)) v += bias[lc];
                v *= scl;
                long ci = (long)row * ldc + lc;
                if (atom) {
                    atomicAdd(&C[ci], v);
                } else {
                    if (p.act == 1) v = 0.5f * v * (1.f + erff(v * 0.70710678118654752f));
                    C[ci] = v;
                }
            }
        }
    }
}

// ---------------- fused flash attention (optionally KV-split), ldmatrix frags ----------------
__global__ __launch_bounds__(128) void flash_kernel(
    const float* __restrict__ Qb, const float* __restrict__ Kb,
    const float* __restrict__ Vb, float* __restrict__ Ob,
    float* __restrict__ mir, int lenKV, long kvBStride, int causal,
    float* __restrict__ Opart, float2* __restrict__ Msum, int kvChunk)
{
    __shared__ uint32_t Kh[64][36], Kl[64][36];
    __shared__ uint32_t Vh[64][36], Vl[64][36];

    int mt = blockIdx.x;
    int by = blockIdx.y;
    int sp = blockIdx.z;
    int b = by / HH, hh = by % HH;

    int kvStart = sp * kvChunk;
    int kvEnd = min(lenKV, kvStart + kvChunk);

    const float* Q = Qb + ((long)b * TT + mt * 64) * DD + hh * DHH;
    const float* K = Kb + (long)b * kvBStride + hh * DHH;
    const float* V = Vb + (long)b * kvBStride + hh * DHH;
    float* Mr = (mir && b == 0)
              ? mir + (size_t)hh * TT * TAA + (size_t)mt * 64 * TAA : nullptr;

    int tid = threadIdx.x;
    int lane = tid & 31, warp = tid >> 5;
    int g = lane >> 2, tig = lane & 3;
    int m0w = warp * 16;

    uint32_t kBaseH = (uint32_t)__cvta_generic_to_shared(&Kh[0][0]);
    uint32_t kBaseL = (uint32_t)__cvta_generic_to_shared(&Kl[0][0]);
    uint32_t vBaseH = (uint32_t)__cvta_generic_to_shared(&Vh[0][0]);
    uint32_t vBaseL = (uint32_t)__cvta_generic_to_shared(&Vl[0][0]);
    uint32_t foff = (((lane & 7) + ((lane >> 4) << 3)) * 36 + ((lane >> 3) & 1) * 4) * 4u;
    const uint32_t QSTEP = 16u * 36u * 4u;

    uint32_t Qah[4][4], Qal[4][4];
#pragma unroll
    for (int kb = 0; kb < 4; kb++) {
        int c0 = 16 * kb + 2 * tig;
        const float* r0 = Q + (long)(m0w + g) * DD;
        const float* r1 = Q + (long)(m0w + g + 8) * DD;
        float2 v;
        v = *(const float2*)(r0 + c0);     split_pair(v, Qah[kb][0], Qal[kb][0]);
        v = *(const float2*)(r1 + c0);     split_pair(v, Qah[kb][1], Qal[kb][1]);
        v = *(const float2*)(r0 + c0 + 8); split_pair(v, Qah[kb][2], Qal[kb][2]);
        v = *(const float2*)(r1 + c0 + 8); split_pair(v, Qah[kb][3], Qal[kb][3]);
    }

    float acc[8][4];
#pragma unroll
    for (int j = 0; j < 8; j++)
#pragma unroll
        for (int e = 0; e < 4; e++) acc[j][e] = 0.f;
    float m0 = -1e30f, m1 = -1e30f, sum0 = 0.f, sum1 = 0.f;

    int chBeg = kvStart >> 6;
    int chEnd = (kvEnd + 63) >> 6;
    if (causal) chEnd = min(chEnd, mt + 1);

    for (int ch = chBeg; ch < chEnd; ch++) {
        int n0 = ch * 64;
#pragma unroll
        for (int i = 0; i < 16; i++) {
            int idx = i * 128 + tid;
            int r = idx >> 5, c = idx & 31;
            float2 v = {0.f, 0.f};
            if (n0 + r < kvEnd) v = *(const float2*)(K + (long)(n0 + r) * DD + 2 * c);
            split_pair(v, Kh[r][c], Kl[r][c]);
        }
#pragma unroll
        for (int i = 0; i < 16; i++) {
            int idx = i * 128 + tid;
            int d = idx & 63, pr = idx >> 6;
            float2 v = {0.f, 0.f};
            int r0i = n0 + 2 * pr;
            if (r0i < kvEnd)     v.x = V[(long)r0i * DD + d];
            if (r0i + 1 < kvEnd) v.y = V[(long)(r0i + 1) * DD + d];
            split_pair(v, Vh[d][pr], Vl[d][pr]);
        }
        __syncthreads();

        float s[8][4];
#pragma unroll
        for (int j = 0; j < 8; j++)
#pragma unroll
            for (int e = 0; e < 4; e++) s[j][e] = 0.f;
#pragma unroll
        for (int kb = 0; kb < 4; kb++) {
            uint32_t kbb = (uint32_t)kb * 32u;
            uint32_t KHf[4][4], KLf[4][4];
#pragma unroll
            for (int q = 0; q < 4; q++) {
                ldsm_x4(KHf[q], kBaseH + foff + q * QSTEP + kbb);
                ldsm_x4(KLf[q], kBaseL + foff + q * QSTEP + kbb);
            }
#pragma unroll
            for (int j = 0; j < 8; j++) {
                const uint32_t* bh = &KHf[j >> 1][(j & 1) * 2];
                const uint32_t* bl = &KLf[j >> 1][(j & 1) * 2];
                mma_bf16(s[j], Qah[kb], bl);
                mma_bf16(s[j], Qal[kb], bh);
                mma_bf16(s[j], Qah[kb], bh);
            }
        }

        if (Mr) {
#pragma unroll
            for (int j = 0; j < 8; j++) {
                int col = n0 + 8 * j + 2 * tig;
                if (col < kvEnd) {
                    float2 v0 = { s[j][0], s[j][1] };
                    float2 v1 = { s[j][2], s[j][3] };
                    *(float2*)&Mr[(long)(m0w + g) * TAA + col] = v0;
                    *(float2*)&Mr[(long)(m0w + g + 8) * TAA + col] = v1;
                }
            }
        }

        if (causal && ch == mt) {
            int t0 = mt * 64 + m0w + g;
#pragma unroll
            for (int j = 0; j < 8; j++) {
                int col = n0 + 8 * j + 2 * tig;
                if (col     > t0)     s[j][0] = -1e30f;
                if (col + 1 > t0)     s[j][1] = -1e30f;
                if (col     > t0 + 8) s[j][2] = -1e30f;
                if (col + 1 > t0 + 8) s[j][3] = -1e30f;
            }
        }
        if (n0 + 64 > kvEnd) {
#pragma unroll
            for (int j = 0; j < 8; j++) {
                int col = n0 + 8 * j + 2 * tig;
                if (col     >= kvEnd) { s[j][0] = -1e30f; s[j][2] = -1e30f; }
                if (col + 1 >= kvEnd) { s[j][1] = -1e30f; s[j][3] = -1e30f; }
            }
        }

        float mx0 = -1e30f, mx1 = -1e30f;
#pragma unroll
        for (int j = 0; j < 8; j++) {
            mx0 = fmaxf(mx0, fmaxf(s[j][0], s[j][1]));
            mx1 = fmaxf(mx1, fmaxf(s[j][2], s[j][3]));
        }
        mx0 = fmaxf(mx0, __shfl_xor_sync(0xffffffffu, mx0, 1));
        mx0 = fmaxf(mx0, __shfl_xor_sync(0xffffffffu, mx0, 2));
        mx1 = fmaxf(mx1, __shfl_xor_sync(0xffffffffu, mx1, 1));
        mx1 = fmaxf(mx1, __shfl_xor_sync(0xffffffffu, mx1, 2));
        float mn0 = fmaxf(m0, mx0), mn1 = fmaxf(m1, mx1);
        float a0 = __expf(m0 - mn0), a1 = __expf(m1 - mn1);
        float ps0 = 0.f, ps1 = 0.f;
#pragma unroll
        for (int j = 0; j < 8; j++) {
            s[j][0] = __expf(s[j][0] - mn0);
            s[j][1] = __expf(s[j][1] - mn0);
            s[j][2] = __expf(s[j][2] - mn1);
            s[j][3] = __expf(s[j][3] - mn1);
            ps0 += s[j][0] + s[j][1];
            ps1 += s[j][2] + s[j][3];
        }
        ps0 += __shfl_xor_sync(0xffffffffu, ps0, 1);
        ps0 += __shfl_xor_sync(0xffffffffu, ps0, 2);
        ps1 += __shfl_xor_sync(0xffffffffu, ps1, 1);
        ps1 += __shfl_xor_sync(0xffffffffu, ps1, 2);
        sum0 = sum0 * a0 + ps0;
        sum1 = sum1 * a1 + ps1;
        m0 = mn0; m1 = mn1;
#pragma unroll
        for (int j = 0; j < 8; j++) {
            acc[j][0] *= a0; acc[j][1] *= a0;
            acc[j][2] *= a1; acc[j][3] *= a1;
        }

#pragma unroll
        for (int kb = 0; kb < 4; kb++) {
            int j0 = 2 * kb, j1 = 2 * kb + 1;
            uint32_t Ah[4], Al[4];
            Ah[0] = pack_bf(s[j0][0], s[j0][1]);  Al[0] = lo_pack(s[j0][0], s[j0][1]);
            Ah[1] = pack_bf(s[j0][2], s[j0][3]);  Al[1] = lo_pack(s[j0][2], s[j0][3]);
            Ah[2] = pack_bf(s[j1][0], s[j1][1]);  Al[2] = lo_pack(s[j1][0], s[j1][1]);
            Ah[3] = pack_bf(s[j1][2], s[j1][3]);  Al[3] = lo_pack(s[j1][2], s[j1][3]);
            uint32_t kbb = (uint32_t)kb * 32u;
            uint32_t VHf[4][4], VLf[4][4];
#pragma unroll
            for (int q = 0; q < 4; q++) {
                ldsm_x4(VHf[q], vBaseH + foff + q * QSTEP + kbb);
                ldsm_x4(VLf[q], vBaseL + foff + q * QSTEP + kbb);
            }
#pragma unroll
            for (int jd = 0; jd < 8; jd++) {
                const uint32_t* bh = &VHf[jd >> 1][(jd & 1) * 2];
                const uint32_t* bl = &VLf[jd >> 1][(jd & 1) * 2];
                mma_bf16(acc[jd], Ah, bl);
                mma_bf16(acc[jd], Al, bh);
                mma_bf16(acc[jd], Ah, bh);
            }
        }
        __syncthreads();
    }

    if (Opart) {
        float* OP = Opart + (((long)sp * BT) + (long)b * TT + mt * 64) * DD + hh * DHH;
#pragma unroll
        for (int jd = 0; jd < 8; jd++) {
            int col = 8 * jd + 2 * tig;
            float2 v0 = { acc[jd][0], acc[jd][1] };
            float2 v1 = { acc[jd][2], acc[jd][3] };
            *(float2*)&OP[(long)(m0w + g) * DD + col] = v0;
            *(float2*)&OP[(long)(m0w + g + 8) * DD + col] = v1;
        }
        if (tig == 0) {
            long base = (((long)sp * BB + b) * HH + hh) * TT + mt * 64;
            Msum[base + m0w + g]     = make_float2(m0, sum0);
            Msum[base + m0w + g + 8] = make_float2(m1, sum1);
        }
    } else {
        float* O = Ob + ((long)b * TT + mt * 64) * DD + hh * DHH;
        float i0 = 1.f / sum0, i1 = 1.f / sum1;
#pragma unroll
        for (int jd = 0; jd < 8; jd++) {
            int col = 8 * jd + 2 * tig;
            float2 v0 = { acc[jd][0] * i0, acc[jd][1] * i0 };
            float2 v1 = { acc[jd][2] * i1, acc[jd][3] * i1 };
            *(float2*)&O[(long)(m0w + g) * DD + col] = v0;
            *(float2*)&O[(long)(m0w + g + 8) * DD + col] = v1;
        }
    }
}

__global__ __launch_bounds__(256) void flash_merge_kernel(
    const float* __restrict__ Opart, const float2* __restrict__ Msum,
    float* __restrict__ O)
{
    __shared__ float wgt[HH][NSPLIT];
    int row = blockIdx.x;
    int b = row / TT, t = row % TT;
    int tid = threadIdx.x;
    if (tid < HH) {
        int h = tid;
        float ms[NSPLIT], ss[NSPLIT];
        float m = -1e30f;
#pragma unroll
        for (int s = 0; s < NSPLIT; s++) {
            float2 v = Msum[(((long)s * BB + b) * HH + h) * TT + t];
            ms[s] = v.x; ss[s] = v.y;
            m = fmaxf(m, v.x);
        }
        float den = 0.f;
#pragma unroll
        for (int s = 0; s < NSPLIT; s++) den += ss[s] * __expf(ms[s] - m);
        float iden = 1.f / den;
#pragma unroll
        for (int s = 0; s < NSPLIT; s++) wgt[h][s] = __expf(ms[s] - m) * iden;
    }
    __syncthreads();
#pragma unroll
    for (int it = 0; it < 3; it++) {
        int d = tid + it * 256;
        int h = d >> 6;
        float acc = 0.f;
#pragma unroll
        for (int s = 0; s < NSPLIT; s++)
            acc += Opart[(((long)s * BT) + row) * DD + d] * wgt[h][s];
        O[(long)row * DD + d] = acc;
    }
}

// ---------------- elementwise / row kernels ----------------
__global__ __launch_bounds__(256) void embed_kernel(
    const int* __restrict__ tokens, const float* __restrict__ tok_emb,
    const float* __restrict__ pos_emb, float* __restrict__ x)
{
    int row = blockIdx.x;
    int t = row % TT;
    int tok = tokens[row];
    const float* te = tok_emb + (long)tok * DD;
    const float* pe = pos_emb + (long)t * DD;
    float* xr = x + (long)row * DD;
#pragma unroll
    for (int it = 0; it < 3; it++) {
        int j = threadIdx.x + it * 256;
        xr[j] = te[j] + pe[j];
    }
}

__global__ __launch_bounds__(256) void ln_kernel(
    const float* __restrict__ x, float* __restrict__ y,
    const float* __restrict__ g, const float* __restrict__ b)
{
    __shared__ float red[256];
    int row = blockIdx.x;
    const float* xr = x + (long)row * DD;
    float* yr = y + (long)row * DD;
    int tid = threadIdx.x;
    float v0 = xr[tid], v1 = xr[tid + 256], v2 = xr[tid + 512];
    float s = v0 + v1 + v2;
    red[tid] = s; __syncthreads();
    for (int st = 128; st > 0; st >>= 1) { if (tid < st) red[tid] += red[tid + st]; __syncthreads(); }
    float mean = red[0] * (1.f / DD);
    __syncthreads();
    float d0 = v0 - mean, d1 = v1 - mean, d2 = v2 - mean;
    red[tid] = d0 * d0 + d1 * d1 + d2 * d2; __syncthreads();
    for (int st = 128; st > 0; st >>= 1) { if (tid < st) red[tid] += red[tid + st]; __syncthreads(); }
    float inv = rsqrtf(red[0] * (1.f / DD) + 1e-5f);
    yr[tid]       = d0 * inv * g[tid]       + b[tid];
    yr[tid + 256] = d1 * inv * g[tid + 256] + b[tid + 256];
    yr[tid + 512] = d2 * inv * g[tid + 512] + b[tid + 512];
}

// ---------------- host-side launch helpers ----------------
static GemmP base_p() {
    GemmP p;
    p.A = nullptr; p.B0 = p.B1 = p.B2 = nullptr;
    p.C0 = p.C1 = p.C2 = nullptr;
    p.bias0 = p.bias1 = p.bias2 = nullptr;
    p.M = p.N = p.K = 0; p.lda = p.ldb = p.ldc = 0;
    p.Hd = 1; p.segW = 1 << 30; p.act = 0; p.splitK = 1; p.kc = 0;
    p.sA0 = p.sA1 = p.sB0 = p.sB1 = p.sC0 = p.sC1 = p.sBias = 0;
    p.s0 = p.s1 = p.s2 = 1.f;
    return p;
}

template <int NT, int BIG>
static inline void launch_g(GemmP p, int batch, int splitK = 1) {
    p.splitK = splitK;
    constexpr int TBKv = BIG ? 64 : 32;
    int kc = (p.K + splitK - 1) / splitK;
    p.kc = ((kc + TBKv - 1) / TBKv) * TBKv;
    constexpr int BN = BIG ? 128 : 64;
    constexpr int NTHR = BIG ? 512 : 256;
    dim3 grd((p.N + BN - 1) / BN, (p.M + 127) / 128, batch * splitK);
    gemm_bf3_kernel<NT, BIG><<<grd, NTHR>>>(p);
}

extern "C" void kernel_launch(void* const* d_in, const int* in_sizes, int n_in,
                              void* d_out, int out_size)
{
    (void)in_sizes; (void)n_in; (void)out_size;

    const int*   tokens  = (const int*)  d_in[0];
    const float* xa      = (const float*)d_in[1];
    const float* tok_emb = (const float*)d_in[2];
    const float* pos_emb = (const float*)d_in[3];
    const float* Wq      = (const float*)d_in[4];
    const float* bq      = (const float*)d_in[5];
    const float* Wk      = (const float*)d_in[6];
    const float* Wv      = (const float*)d_in[7];
    const float* bv      = (const float*)d_in[8];
    const float* Wo      = (const float*)d_in[9];
    const float* bo      = (const float*)d_in[10];
    const float* ln1_g   = (const float*)d_in[11];
    const float* ln1_b   = (const float*)d_in[12];
    const float* Wcq     = (const float*)d_in[13];
    const float* bcq     = (const float*)d_in[14];
    const float* Wck     = (const float*)d_in[15];
    const float* Wcv     = (const float*)d_in[16];
    const float* bcv     = (const float*)d_in[17];
    const float* Wco     = (const float*)d_in[18];
    const float* bco     = (const float*)d_in[19];
    const float* ln2_g   = (const float*)d_in[20];
    const float* ln2_b   = (const float*)d_in[21];
    const float* W1      = (const float*)d_in[22];
    const float* b1      = (const float*)d_in[23];
    const float* W2      = (const float*)d_in[24];
    const float* b2      = (const float*)d_in[25];
    const float* ln3_g   = (const float*)d_in[26];
    const float* ln3_b   = (const float*)d_in[27];
    const float* lnf_g   = (const float*)d_in[28];
    const float* lnf_b   = (const float*)d_in[29];

    float* out = (float*)d_out;
    float* out_logits = out;
    float* out_chw    = out_logits + (size_t)BB * TT * VV;
    float* out_kv     = out_chw + (size_t)(LL / 2) * HH * TT * TAA;

    float *x, *h, *q, *o, *ckall, *cvall, *hid, *opart;
    float2* msum;
    cudaGetSymbolAddress((void**)&x,     g_x);
    cudaGetSymbolAddress((void**)&h,     g_h);
    cudaGetSymbolAddress((void**)&q,     g_q);
    cudaGetSymbolAddress((void**)&o,     g_o);
    cudaGetSymbolAddress((void**)&ckall, g_ckall);
    cudaGetSymbolAddress((void**)&cvall, g_cvall);
    cudaGetSymbolAddress((void**)&hid,   g_hid);
    cudaGetSymbolAddress((void**)&opart, g_opart);
    cudaGetSymbolAddress((void**)&msum,  g_msum);

    embed_kernel<<<BT, 256>>>(tokens, tok_emb, pos_emb, x);

    const long DTD = (long)TT * DD;
    const long TAD = (long)TAA * DD;
    const size_t XBYTES = (size_t)BT * DD * sizeof(float);
    const int KVCH = ((TAA + NSPLIT * 64 - 1) / (NSPLIT * 64)) * 64;   // 384

    // cross K/V for ALL layers, batched over z=12 (BIG tiles)
    {
        GemmP p = base_p();
        p.A = xa; p.lda = DD;
        p.B0 = Wck; p.ldb = DD; p.sB1 = (long)DD * DD;
        p.C0 = ckall; p.ldc = DD; p.sC1 = (long)BTAD;
        p.M = BB * TAA; p.N = DD; p.K = DD; p.Hd = LL;
        launch_g<0, 1>(p, LL);
        p.B0 = Wcv; p.C0 = cvall;
        p.bias0 = bcv; p.sBias = DD;
        launch_g<0, 1>(p, LL);
    }

    for (int l = 0; l < LL; l++) {
        const float* Wq_l = Wq + (size_t)l * DD * DD;
        const float* Wk_l = Wk + (size_t)l * DD * DD;
        const float* Wv_l = Wv + (size_t)l * DD * DD;
        const float* Wo_l = Wo + (size_t)l * DD * DD;
        const float* Wcq_l = Wcq + (size_t)l * DD * DD;
        const float* Wco_l = Wco + (size_t)l * DD * DD;
        const float* W1_l = W1 + (size_t)l * DD * 4 * DD;
        const float* W2_l = W2 + (size_t)l * 4 * DD * DD;

        float* kout = out_kv + (size_t)(2 * l) * BT * DD;
        float* vout = out_kv + (size_t)(2 * l + 1) * BT * DD;
        float* ck_l = ckall + (size_t)l * BTAD;
        float* cv_l = cvall + (size_t)l * BTAD;

        // ---- self attention ----
        ln_kernel<<<BT, 256>>>(x, h, ln1_g + l * DD, ln1_b + l * DD);
        {   // fused QKV (BIG tiles)
            GemmP p = base_p();
            p.A = h; p.lda = DD;
            p.B0 = Wq_l; p.B1 = Wk_l; p.B2 = Wv_l; p.ldb = DD;
            p.C0 = q; p.C1 = kout; p.C2 = vout; p.ldc = DD;
            p.bias0 = bq + l * DD; p.bias1 = nullptr; p.bias2 = bv + l * DD;
            p.s0 = SCALE_Q; p.s1 = 1.f; p.s2 = 1.f;
            p.segW = DD;
            p.M = BT; p.N = 3 * DD; p.K = DD;
            launch_g<0, 1>(p, 1);
        }
        flash_kernel<<<dim3(TT / 64, BB * HH, 1), 128>>>(
            q, kout, vout, o, nullptr, TT, DTD, 1, nullptr, nullptr, TT);
        {   // x += o @ Wo + bo  (small tiles, split-K atomics)
            GemmP p = base_p();
            p.A = o; p.lda = DD;
            p.B0 = Wo_l; p.ldb = DD;
            p.C0 = x; p.ldc = DD;
            p.bias0 = bo + l * DD;
            p.M = BT; p.N = DD; p.K = DD;
            launch_g<0, 0>(p, 1, 4);
        }

        // ---- cross attention ----
        ln_kernel<<<BT, 256>>>(x, h, ln2_g + l * DD, ln2_b + l * DD);
        cudaMemsetAsync(q, 0, XBYTES);
        {   // q2 (small tiles, split-K atomics)
            GemmP p = base_p();
            p.A = h; p.lda = DD;
            p.B0 = Wcq_l; p.ldb = DD;
            p.C0 = q; p.ldc = DD;
            p.bias0 = bcq + l * DD; p.s0 = SCALE_Q;
            p.M = BT; p.N = DD; p.K = DD;
            launch_g<0, 0>(p, 1, 4);
        }
        {
            float* mir = (l >= LL / 2)
                       ? out_chw + (size_t)(l - LL / 2) * HH * TT * TAA : nullptr;
            flash_kernel<<<dim3(TT / 64, BB * HH, NSPLIT), 128>>>(
                q, ck_l, cv_l, nullptr, mir, TAA, TAD, 0, opart, msum, KVCH);
            flash_merge_kernel<<<BT, 256>>>(opart, msum, o);
        }
        {   // x += o @ Wco + bco  (small tiles, split-K atomics)
            GemmP p = base_p();
            p.A = o; p.lda = DD;
            p.B0 = Wco_l; p.ldb = DD;
            p.C0 = x; p.ldc = DD;
            p.bias0 = bco + l * DD;
            p.M = BT; p.N = DD; p.K = DD;
            launch_g<0, 0>(p, 1, 4);
        }

        // ---- MLP ----
        ln_kernel<<<BT, 256>>>(x, h, ln3_g + l * DD, ln3_b + l * DD);
        {   // hid = gelu(h @ W1 + b1)  (BIG tiles)
            GemmP p = base_p();
            p.A = h; p.lda = DD;
            p.B0 = W1_l; p.ldb = 4 * DD;
            p.C0 = hid; p.ldc = 4 * DD;
            p.bias0 = b1 + (size_t)l * 4 * DD; p.act = 1;
            p.M = BT; p.N = 4 * DD; p.K = DD;
            launch_g<0, 1>(p, 1);
        }
        {   // x += hid @ W2 + b2  (BIG tiles, split-K 8)
            GemmP p = base_p();
            p.A = hid; p.lda = 4 * DD;
            p.B0 = W2_l; p.ldb = DD;
            p.C0 = x; p.ldc = DD;
            p.bias0 = b2 + l * DD;
            p.M = BT; p.N = DD; p.K = 4 * DD;
            launch_g<0, 1>(p, 1, 8);
        }
    }

    // final LN + tied-embedding logits (BIG tiles)
    ln_kernel<<<BT, 256>>>(x, h, lnf_g, lnf_b);
    {
        GemmP p = base_p();
        p.A = h; p.lda = DD;
        p.B0 = tok_emb; p.ldb = DD;
        p.C0 = out_logits; p.ldc = VV;
        p.M = BT; p.N = VV; p.K = DD;
        launch_g<1, 1>(p, 1);
    }
}

// round 12
// speedup vs baseline: 1.0358x; 1.0358x over previous
#include <cuda_runtime.h>
#include <cuda_bf16.h>
#include <math.h>
#include <stdint.h>

// ---------------- problem constants ----------------
#define BB   4
#define TT   256
#define TAA  1500
#define DD   768
#define HH   12
#define LL   12
#define VV   51865
#define DHH  64
#define BT   (BB*TT)          // 1024
#define SCALE_Q 0.125f
#define BTAD ((size_t)BB*TAA*DD)
#define NSPLIT 4

// ---------------- scratch ----------------
__device__ float g_x  [BT*DD];
__device__ float g_h  [BT*DD];
__device__ float g_q  [BT*DD];
__device__ float g_o  [BT*DD];
__device__ float g_ckall[(size_t)LL*BTAD];
__device__ float g_cvall[(size_t)LL*BTAD];
__device__ float g_hid[(size_t)BT*4*DD];
__device__ float g_opart[(size_t)NSPLIT*BT*DD];
__device__ float2 g_msum[(size_t)NSPLIT*BB*HH*TT];

// ---------------- shared helpers ----------------
__device__ __forceinline__ uint32_t pack_bf(float a, float b) {
    __nv_bfloat162 t;
    t.x = __float2bfloat16_rn(a);
    t.y = __float2bfloat16_rn(b);
    return *(uint32_t*)&t;
}

__device__ __forceinline__ void split_pair(float2 v, uint32_t& hi, uint32_t& lo) {
    __nv_bfloat16 hx = __float2bfloat16_rn(v.x);
    __nv_bfloat16 hy = __float2bfloat16_rn(v.y);
    hi = pack_bf(v.x, v.y);
    lo = pack_bf(v.x - __bfloat162float(hx), v.y - __bfloat162float(hy));
}

__device__ __forceinline__ uint32_t lo_pack(float a, float b) {
    float ra = a - __bfloat162float(__float2bfloat16_rn(a));
    float rb = b - __bfloat162float(__float2bfloat16_rn(b));
    return pack_bf(ra, rb);
}

__device__ __forceinline__ void mma_bf16(float* c, const uint32_t* a, const uint32_t* b) {
    asm volatile(
        "mma.sync.aligned.m16n8k16.row.col.f32.bf16.bf16.f32 "
        "{%0,%1,%2,%3}, {%4,%5,%6,%7}, {%8,%9}, {%0,%1,%2,%3};"
        : "+f"(c[0]), "+f"(c[1]), "+f"(c[2]), "+f"(c[3])
        : "r"(a[0]), "r"(a[1]), "r"(a[2]), "r"(a[3]), "r"(b[0]), "r"(b[1]));
}

// ---------------- bf16 split GEMM (3-term) + split-K, double-buffered smem ----------------
// BIG=0: 128x64 tile, 256 thr, TBK=32, 2 CTAs/SM. BIG=1: 128x128, 512 thr, TBK=64.
// Per iter: LDG prefetch(it+1) -> MMA(stage it&1) -> store(stage (it+1)&1) -> 1 barrier.
struct GemmP {
    const float *A, *B0, *B1, *B2;
    float *C0, *C1, *C2;
    const float *bias0, *bias1, *bias2;
    int M, N, K, lda, ldb, ldc, Hd, segW, act, splitK, kc;
    long sA0, sA1, sB0, sB1, sC0, sC1, sBias;
    float s0, s1, s2;
};

template <int NT, int BIG>
__global__ __launch_bounds__(BIG ? 512 : 256, BIG ? 1 : 2) void gemm_bf3_kernel(GemmP p)
{
    constexpr int BN    = BIG ? 128 : 64;
    constexpr int NTHR  = BIG ? 512 : 256;
    constexpr int TBKv  = BIG ? 64 : 32;
    constexpr int KP    = TBKv / 2;
    constexpr int ALD   = BIG ? 36 : 20;      // A / NT-B stride (u32)
    constexpr int BLDN  = BIG ? 136 : 72;     // NN-B stride (≡8 mod 32)
    constexpr int AIT   = 128 * KP / NTHR;    // 8
    constexpr int BIT   = BN * KP / NTHR;     // BIG 8, small 4
    constexpr int AAREA = 128 * ALD;
    constexpr int BAREA = BIG ? (128 * 36) : (64 * 20);  // covers NT BN*ALD and NN KP*BLDN
    constexpr int STAGE = 2 * AAREA + 2 * BAREA;

    extern __shared__ uint32_t dsm[];

    int z = blockIdx.z;
    int sk = z % p.splitK;
    int zz = z / p.splitK;
    int zb = zz / p.Hd, zh = zz % p.Hd;
    int bm = blockIdx.y * 128, bn = blockIdx.x * BN;
    int seg = bn / p.segW;
    int bnl = bn - seg * p.segW;

    const float* A = p.A + zb * p.sA0 + zh * p.sA1;
    const float* B = (seg == 0 ? p.B0 : seg == 1 ? p.B1 : p.B2) + zb * p.sB0 + zh * p.sB1;
    float* C = (seg == 0 ? p.C0 : seg == 1 ? p.C1 : p.C2) + zb * p.sC0 + zh * p.sC1;
    const float* bias = (seg == 0 ? p.bias0 : seg == 1 ? p.bias1 : p.bias2);
    if (bias) bias += zh * p.sBias;
    float scl = seg == 0 ? p.s0 : seg == 1 ? p.s1 : p.s2;
    bool atom = p.splitK > 1;

    int M = p.M, N = p.N;
    int lda = p.lda, ldb = p.ldb, ldc = p.ldc;
    int kstart = sk * p.kc;
    int kend = min(p.K, kstart + p.kc);

    int tid  = threadIdx.x;
    int lane = tid & 31;
    int warp = tid >> 5;
    int g    = lane >> 2;
    int tig  = lane & 3;
    int m0w  = (warp & 3) * 32;
    int n0w  = (warp >> 2) * 32;

    float c[2][4][4];
#pragma unroll
    for (int mi = 0; mi < 2; mi++)
#pragma unroll
        for (int ni = 0; ni < 4; ni++)
#pragma unroll
            for (int e = 0; e < 4; e++) c[mi][ni][e] = 0.f;

    int iters = (kend - kstart + TBKv - 1) / TBKv;
    float2 ra[AIT], rb[BIT];

    // ---- LDG prefetch of tile `kk` into registers ----
    auto prefetch = [&](int kk) {
#pragma unroll
        for (int i = 0; i < AIT; i++) {
            int pidx = i * NTHR + tid;
            int r = pidx / KP, kp = pidx % KP;
            int gr = bm + r, k0 = kk + 2 * kp;
            float2 v = {0.f, 0.f};
            if (gr < M) {
                if (k0 + 1 < kend)      v = *(const float2*)&A[(long)gr * lda + k0];
                else if (k0 < kend)     v.x = A[(long)gr * lda + k0];
            }
            ra[i] = v;
        }
#pragma unroll
        for (int i = 0; i < BIT; i++) {
            int pidx = i * NTHR + tid;
            float2 v = {0.f, 0.f};
            if (NT) {
                int n = pidx / KP, kp = pidx % KP;
                int k0 = kk + 2 * kp;
                if (bn + n < N) {
                    long base = (long)(bnl + n) * ldb;
                    if (k0 + 1 < kend)  v = *(const float2*)&B[base + k0];
                    else if (k0 < kend) v.x = B[base + k0];
                }
            } else {
                int n = pidx % BN, kp = pidx / BN;
                int k0 = kk + 2 * kp;
                if (bn + n < N) {
                    if (k0 < kend)     v.x = B[(long)k0 * ldb + bnl + n];
                    if (k0 + 1 < kend) v.y = B[(long)(k0 + 1) * ldb + bnl + n];
                }
            }
            rb[i] = v;
        }
    };

    // ---- store registers into smem stage s ----
    auto store_stage = [&](int s) {
        uint32_t* AHs = dsm + s * STAGE;
        uint32_t* ALs = AHs + AAREA;
        uint32_t* BHs = ALs + AAREA;
        uint32_t* BLs = BHs + BAREA;
#pragma unroll
        for (int i = 0; i < AIT; i++) {
            int pidx = i * NTHR + tid;
            int r = pidx / KP, kp = pidx % KP;
            split_pair(ra[i], AHs[r * ALD + kp], ALs[r * ALD + kp]);
        }
#pragma unroll
        for (int i = 0; i < BIT; i++) {
            int pidx = i * NTHR + tid;
            uint32_t hi, lo;
            split_pair(rb[i], hi, lo);
            if (NT) {
                int n = pidx / KP, kp = pidx % KP;
                BHs[n * ALD + kp] = hi;
                BLs[n * ALD + kp] = lo;
            } else {
                int n = pidx % BN, kp = pidx / BN;
                BHs[kp * BLDN + n] = hi;
                BLs[kp * BLDN + n] = lo;
            }
        }
    };

    prefetch(kstart);
    store_stage(0);
    __syncthreads();

    for (int it = 0; it < iters; it++) {
        bool more = (it + 1 < iters);
        if (more) prefetch(kstart + (it + 1) * TBKv);

        int s = it & 1;
        const uint32_t* AHs = dsm + s * STAGE;
        const uint32_t* ALs = AHs + AAREA;
        const uint32_t* BHs = ALs + AAREA;
        const uint32_t* BLs = BHs + BAREA;

#pragma unroll
        for (int h = 0; h < TBKv / 16; h++) {
            int kb = h * 8;
            uint32_t aH4[2][4], aL4[2][4];
#pragma unroll
            for (int mi = 0; mi < 2; mi++) {
                int m = m0w + mi * 16 + g;
                aH4[mi][0] = AHs[(m    ) * ALD + kb + tig];
                aH4[mi][1] = AHs[(m + 8) * ALD + kb + tig];
                aH4[mi][2] = AHs[(m    ) * ALD + kb + tig + 4];
                aH4[mi][3] = AHs[(m + 8) * ALD + kb + tig + 4];
                aL4[mi][0] = ALs[(m    ) * ALD + kb + tig];
                aL4[mi][1] = ALs[(m + 8) * ALD + kb + tig];
                aL4[mi][2] = ALs[(m    ) * ALD + kb + tig + 4];
                aL4[mi][3] = ALs[(m + 8) * ALD + kb + tig + 4];
            }
            uint32_t bh2[4][2], bl2[4][2];
#pragma unroll
            for (int ni = 0; ni < 4; ni++) {
                int n = n0w + ni * 8 + g;
                if (NT) {
                    bh2[ni][0] = BHs[n * ALD + kb + tig];
                    bh2[ni][1] = BHs[n * ALD + kb + tig + 4];
                    bl2[ni][0] = BLs[n * ALD + kb + tig];
                    bl2[ni][1] = BLs[n * ALD + kb + tig + 4];
                } else {
                    bh2[ni][0] = BHs[(kb + tig) * BLDN + n];
                    bh2[ni][1] = BHs[(kb + tig + 4) * BLDN + n];
                    bl2[ni][0] = BLs[(kb + tig) * BLDN + n];
                    bl2[ni][1] = BLs[(kb + tig + 4) * BLDN + n];
                }
            }
#pragma unroll
            for (int mi = 0; mi < 2; mi++)
#pragma unroll
                for (int ni = 0; ni < 4; ni++) {
                    mma_bf16(c[mi][ni], aH4[mi], bl2[ni]);
                    mma_bf16(c[mi][ni], aL4[mi], bh2[ni]);
                    mma_bf16(c[mi][ni], aH4[mi], bh2[ni]);
                }
        }

        if (more) store_stage(s ^ 1);
        __syncthreads();
    }

#pragma unroll
    for (int mi = 0; mi < 2; mi++) {
#pragma unroll
        for (int ni = 0; ni < 4; ni++) {
#pragma unroll
            for (int e = 0; e < 4; e++) {
                int row = bm + m0w + mi * 16 + g + ((e >= 2) ? 8 : 0);
                int gcol = bn + n0w + ni * 8 + tig * 2 + (e & 1);
                if (row >= M || gcol >= N) continue;
                int lc = gcol - seg * p.segW;
                float v = c[mi][ni][e];
                if (bias && (!atom || sk == 0)) v += bias[lc];
                v *= scl;
                long ci = (long)row * ldc + lc;
                if (atom) {
                    atomicAdd(&C[ci], v);
                } else {
                    if (p.act == 1) v = 0.5f * v * (1.f + erff(v * 0.70710678118654752f));
                    C[ci] = v;
                }
            }
        }
    }
}

// ---------------- fused flash attention (round-10 proven version) ----------------
__global__ __launch_bounds__(128) void flash_kernel(
    const float* __restrict__ Qb, const float* __restrict__ Kb,
    const float* __restrict__ Vb, float* __restrict__ Ob,
    float* __restrict__ mir, int lenKV, long kvBStride, int causal,
    float* __restrict__ Opart, float2* __restrict__ Msum, int kvChunk)
{
    __shared__ uint32_t Kh[64][36], Kl[64][36];
    __shared__ uint32_t Vh[64][33], Vl[64][33];

    int mt = blockIdx.x;
    int by = blockIdx.y;
    int sp = blockIdx.z;
    int b = by / HH, hh = by % HH;

    int kvStart = sp * kvChunk;
    int kvEnd = min(lenKV, kvStart + kvChunk);

    const float* Q = Qb + ((long)b * TT + mt * 64) * DD + hh * DHH;
    const float* K = Kb + (long)b * kvBStride + hh * DHH;
    const float* V = Vb + (long)b * kvBStride + hh * DHH;
    float* Mr = (mir && b == 0)
              ? mir + (size_t)hh * TT * TAA + (size_t)mt * 64 * TAA : nullptr;

    int tid = threadIdx.x;
    int lane = tid & 31, warp = tid >> 5;
    int g = lane >> 2, tig = lane & 3;
    int m0w = warp * 16;

    uint32_t Qah[4][4], Qal[4][4];
#pragma unroll
    for (int kb = 0; kb < 4; kb++) {
        int c0 = 16 * kb + 2 * tig;
        const float* r0 = Q + (long)(m0w + g) * DD;
        const float* r1 = Q + (long)(m0w + g + 8) * DD;
        float2 v;
        v = *(const float2*)(r0 + c0);     split_pair(v, Qah[kb][0], Qal[kb][0]);
        v = *(const float2*)(r1 + c0);     split_pair(v, Qah[kb][1], Qal[kb][1]);
        v = *(const float2*)(r0 + c0 + 8); split_pair(v, Qah[kb][2], Qal[kb][2]);
        v = *(const float2*)(r1 + c0 + 8); split_pair(v, Qah[kb][3], Qal[kb][3]);
    }

    float acc[8][4];
#pragma unroll
    for (int j = 0; j < 8; j++)
#pragma unroll
        for (int e = 0; e < 4; e++) acc[j][e] = 0.f;
    float m0 = -1e30f, m1 = -1e30f, sum0 = 0.f, sum1 = 0.f;

    int chBeg = kvStart >> 6;
    int chEnd = (kvEnd + 63) >> 6;
    if (causal) chEnd = min(chEnd, mt + 1);

    for (int ch = chBeg; ch < chEnd; ch++) {
        int n0 = ch * 64;
#pragma unroll
        for (int i = 0; i < 16; i++) {
            int idx = i * 128 + tid;
            int r = idx >> 5, c = idx & 31;
            float2 v = {0.f, 0.f};
            if (n0 + r < kvEnd) v = *(const float2*)(K + (long)(n0 + r) * DD + 2 * c);
            split_pair(v, Kh[r][c], Kl[r][c]);
        }
#pragma unroll
        for (int i = 0; i < 16; i++) {
            int idx = i * 128 + tid;
            int d = idx & 63, pr = idx >> 6;
            float2 v = {0.f, 0.f};
            int r0i = n0 + 2 * pr;
            if (r0i < kvEnd)     v.x = V[(long)r0i * DD + d];
            if (r0i + 1 < kvEnd) v.y = V[(long)(r0i + 1) * DD + d];
            split_pair(v, Vh[d][pr], Vl[d][pr]);
        }
        __syncthreads();

        float s[8][4];
#pragma unroll
        for (int j = 0; j < 8; j++)
#pragma unroll
            for (int e = 0; e < 4; e++) s[j][e] = 0.f;
#pragma unroll
        for (int kb = 0; kb < 4; kb++) {
#pragma unroll
            for (int j = 0; j < 8; j++) {
                uint32_t bh[2] = { Kh[8 * j + g][8 * kb + tig], Kh[8 * j + g][8 * kb + tig + 4] };
                uint32_t bl[2] = { Kl[8 * j + g][8 * kb + tig], Kl[8 * j + g][8 * kb + tig + 4] };
                mma_bf16(s[j], Qah[kb], bl);
                mma_bf16(s[j], Qal[kb], bh);
                mma_bf16(s[j], Qah[kb], bh);
            }
        }

        if (Mr) {
#pragma unroll
            for (int j = 0; j < 8; j++) {
                int col = n0 + 8 * j + 2 * tig;
                if (col < kvEnd) {
                    float2 v0 = { s[j][0], s[j][1] };
                    float2 v1 = { s[j][2], s[j][3] };
                    *(float2*)&Mr[(long)(m0w + g) * TAA + col] = v0;
                    *(float2*)&Mr[(long)(m0w + g + 8) * TAA + col] = v1;
                }
            }
        }

        if (causal && ch == mt) {
            int t0 = mt * 64 + m0w + g;
#pragma unroll
            for (int j = 0; j < 8; j++) {
                int col = n0 + 8 * j + 2 * tig;
                if (col     > t0)     s[j][0] = -1e30f;
                if (col + 1 > t0)     s[j][1] = -1e30f;
                if (col     > t0 + 8) s[j][2] = -1e30f;
                if (col + 1 > t0 + 8) s[j][3] = -1e30f;
            }
        }
        if (n0 + 64 > kvEnd) {
#pragma unroll
            for (int j = 0; j < 8; j++) {
                int col = n0 + 8 * j + 2 * tig;
                if (col     >= kvEnd) { s[j][0] = -1e30f; s[j][2] = -1e30f; }
                if (col + 1 >= kvEnd) { s[j][1] = -1e30f; s[j][3] = -1e30f; }
            }
        }

        float mx0 = -1e30f, mx1 = -1e30f;
#pragma unroll
        for (int j = 0; j < 8; j++) {
            mx0 = fmaxf(mx0, fmaxf(s[j][0], s[j][1]));
            mx1 = fmaxf(mx1, fmaxf(s[j][2], s[j][3]));
        }
        mx0 = fmaxf(mx0, __shfl_xor_sync(0xffffffffu, mx0, 1));
        mx0 = fmaxf(mx0, __shfl_xor_sync(0xffffffffu, mx0, 2));
        mx1 = fmaxf(mx1, __shfl_xor_sync(0xffffffffu, mx1, 1));
        mx1 = fmaxf(mx1, __shfl_xor_sync(0xffffffffu, mx1, 2));
        float mn0 = fmaxf(m0, mx0), mn1 = fmaxf(m1, mx1);
        float a0 = __expf(m0 - mn0), a1 = __expf(m1 - mn1);
        float ps0 = 0.f, ps1 = 0.f;
#pragma unroll
        for (int j = 0; j < 8; j++) {
            s[j][0] = __expf(s[j][0] - mn0);
            s[j][1] = __expf(s[j][1] - mn0);
            s[j][2] = __expf(s[j][2] - mn1);
            s[j][3] = __expf(s[j][3] - mn1);
            ps0 += s[j][0] + s[j][1];
            ps1 += s[j][2] + s[j][3];
        }
        ps0 += __shfl_xor_sync(0xffffffffu, ps0, 1);
        ps0 += __shfl_xor_sync(0xffffffffu, ps0, 2);
        ps1 += __shfl_xor_sync(0xffffffffu, ps1, 1);
        ps1 += __shfl_xor_sync(0xffffffffu, ps1, 2);
        sum0 = sum0 * a0 + ps0;
        sum1 = sum1 * a1 + ps1;
        m0 = mn0; m1 = mn1;
#pragma unroll
        for (int j = 0; j < 8; j++) {
            acc[j][0] *= a0; acc[j][1] *= a0;
            acc[j][2] *= a1; acc[j][3] *= a1;
        }

#pragma unroll
        for (int kb = 0; kb < 4; kb++) {
            int j0 = 2 * kb, j1 = 2 * kb + 1;
            uint32_t Ah[4], Al[4];
            Ah[0] = pack_bf(s[j0][0], s[j0][1]);  Al[0] = lo_pack(s[j0][0], s[j0][1]);
            Ah[1] = pack_bf(s[j0][2], s[j0][3]);  Al[1] = lo_pack(s[j0][2], s[j0][3]);
            Ah[2] = pack_bf(s[j1][0], s[j1][1]);  Al[2] = lo_pack(s[j1][0], s[j1][1]);
            Ah[3] = pack_bf(s[j1][2], s[j1][3]);  Al[3] = lo_pack(s[j1][2], s[j1][3]);
#pragma unroll
            for (int jd = 0; jd < 8; jd++) {
                uint32_t bh[2] = { Vh[8 * jd + g][8 * kb + tig], Vh[8 * jd + g][8 * kb + tig + 4] };
                uint32_t bl[2] = { Vl[8 * jd + g][8 * kb + tig], Vl[8 * jd + g][8 * kb + tig + 4] };
                mma_bf16(acc[jd], Ah, bl);
                mma_bf16(acc[jd], Al, bh);
                mma_bf16(acc[jd], Ah, bh);
            }
        }
        __syncthreads();
    }

    if (Opart) {
        float* OP = Opart + (((long)sp * BT) + (long)b * TT + mt * 64) * DD + hh * DHH;
#pragma unroll
        for (int jd = 0; jd < 8; jd++) {
            int col = 8 * jd + 2 * tig;
            float2 v0 = { acc[jd][0], acc[jd][1] };
            float2 v1 = { acc[jd][2], acc[jd][3] };
            *(float2*)&OP[(long)(m0w + g) * DD + col] = v0;
            *(float2*)&OP[(long)(m0w + g + 8) * DD + col] = v1;
        }
        if (tig == 0) {
            long base = (((long)sp * BB + b) * HH + hh) * TT + mt * 64;
            Msum[base + m0w + g]     = make_float2(m0, sum0);
            Msum[base + m0w + g + 8] = make_float2(m1, sum1);
        }
    } else {
        float* O = Ob + ((long)b * TT + mt * 64) * DD + hh * DHH;
        float i0 = 1.f / sum0, i1 = 1.f / sum1;
#pragma unroll
        for (int jd = 0; jd < 8; jd++) {
            int col = 8 * jd + 2 * tig;
            float2 v0 = { acc[jd][0] * i0, acc[jd][1] * i0 };
            float2 v1 = { acc[jd][2] * i1, acc[jd][3] * i1 };
            *(float2*)&O[(long)(m0w + g) * DD + col] = v0;
            *(float2*)&O[(long)(m0w + g + 8) * DD + col] = v1;
        }
    }
}

__global__ __launch_bounds__(256) void flash_merge_kernel(
    const float* __restrict__ Opart, const float2* __restrict__ Msum,
    float* __restrict__ O)
{
    __shared__ float wgt[HH][NSPLIT];
    int row = blockIdx.x;
    int b = row / TT, t = row % TT;
    int tid = threadIdx.x;
    if (tid < HH) {
        int h = tid;
        float ms[NSPLIT], ss[NSPLIT];
        float m = -1e30f;
#pragma unroll
        for (int s = 0; s < NSPLIT; s++) {
            float2 v = Msum[(((long)s * BB + b) * HH + h) * TT + t];
            ms[s] = v.x; ss[s] = v.y;
            m = fmaxf(m, v.x);
        }
        float den = 0.f;
#pragma unroll
        for (int s = 0; s < NSPLIT; s++) den += ss[s] * __expf(ms[s] - m);
        float iden = 1.f / den;
#pragma unroll
        for (int s = 0; s < NSPLIT; s++) wgt[h][s] = __expf(ms[s] - m) * iden;
    }
    __syncthreads();
#pragma unroll
    for (int it = 0; it < 3; it++) {
        int d = tid + it * 256;
        int h = d >> 6;
        float acc = 0.f;
#pragma unroll
        for (int s = 0; s < NSPLIT; s++)
            acc += Opart[(((long)s * BT) + row) * DD + d] * wgt[h][s];
        O[(long)row * DD + d] = acc;
    }
}

// ---------------- elementwise / row kernels ----------------
__global__ __launch_bounds__(256) void embed_kernel(
    const int* __restrict__ tokens, const float* __restrict__ tok_emb,
    const float* __restrict__ pos_emb, float* __restrict__ x)
{
    int row = blockIdx.x;
    int t = row % TT;
    int tok = tokens[row];
    const float* te = tok_emb + (long)tok * DD;
    const float* pe = pos_emb + (long)t * DD;
    float* xr = x + (long)row * DD;
#pragma unroll
    for (int it = 0; it < 3; it++) {
        int j = threadIdx.x + it * 256;
        xr[j] = te[j] + pe[j];
    }
}

__global__ __launch_bounds__(256) void ln_kernel(
    const float* __restrict__ x, float* __restrict__ y,
    const float* __restrict__ g, const float* __restrict__ b)
{
    __shared__ float red[256];
    int row = blockIdx.x;
    const float* xr = x + (long)row * DD;
    float* yr = y + (long)row * DD;
    int tid = threadIdx.x;
    float v0 = xr[tid], v1 = xr[tid + 256], v2 = xr[tid + 512];
    float s = v0 + v1 + v2;
    red[tid] = s; __syncthreads();
    for (int st = 128; st > 0; st >>= 1) { if (tid < st) red[tid] += red[tid + st]; __syncthreads(); }
    float mean = red[0] * (1.f / DD);
    __syncthreads();
    float d0 = v0 - mean, d1 = v1 - mean, d2 = v2 - mean;
    red[tid] = d0 * d0 + d1 * d1 + d2 * d2; __syncthreads();
    for (int st = 128; st > 0; st >>= 1) { if (tid < st) red[tid] += red[tid + st]; __syncthreads(); }
    float inv = rsqrtf(red[0] * (1.f / DD) + 1e-5f);
    yr[tid]       = d0 * inv * g[tid]       + b[tid];
    yr[tid + 256] = d1 * inv * g[tid + 256] + b[tid + 256];
    yr[tid + 512] = d2 * inv * g[tid + 512] + b[tid + 512];
}

// ---------------- host-side launch helpers ----------------
static GemmP base_p() {
    GemmP p;
    p.A = nullptr; p.B0 = p.B1 = p.B2 = nullptr;
    p.C0 = p.C1 = p.C2 = nullptr;
    p.bias0 = p.bias1 = p.bias2 = nullptr;
    p.M = p.N = p.K = 0; p.lda = p.ldb = p.ldc = 0;
    p.Hd = 1; p.segW = 1 << 30; p.act = 0; p.splitK = 1; p.kc = 0;
    p.sA0 = p.sA1 = p.sB0 = p.sB1 = p.sC0 = p.sC1 = p.sBias = 0;
    p.s0 = p.s1 = p.s2 = 1.f;
    return p;
}

// dynamic smem bytes per variant (2 stages)
static inline int smem_bytes(int BIG) {
    int ALD = BIG ? 36 : 20;
    int AAREA = 128 * ALD;
    int BAREA = BIG ? (128 * 36) : (64 * 20);
    return 2 * (2 * AAREA + 2 * BAREA) * 4;
}

template <int NT, int BIG>
static inline void launch_g(GemmP p, int batch, int splitK = 1) {
    p.splitK = splitK;
    constexpr int TBKv = BIG ? 64 : 32;
    int kc = (p.K + splitK - 1) / splitK;
    p.kc = ((kc + TBKv - 1) / TBKv) * TBKv;
    constexpr int BN = BIG ? 128 : 64;
    constexpr int NTHR = BIG ? 512 : 256;
    dim3 grd((p.N + BN - 1) / BN, (p.M + 127) / 128, batch * splitK);
    gemm_bf3_kernel<NT, BIG><<<grd, NTHR, smem_bytes(BIG)>>>(p);
}

extern "C" void kernel_launch(void* const* d_in, const int* in_sizes, int n_in,
                              void* d_out, int out_size)
{
    (void)in_sizes; (void)n_in; (void)out_size;

    cudaFuncSetAttribute(gemm_bf3_kernel<0, 0>, cudaFuncAttributeMaxDynamicSharedMemorySize, smem_bytes(0));
    cudaFuncSetAttribute(gemm_bf3_kernel<1, 0>, cudaFuncAttributeMaxDynamicSharedMemorySize, smem_bytes(0));
    cudaFuncSetAttribute(gemm_bf3_kernel<0, 1>, cudaFuncAttributeMaxDynamicSharedMemorySize, smem_bytes(1));
    cudaFuncSetAttribute(gemm_bf3_kernel<1, 1>, cudaFuncAttributeMaxDynamicSharedMemorySize, smem_bytes(1));

    const int*   tokens  = (const int*)  d_in[0];
    const float* xa      = (const float*)d_in[1];
    const float* tok_emb = (const float*)d_in[2];
    const float* pos_emb = (const float*)d_in[3];
    const float* Wq      = (const float*)d_in[4];
    const float* bq      = (const float*)d_in[5];
    const float* Wk      = (const float*)d_in[6];
    const float* Wv      = (const float*)d_in[7];
    const float* bv      = (const float*)d_in[8];
    const float* Wo      = (const float*)d_in[9];
    const float* bo      = (const float*)d_in[10];
    const float* ln1_g   = (const float*)d_in[11];
    const float* ln1_b   = (const float*)d_in[12];
    const float* Wcq     = (const float*)d_in[13];
    const float* bcq     = (const float*)d_in[14];
    const float* Wck     = (const float*)d_in[15];
    const float* Wcv     = (const float*)d_in[16];
    const float* bcv     = (const float*)d_in[17];
    const float* Wco     = (const float*)d_in[18];
    const float* bco     = (const float*)d_in[19];
    const float* ln2_g   = (const float*)d_in[20];
    const float* ln2_b   = (const float*)d_in[21];
    const float* W1      = (const float*)d_in[22];
    const float* b1      = (const float*)d_in[23];
    const float* W2      = (const float*)d_in[24];
    const float* b2      = (const float*)d_in[25];
    const float* ln3_g   = (const float*)d_in[26];
    const float* ln3_b   = (const float*)d_in[27];
    const float* lnf_g   = (const float*)d_in[28];
    const float* lnf_b   = (const float*)d_in[29];

    float* out = (float*)d_out;
    float* out_logits = out;
    float* out_chw    = out_logits + (size_t)BB * TT * VV;
    float* out_kv     = out_chw + (size_t)(LL / 2) * HH * TT * TAA;

    float *x, *h, *q, *o, *ckall, *cvall, *hid, *opart;
    float2* msum;
    cudaGetSymbolAddress((void**)&x,     g_x);
    cudaGetSymbolAddress((void**)&h,     g_h);
    cudaGetSymbolAddress((void**)&q,     g_q);
    cudaGetSymbolAddress((void**)&o,     g_o);
    cudaGetSymbolAddress((void**)&ckall, g_ckall);
    cudaGetSymbolAddress((void**)&cvall, g_cvall);
    cudaGetSymbolAddress((void**)&hid,   g_hid);
    cudaGetSymbolAddress((void**)&opart, g_opart);
    cudaGetSymbolAddress((void**)&msum,  g_msum);

    embed_kernel<<<BT, 256>>>(tokens, tok_emb, pos_emb, x);

    const long DTD = (long)TT * DD;
    const long TAD = (long)TAA * DD;
    const size_t XBYTES = (size_t)BT * DD * sizeof(float);
    const int KVCH = ((TAA + NSPLIT * 64 - 1) / (NSPLIT * 64)) * 64;   // 384

    // cross K/V for ALL layers, batched over z=12 (BIG tiles)
    {
        GemmP p = base_p();
        p.A = xa; p.lda = DD;
        p.B0 = Wck; p.ldb = DD; p.sB1 = (long)DD * DD;
        p.C0 = ckall; p.ldc = DD; p.sC1 = (long)BTAD;
        p.M = BB * TAA; p.N = DD; p.K = DD; p.Hd = LL;
        launch_g<0, 1>(p, LL);
        p.B0 = Wcv; p.C0 = cvall;
        p.bias0 = bcv; p.sBias = DD;
        launch_g<0, 1>(p, LL);
    }

    for (int l = 0; l < LL; l++) {
        const float* Wq_l = Wq + (size_t)l * DD * DD;
        const float* Wk_l = Wk + (size_t)l * DD * DD;
        const float* Wv_l = Wv + (size_t)l * DD * DD;
        const float* Wo_l = Wo + (size_t)l * DD * DD;
        const float* Wcq_l = Wcq + (size_t)l * DD * DD;
        const float* Wco_l = Wco + (size_t)l * DD * DD;
        const float* W1_l = W1 + (size_t)l * DD * 4 * DD;
        const float* W2_l = W2 + (size_t)l * 4 * DD * DD;

        float* kout = out_kv + (size_t)(2 * l) * BT * DD;
        float* vout = out_kv + (size_t)(2 * l + 1) * BT * DD;
        float* ck_l = ckall + (size_t)l * BTAD;
        float* cv_l = cvall + (size_t)l * BTAD;

        // ---- self attention ----
        ln_kernel<<<BT, 256>>>(x, h, ln1_g + l * DD, ln1_b + l * DD);
        {   // fused QKV (BIG tiles)
            GemmP p = base_p();
            p.A = h; p.lda = DD;
            p.B0 = Wq_l; p.B1 = Wk_l; p.B2 = Wv_l; p.ldb = DD;
            p.C0 = q; p.C1 = kout; p.C2 = vout; p.ldc = DD;
            p.bias0 = bq + l * DD; p.bias1 = nullptr; p.bias2 = bv + l * DD;
            p.s0 = SCALE_Q; p.s1 = 1.f; p.s2 = 1.f;
            p.segW = DD;
            p.M = BT; p.N = 3 * DD; p.K = DD;
            launch_g<0, 1>(p, 1);
        }
        flash_kernel<<<dim3(TT / 64, BB * HH, 1), 128>>>(
            q, kout, vout, o, nullptr, TT, DTD, 1, nullptr, nullptr, TT);
        {   // x += o @ Wo + bo  (small tiles, split-K atomics)
            GemmP p = base_p();
            p.A = o; p.lda = DD;
            p.B0 = Wo_l; p.ldb = DD;
            p.C0 = x; p.ldc = DD;
            p.bias0 = bo + l * DD;
            p.M = BT; p.N = DD; p.K = DD;
            launch_g<0, 0>(p, 1, 4);
        }

        // ---- cross attention ----
        ln_kernel<<<BT, 256>>>(x, h, ln2_g + l * DD, ln2_b + l * DD);
        cudaMemsetAsync(q, 0, XBYTES);
        {   // q2 (small tiles, split-K atomics)
            GemmP p = base_p();
            p.A = h; p.lda = DD;
            p.B0 = Wcq_l; p.ldb = DD;
            p.C0 = q; p.ldc = DD;
            p.bias0 = bcq + l * DD; p.s0 = SCALE_Q;
            p.M = BT; p.N = DD; p.K = DD;
            launch_g<0, 0>(p, 1, 4);
        }
        {
            float* mir = (l >= LL / 2)
                       ? out_chw + (size_t)(l - LL / 2) * HH * TT * TAA : nullptr;
            flash_kernel<<<dim3(TT / 64, BB * HH, NSPLIT), 128>>>(
                q, ck_l, cv_l, nullptr, mir, TAA, TAD, 0, opart, msum, KVCH);
            flash_merge_kernel<<<BT, 256>>>(opart, msum, o);
        }
        {   // x += o @ Wco + bco  (small tiles, split-K atomics)
            GemmP p = base_p();
            p.A = o; p.lda = DD;
            p.B0 = Wco_l; p.ldb = DD;
            p.C0 = x; p.ldc = DD;
            p.bias0 = bco + l * DD;
            p.M = BT; p.N = DD; p.K = DD;
            launch_g<0, 0>(p, 1, 4);
        }

        // ---- MLP ----
        ln_kernel<<<BT, 256>>>(x, h, ln3_g + l * DD, ln3_b + l * DD);
        {   // hid = gelu(h @ W1 + b1)  (BIG tiles)
            GemmP p = base_p();
            p.A = h; p.lda = DD;
            p.B0 = W1_l; p.ldb = 4 * DD;
            p.C0 = hid; p.ldc = 4 * DD;
            p.bias0 = b1 + (size_t)l * 4 * DD; p.act = 1;
            p.M = BT; p.N = 4 * DD; p.K = DD;
            launch_g<0, 1>(p, 1);
        }
        {   // x += hid @ W2 + b2  (BIG tiles, split-K 8)
            GemmP p = base_p();
            p.A = hid; p.lda = 4 * DD;
            p.B0 = W2_l; p.ldb = DD;
            p.C0 = x; p.ldc = DD;
            p.bias0 = b2 + l * DD;
            p.M = BT; p.N = DD; p.K = 4 * DD;
            launch_g<0, 1>(p, 1, 8);
        }
    }

    // final LN + tied-embedding logits (BIG tiles)
    ln_kernel<<<BT, 256>>>(x, h, lnf_g, lnf_b);
    {
        GemmP p = base_p();
        p.A = h; p.lda = DD;
        p.B0 = tok_emb; p.ldb = DD;
        p.C0 = out_logits; p.ldc = VV;
        p.M = BT; p.N = VV; p.K = DD;
        launch_g<1, 1>(p, 1);
    }
}

// round 13
// speedup vs baseline: 1.0665x; 1.0296x over previous
#include <cuda_runtime.h>
#include <cuda_bf16.h>
#include <math.h>
#include <stdint.h>

// ---------------- problem constants ----------------
#define BB   4
#define TT   256
#define TAA  1500
#define DD   768
#define HH   12
#define LL   12
#define VV   51865
#define DHH  64
#define BT   (BB*TT)          // 1024
#define DP   (DD/2)           // 384 pairs
#define SCALE_Q 0.125f
#define BTAD ((size_t)BB*TAA*DD)
#define NSPLIT 4

// ---------------- scratch ----------------
__device__ float g_x  [BT*DD];
__device__ float g_q  [BT*DD];
__device__ float g_ckall[(size_t)LL*BTAD];
__device__ float g_cvall[(size_t)LL*BTAD];
__device__ float g_opart[(size_t)NSPLIT*BT*DD];
__device__ float2 g_msum[(size_t)NSPLIT*BB*HH*TT];

// packed hi/lo bf16 buffers (uint2: x=hi pair, y=lo pair)
__device__ uint2 g_hP  [(size_t)BT*DP];
__device__ uint2 g_oP  [(size_t)BT*DP];
__device__ uint2 g_hidP[(size_t)BT*2*DD];               // 1536 pairs per row
__device__ uint2 g_xaP [(size_t)BB*TAA*DP];
__device__ uint2 g_tokP[(size_t)VV*DP];
__device__ uint2 g_WqP [(size_t)LL*DP*DD];
__device__ uint2 g_WkP [(size_t)LL*DP*DD];
__device__ uint2 g_WvP [(size_t)LL*DP*DD];
__device__ uint2 g_WoP [(size_t)LL*DP*DD];
__device__ uint2 g_WcqP[(size_t)LL*DP*DD];
__device__ uint2 g_WckP[(size_t)LL*DP*DD];
__device__ uint2 g_WcvP[(size_t)LL*DP*DD];
__device__ uint2 g_WcoP[(size_t)LL*DP*DD];
__device__ uint2 g_W1P [(size_t)LL*DP*4*DD];
__device__ uint2 g_W2P [(size_t)LL*2*DD*DD];

// ---------------- shared helpers ----------------
__device__ __forceinline__ uint32_t pack_bf(float a, float b) {
    __nv_bfloat162 t;
    t.x = __float2bfloat16_rn(a);
    t.y = __float2bfloat16_rn(b);
    return *(uint32_t*)&t;
}

__device__ __forceinline__ void split_pair(float2 v, uint32_t& hi, uint32_t& lo) {
    __nv_bfloat16 hx = __float2bfloat16_rn(v.x);
    __nv_bfloat16 hy = __float2bfloat16_rn(v.y);
    hi = pack_bf(v.x, v.y);
    lo = pack_bf(v.x - __bfloat162float(hx), v.y - __bfloat162float(hy));
}

__device__ __forceinline__ uint2 split2(float a, float b) {
    uint32_t hi, lo;
    split_pair(make_float2(a, b), hi, lo);
    return make_uint2(hi, lo);
}

__device__ __forceinline__ uint32_t lo_pack(float a, float b) {
    float ra = a - __bfloat162float(__float2bfloat16_rn(a));
    float rb = b - __bfloat162float(__float2bfloat16_rn(b));
    return pack_bf(ra, rb);
}

__device__ __forceinline__ void mma_bf16(float* c, const uint32_t* a, const uint32_t* b) {
    asm volatile(
        "mma.sync.aligned.m16n8k16.row.col.f32.bf16.bf16.f32 "
        "{%0,%1,%2,%3}, {%4,%5,%6,%7}, {%8,%9}, {%0,%1,%2,%3};"
        : "+f"(c[0]), "+f"(c[1]), "+f"(c[2]), "+f"(c[3])
        : "r"(a[0]), "r"(a[1]), "r"(a[2]), "r"(a[3]), "r"(b[0]), "r"(b[1]));
}

// ---------------- prepack kernels ----------------
__global__ __launch_bounds__(256) void pack_contig_kernel(
    const float* __restrict__ in, uint2* __restrict__ out, long n)
{
    long i = blockIdx.x * 256L + threadIdx.x;
    long stride = (long)gridDim.x * 256;
    for (; i < n; i += stride) {
        float2 v = ((const float2*)in)[i];
        uint32_t hi, lo; split_pair(v, hi, lo);
        out[i] = make_uint2(hi, lo);
    }
}

// in: [B][K][N] fp32 -> out: [B][K/2][N], pairing along K
__global__ __launch_bounds__(256) void pack_strideK_kernel(
    const float* __restrict__ in, uint2* __restrict__ out,
    int Khalf, int N, long total)
{
    long i = blockIdx.x * 256L + threadIdx.x;
    long stride = (long)gridDim.x * 256;
    for (; i < total; i += stride) {
        int n = (int)(i % N);
        long r = i / N;
        int kp = (int)(r % Khalf);
        long b = r / Khalf;
        const float* base = in + b * (long)Khalf * 2 * N;
        float2 v = { base[(long)(2 * kp) * N + n], base[(long)(2 * kp + 1) * N + n] };
        uint32_t hi, lo; split_pair(v, hi, lo);
        out[i] = make_uint2(hi, lo);
    }
}

// ---------------- packed bf16 GEMM (3-term) + split-K, double-buffered ----------------
struct GemmP {
    const uint2 *A, *B0, *B1, *B2;
    float *C0, *C1, *C2;
    uint2 *CP;                 // packed output (MLP1) else null
    const float *bias0, *bias1, *bias2;
    int M, N, K, ldap, ldbp, ldc, Hd, segW, act, splitK, kc;
    long sA0, sA1, sB0, sB1, sC0, sC1, sBias;   // sA/sB in pairs, sC in floats
    float s0, s1, s2;
};

template <int NT, int BIG>
__global__ __launch_bounds__(BIG ? 512 : 256, BIG ? 1 : 2) void gemm_bf3_kernel(GemmP p)
{
    constexpr int BN    = BIG ? 128 : 64;
    constexpr int NTHR  = BIG ? 512 : 256;
    constexpr int TBKv  = BIG ? 64 : 32;
    constexpr int KP    = TBKv / 2;           // pairs per chunk
    constexpr int ALD2  = BIG ? 36 : 20;      // uint2 stride, A and NT-B
    constexpr int BLDN2 = BIG ? 132 : 68;     // uint2 stride, NN-B [kp][n]
    constexpr int AIT   = 128 * KP / NTHR;    // 8
    constexpr int BIT   = BN * KP / NTHR;     // 8 / 4
    constexpr int AAREA = 128 * ALD2;
    constexpr int BAREA = BIG ? 4608 : 1280;  // covers NT BN*ALD2 and NN KP*BLDN2
    constexpr int STAGE = AAREA + BAREA;

    extern __shared__ uint2 dsm2[];

    int z = blockIdx.z;
    int sk = z % p.splitK;
    int zz = z / p.splitK;
    int zb = zz / p.Hd, zh = zz % p.Hd;
    int bm = blockIdx.y * 128, bn = blockIdx.x * BN;
    int seg = bn / p.segW;
    int bnl = bn - seg * p.segW;

    const uint2* A = p.A + zb * p.sA0 + zh * p.sA1;
    const uint2* B = (seg == 0 ? p.B0 : seg == 1 ? p.B1 : p.B2) + zb * p.sB0 + zh * p.sB1;
    float* C = (seg == 0 ? p.C0 : seg == 1 ? p.C1 : p.C2) + zb * p.sC0 + zh * p.sC1;
    const float* bias = (seg == 0 ? p.bias0 : seg == 1 ? p.bias1 : p.bias2);
    if (bias) bias += zh * p.sBias;
    float scl = seg == 0 ? p.s0 : seg == 1 ? p.s1 : p.s2;
    bool atom = p.splitK > 1;

    int M = p.M, N = p.N;
    int ldap = p.ldap, ldbp = p.ldbp, ldc = p.ldc;
    int kpstart = (sk * p.kc) >> 1;
    int kpend = min(p.K, sk * p.kc + p.kc) >> 1;

    int tid  = threadIdx.x;
    int lane = tid & 31;
    int warp = tid >> 5;
    int g    = lane >> 2;
    int tig  = lane & 3;
    int m0w  = (warp & 3) * 32;
    int n0w  = (warp >> 2) * 32;

    float c[2][4][4];
#pragma unroll
    for (int mi = 0; mi < 2; mi++)
#pragma unroll
        for (int ni = 0; ni < 4; ni++)
#pragma unroll
            for (int e = 0; e < 4; e++) c[mi][ni][e] = 0.f;

    int iters = (kpend - kpstart + KP - 1) / KP;
    uint2 ra[AIT], rb[BIT];

    auto prefetch = [&](int kp0) {
#pragma unroll
        for (int i = 0; i < AIT; i++) {
            int pidx = i * NTHR + tid;
            int r = pidx / KP, kp = pidx % KP;
            int gr = bm + r, kpg = kp0 + kp;
            ra[i] = (gr < M && kpg < kpend) ? A[(long)gr * ldap + kpg] : make_uint2(0u, 0u);
        }
#pragma unroll
        for (int i = 0; i < BIT; i++) {
            int pidx = i * NTHR + tid;
            if (NT) {
                int n = pidx / KP, kp = pidx % KP;
                int kpg = kp0 + kp;
                rb[i] = (bn + n < N && kpg < kpend)
                      ? B[(long)(bnl + n) * ldbp + kpg] : make_uint2(0u, 0u);
            } else {
                int n = pidx % BN, kp = pidx / BN;
                int kpg = kp0 + kp;
                rb[i] = (bn + n < N && kpg < kpend)
                      ? B[(long)kpg * ldbp + bnl + n] : make_uint2(0u, 0u);
            }
        }
    };

    auto store_stage = [&](int s) {
        uint2* As = dsm2 + s * STAGE;
        uint2* Bs = As + AAREA;
#pragma unroll
        for (int i = 0; i < AIT; i++) {
            int pidx = i * NTHR + tid;
            int r = pidx / KP, kp = pidx % KP;
            As[r * ALD2 + kp] = ra[i];
        }
#pragma unroll
        for (int i = 0; i < BIT; i++) {
            int pidx = i * NTHR + tid;
            if (NT) {
                int n = pidx / KP, kp = pidx % KP;
                Bs[n * ALD2 + kp] = rb[i];
            } else {
                int n = pidx % BN, kp = pidx / BN;
                Bs[kp * BLDN2 + n] = rb[i];
            }
        }
    };

    prefetch(kpstart);
    store_stage(0);
    __syncthreads();

    for (int it = 0; it < iters; it++) {
        bool more = (it + 1 < iters);
        if (more) prefetch(kpstart + (it + 1) * KP);

        int s = it & 1;
        const uint2* As = dsm2 + s * STAGE;
        const uint2* Bs = As + AAREA;

#pragma unroll
        for (int h = 0; h < TBKv / 16; h++) {
            int kb = h * 8;
            uint32_t aH4[2][4], aL4[2][4];
#pragma unroll
            for (int mi = 0; mi < 2; mi++) {
                int m = m0w + mi * 16 + g;
                uint2 t0 = As[(m    ) * ALD2 + kb + tig];
                uint2 t1 = As[(m + 8) * ALD2 + kb + tig];
                uint2 t2 = As[(m    ) * ALD2 + kb + tig + 4];
                uint2 t3 = As[(m + 8) * ALD2 + kb + tig + 4];
                aH4[mi][0] = t0.x; aH4[mi][1] = t1.x; aH4[mi][2] = t2.x; aH4[mi][3] = t3.x;
                aL4[mi][0] = t0.y; aL4[mi][1] = t1.y; aL4[mi][2] = t2.y; aL4[mi][3] = t3.y;
            }
            uint32_t bh2[4][2], bl2[4][2];
#pragma unroll
            for (int ni = 0; ni < 4; ni++) {
                int n = n0w + ni * 8 + g;
                uint2 u0, u1;
                if (NT) {
                    u0 = Bs[n * ALD2 + kb + tig];
                    u1 = Bs[n * ALD2 + kb + tig + 4];
                } else {
                    u0 = Bs[(kb + tig) * BLDN2 + n];
                    u1 = Bs[(kb + tig + 4) * BLDN2 + n];
                }
                bh2[ni][0] = u0.x; bh2[ni][1] = u1.x;
                bl2[ni][0] = u0.y; bl2[ni][1] = u1.y;
            }
#pragma unroll
            for (int mi = 0; mi < 2; mi++)
#pragma unroll
                for (int ni = 0; ni < 4; ni++) {
                    mma_bf16(c[mi][ni], aH4[mi], bl2[ni]);
                    mma_bf16(c[mi][ni], aL4[mi], bh2[ni]);
                    mma_bf16(c[mi][ni], aH4[mi], bh2[ni]);
                }
        }

        if (more) store_stage(s ^ 1);
        __syncthreads();
    }

    // ---- epilogue ----
    if (p.CP) {
        int ldcp = ldc >> 1;
#pragma unroll
        for (int mi = 0; mi < 2; mi++) {
#pragma unroll
            for (int ni = 0; ni < 4; ni++) {
                float v[4];
#pragma unroll
                for (int e = 0; e < 4; e++) {
                    int lc = bn + n0w + ni * 8 + tig * 2 + (e & 1);
                    float t = c[mi][ni][e];
                    if (bias) t += bias[lc];
                    t *= scl;
                    if (p.act == 1) t = 0.5f * t * (1.f + erff(t * 0.70710678118654752f));
                    v[e] = t;
                }
                int row0 = bm + m0w + mi * 16 + g;
                int pc = (bn + n0w + ni * 8) / 2 + tig;
                if (row0 < M)     p.CP[(long)row0 * ldcp + pc]       = split2(v[0], v[1]);
                if (row0 + 8 < M) p.CP[(long)(row0 + 8) * ldcp + pc] = split2(v[2], v[3]);
            }
        }
    } else {
#pragma unroll
        for (int mi = 0; mi < 2; mi++) {
#pragma unroll
            for (int ni = 0; ni < 4; ni++) {
#pragma unroll
                for (int e = 0; e < 4; e++) {
                    int row = bm + m0w + mi * 16 + g + ((e >= 2) ? 8 : 0);
                    int gcol = bn + n0w + ni * 8 + tig * 2 + (e & 1);
                    if (row >= M || gcol >= N) continue;
                    int lc = gcol - seg * p.segW;
                    float v = c[mi][ni][e];
                    if (bias && (!atom || sk == 0)) v += bias[lc];
                    v *= scl;
                    long ci = (long)row * ldc + lc;
                    if (atom) {
                        atomicAdd(&C[ci], v);
                    } else {
                        if (p.act == 1) v = 0.5f * v * (1.f + erff(v * 0.70710678118654752f));
                        C[ci] = v;
                    }
                }
            }
        }
    }
}

// ---------------- fused flash attention (KV-split optional); packed final output ----------------
__global__ __launch_bounds__(128) void flash_kernel(
    const float* __restrict__ Qb, const float* __restrict__ Kb,
    const float* __restrict__ Vb, uint2* __restrict__ OPk,
    float* __restrict__ mir, int lenKV, long kvBStride, int causal,
    float* __restrict__ Opart, float2* __restrict__ Msum, int kvChunk)
{
    __shared__ uint32_t Kh[64][36], Kl[64][36];
    __shared__ uint32_t Vh[64][33], Vl[64][33];

    int mt = blockIdx.x;
    int by = blockIdx.y;
    int sp = blockIdx.z;
    int b = by / HH, hh = by % HH;

    int kvStart = sp * kvChunk;
    int kvEnd = min(lenKV, kvStart + kvChunk);

    const float* Q = Qb + ((long)b * TT + mt * 64) * DD + hh * DHH;
    const float* K = Kb + (long)b * kvBStride + hh * DHH;
    const float* V = Vb + (long)b * kvBStride + hh * DHH;
    float* Mr = (mir && b == 0)
              ? mir + (size_t)hh * TT * TAA + (size_t)mt * 64 * TAA : nullptr;

    int tid = threadIdx.x;
    int lane = tid & 31, warp = tid >> 5;
    int g = lane >> 2, tig = lane & 3;
    int m0w = warp * 16;

    uint32_t Qah[4][4], Qal[4][4];
#pragma unroll
    for (int kb = 0; kb < 4; kb++) {
        int c0 = 16 * kb + 2 * tig;
        const float* r0 = Q + (long)(m0w + g) * DD;
        const float* r1 = Q + (long)(m0w + g + 8) * DD;
        float2 v;
        v = *(const float2*)(r0 + c0);     split_pair(v, Qah[kb][0], Qal[kb][0]);
        v = *(const float2*)(r1 + c0);     split_pair(v, Qah[kb][1], Qal[kb][1]);
        v = *(const float2*)(r0 + c0 + 8); split_pair(v, Qah[kb][2], Qal[kb][2]);
        v = *(const float2*)(r1 + c0 + 8); split_pair(v, Qah[kb][3], Qal[kb][3]);
    }

    float acc[8][4];
#pragma unroll
    for (int j = 0; j < 8; j++)
#pragma unroll
        for (int e = 0; e < 4; e++) acc[j][e] = 0.f;
    float m0 = -1e30f, m1 = -1e30f, sum0 = 0.f, sum1 = 0.f;

    int chBeg = kvStart >> 6;
    int chEnd = (kvEnd + 63) >> 6;
    if (causal) chEnd = min(chEnd, mt + 1);

    for (int ch = chBeg; ch < chEnd; ch++) {
        int n0 = ch * 64;
#pragma unroll
        for (int i = 0; i < 16; i++) {
            int idx = i * 128 + tid;
            int r = idx >> 5, c = idx & 31;
            float2 v = {0.f, 0.f};
            if (n0 + r < kvEnd) v = *(const float2*)(K + (long)(n0 + r) * DD + 2 * c);
            split_pair(v, Kh[r][c], Kl[r][c]);
        }
#pragma unroll
        for (int i = 0; i < 16; i++) {
            int idx = i * 128 + tid;
            int d = idx & 63, pr = idx >> 6;
            float2 v = {0.f, 0.f};
            int r0i = n0 + 2 * pr;
            if (r0i < kvEnd)     v.x = V[(long)r0i * DD + d];
            if (r0i + 1 < kvEnd) v.y = V[(long)(r0i + 1) * DD + d];
            split_pair(v, Vh[d][pr], Vl[d][pr]);
        }
        __syncthreads();

        float s[8][4];
#pragma unroll
        for (int j = 0; j < 8; j++)
#pragma unroll
            for (int e = 0; e < 4; e++) s[j][e] = 0.f;
#pragma unroll
        for (int kb = 0; kb < 4; kb++) {
#pragma unroll
            for (int j = 0; j < 8; j++) {
                uint32_t bh[2] = { Kh[8 * j + g][8 * kb + tig], Kh[8 * j + g][8 * kb + tig + 4] };
                uint32_t bl[2] = { Kl[8 * j + g][8 * kb + tig], Kl[8 * j + g][8 * kb + tig + 4] };
                mma_bf16(s[j], Qah[kb], bl);
                mma_bf16(s[j], Qal[kb], bh);
                mma_bf16(s[j], Qah[kb], bh);
            }
        }

        if (Mr) {
#pragma unroll
            for (int j = 0; j < 8; j++) {
                int col = n0 + 8 * j + 2 * tig;
                if (col < kvEnd) {
                    float2 v0 = { s[j][0], s[j][1] };
                    float2 v1 = { s[j][2], s[j][3] };
                    *(float2*)&Mr[(long)(m0w + g) * TAA + col] = v0;
                    *(float2*)&Mr[(long)(m0w + g + 8) * TAA + col] = v1;
                }
            }
        }

        if (causal && ch == mt) {
            int t0 = mt * 64 + m0w + g;
#pragma unroll
            for (int j = 0; j < 8; j++) {
                int col = n0 + 8 * j + 2 * tig;
                if (col     > t0)     s[j][0] = -1e30f;
                if (col + 1 > t0)     s[j][1] = -1e30f;
                if (col     > t0 + 8) s[j][2] = -1e30f;
                if (col + 1 > t0 + 8) s[j][3] = -1e30f;
            }
        }
        if (n0 + 64 > kvEnd) {
#pragma unroll
            for (int j = 0; j < 8; j++) {
                int col = n0 + 8 * j + 2 * tig;
                if (col     >= kvEnd) { s[j][0] = -1e30f; s[j][2] = -1e30f; }
                if (col + 1 >= kvEnd) { s[j][1] = -1e30f; s[j][3] = -1e30f; }
            }
        }

        float mx0 = -1e30f, mx1 = -1e30f;
#pragma unroll
        for (int j = 0; j < 8; j++) {
            mx0 = fmaxf(mx0, fmaxf(s[j][0], s[j][1]));
            mx1 = fmaxf(mx1, fmaxf(s[j][2], s[j][3]));
        }
        mx0 = fmaxf(mx0, __shfl_xor_sync(0xffffffffu, mx0, 1));
        mx0 = fmaxf(mx0, __shfl_xor_sync(0xffffffffu, mx0, 2));
        mx1 = fmaxf(mx1, __shfl_xor_sync(0xffffffffu, mx1, 1));
        mx1 = fmaxf(mx1, __shfl_xor_sync(0xffffffffu, mx1, 2));
        float mn0 = fmaxf(m0, mx0), mn1 = fmaxf(m1, mx1);
        float a0 = __expf(m0 - mn0), a1 = __expf(m1 - mn1);
        float ps0 = 0.f, ps1 = 0.f;
#pragma unroll
        for (int j = 0; j < 8; j++) {
            s[j][0] = __expf(s[j][0] - mn0);
            s[j][1] = __expf(s[j][1] - mn0);
            s[j][2] = __expf(s[j][2] - mn1);
            s[j][3] = __expf(s[j][3] - mn1);
            ps0 += s[j][0] + s[j][1];
            ps1 += s[j][2] + s[j][3];
        }
        ps0 += __shfl_xor_sync(0xffffffffu, ps0, 1);
        ps0 += __shfl_xor_sync(0xffffffffu, ps0, 2);
        ps1 += __shfl_xor_sync(0xffffffffu, ps1, 1);
        ps1 += __shfl_xor_sync(0xffffffffu, ps1, 2);
        sum0 = sum0 * a0 + ps0;
        sum1 = sum1 * a1 + ps1;
        m0 = mn0; m1 = mn1;
#pragma unroll
        for (int j = 0; j < 8; j++) {
            acc[j][0] *= a0; acc[j][1] *= a0;
            acc[j][2] *= a1; acc[j][3] *= a1;
        }

#pragma unroll
        for (int kb = 0; kb < 4; kb++) {
            int j0 = 2 * kb, j1 = 2 * kb + 1;
            uint32_t Ah[4], Al[4];
            Ah[0] = pack_bf(s[j0][0], s[j0][1]);  Al[0] = lo_pack(s[j0][0], s[j0][1]);
            Ah[1] = pack_bf(s[j0][2], s[j0][3]);  Al[1] = lo_pack(s[j0][2], s[j0][3]);
            Ah[2] = pack_bf(s[j1][0], s[j1][1]);  Al[2] = lo_pack(s[j1][0], s[j1][1]);
            Ah[3] = pack_bf(s[j1][2], s[j1][3]);  Al[3] = lo_pack(s[j1][2], s[j1][3]);
#pragma unroll
            for (int jd = 0; jd < 8; jd++) {
                uint32_t bh[2] = { Vh[8 * jd + g][8 * kb + tig], Vh[8 * jd + g][8 * kb + tig + 4] };
                uint32_t bl[2] = { Vl[8 * jd + g][8 * kb + tig], Vl[8 * jd + g][8 * kb + tig + 4] };
                mma_bf16(acc[jd], Ah, bl);
                mma_bf16(acc[jd], Al, bh);
                mma_bf16(acc[jd], Ah, bh);
            }
        }
        __syncthreads();
    }

    if (Opart) {
        float* OP = Opart + (((long)sp * BT) + (long)b * TT + mt * 64) * DD + hh * DHH;
#pragma unroll
        for (int jd = 0; jd < 8; jd++) {
            int col = 8 * jd + 2 * tig;
            float2 v0 = { acc[jd][0], acc[jd][1] };
            float2 v1 = { acc[jd][2], acc[jd][3] };
            *(float2*)&OP[(long)(m0w + g) * DD + col] = v0;
            *(float2*)&OP[(long)(m0w + g + 8) * DD + col] = v1;
        }
        if (tig == 0) {
            long base = (((long)sp * BB + b) * HH + hh) * TT + mt * 64;
            Msum[base + m0w + g]     = make_float2(m0, sum0);
            Msum[base + m0w + g + 8] = make_float2(m1, sum1);
        }
    } else {
        uint2* O2 = OPk + ((long)b * TT + mt * 64) * DP + hh * 32;
        float i0 = 1.f / sum0, i1 = 1.f / sum1;
#pragma unroll
        for (int jd = 0; jd < 8; jd++) {
            int pc = 4 * jd + tig;
            O2[(long)(m0w + g) * DP + pc]     = split2(acc[jd][0] * i0, acc[jd][1] * i0);
            O2[(long)(m0w + g + 8) * DP + pc] = split2(acc[jd][2] * i1, acc[jd][3] * i1);
        }
    }
}

__global__ __launch_bounds__(256) void flash_merge_kernel(
    const float* __restrict__ Opart, const float2* __restrict__ Msum,
    uint2* __restrict__ OPk)
{
    __shared__ float wgt[HH][NSPLIT];
    int row = blockIdx.x;
    int b = row / TT, t = row % TT;
    int tid = threadIdx.x;
    if (tid < HH) {
        int h = tid;
        float ms[NSPLIT], ss[NSPLIT];
        float m = -1e30f;
#pragma unroll
        for (int s = 0; s < NSPLIT; s++) {
            float2 v = Msum[(((long)s * BB + b) * HH + h) * TT + t];
            ms[s] = v.x; ss[s] = v.y;
            m = fmaxf(m, v.x);
        }
        float den = 0.f;
#pragma unroll
        for (int s = 0; s < NSPLIT; s++) den += ss[s] * __expf(ms[s] - m);
        float iden = 1.f / den;
#pragma unroll
        for (int s = 0; s < NSPLIT; s++) wgt[h][s] = __expf(ms[s] - m) * iden;
    }
    __syncthreads();
#pragma unroll
    for (int it = 0; it < 2; it++) {
        int pd = tid + it * 256;
        if (pd >= DP) break;
        int h = pd >> 5;
        float a0 = 0.f, a1 = 0.f;
#pragma unroll
        for (int s = 0; s < NSPLIT; s++) {
            const float* op = &Opart[(((long)s * BT) + row) * DD + 2 * pd];
            a0 += op[0] * wgt[h][s];
            a1 += op[1] * wgt[h][s];
        }
        OPk[(long)row * DP + pd] = split2(a0, a1);
    }
}

// ---------------- elementwise / row kernels ----------------
__global__ __launch_bounds__(256) void embed_kernel(
    const int* __restrict__ tokens, const float* __restrict__ tok_emb,
    const float* __restrict__ pos_emb, float* __restrict__ x)
{
    int row = blockIdx.x;
    int t = row % TT;
    int tok = tokens[row];
    const float* te = tok_emb + (long)tok * DD;
    const float* pe = pos_emb + (long)t * DD;
    float* xr = x + (long)row * DD;
#pragma unroll
    for (int it = 0; it < 3; it++) {
        int j = threadIdx.x + it * 256;
        xr[j] = te[j] + pe[j];
    }
}

// LayerNorm emitting packed hi/lo bf16 pairs
__global__ __launch_bounds__(256) void ln_pack_kernel(
    const float* __restrict__ x, uint2* __restrict__ y,
    const float* __restrict__ g, const float* __restrict__ b)
{
    __shared__ float red[256];
    int row = blockIdx.x;
    const float* xr = x + (long)row * DD;
    uint2* yr = y + (long)row * DP;
    int tid = threadIdx.x;
    float v0 = xr[tid], v1 = xr[tid + 256], v2 = xr[tid + 512];
    float s = v0 + v1 + v2;
    red[tid] = s; __syncthreads();
    for (int st = 128; st > 0; st >>= 1) { if (tid < st) red[tid] += red[tid + st]; __syncthreads(); }
    float mean = red[0] * (1.f / DD);
    __syncthreads();
    float d0 = v0 - mean, d1 = v1 - mean, d2 = v2 - mean;
    red[tid] = d0 * d0 + d1 * d1 + d2 * d2; __syncthreads();
    for (int st = 128; st > 0; st >>= 1) { if (tid < st) red[tid] += red[tid + st]; __syncthreads(); }
    float inv = rsqrtf(red[0] * (1.f / DD) + 1e-5f);
    {
        int c0 = 2 * tid;
        float a = (xr[c0]     - mean) * inv * g[c0]     + b[c0];
        float c = (xr[c0 + 1] - mean) * inv * g[c0 + 1] + b[c0 + 1];
        yr[tid] = split2(a, c);
    }
    if (tid < 128) {
        int p1 = tid + 256;
        int c0 = 2 * p1;
        float a = (xr[c0]     - mean) * inv * g[c0]     + b[c0];
        float c = (xr[c0 + 1] - mean) * inv * g[c0 + 1] + b[c0 + 1];
        yr[p1] = split2(a, c);
    }
}

// ---------------- host-side launch helpers ----------------
static GemmP base_p() {
    GemmP p;
    p.A = nullptr; p.B0 = p.B1 = p.B2 = nullptr;
    p.C0 = p.C1 = p.C2 = nullptr; p.CP = nullptr;
    p.bias0 = p.bias1 = p.bias2 = nullptr;
    p.M = p.N = p.K = 0; p.ldap = p.ldbp = p.ldc = 0;
    p.Hd = 1; p.segW = 1 << 30; p.act = 0; p.splitK = 1; p.kc = 0;
    p.sA0 = p.sA1 = p.sB0 = p.sB1 = p.sC0 = p.sC1 = p.sBias = 0;
    p.s0 = p.s1 = p.s2 = 1.f;
    return p;
}

static inline int smem_bytes(int BIG) {
    int ALD2 = BIG ? 36 : 20;
    int AAREA = 128 * ALD2;
    int BAREA = BIG ? 4608 : 1280;
    return 2 * (AAREA + BAREA) * 8;
}

template <int NT, int BIG>
static inline void launch_g(GemmP p, int batch, int splitK = 1) {
    p.splitK = splitK;
    constexpr int TBKv = BIG ? 64 : 32;
    int kc = (p.K + splitK - 1) / splitK;
    p.kc = ((kc + TBKv - 1) / TBKv) * TBKv;
    constexpr int BN = BIG ? 128 : 64;
    constexpr int NTHR = BIG ? 512 : 256;
    dim3 grd((p.N + BN - 1) / BN, (p.M + 127) / 128, batch * splitK);
    gemm_bf3_kernel<NT, BIG><<<grd, NTHR, smem_bytes(BIG)>>>(p);
}

static inline int pkblocks(long n) {
    long b = (n + 255) / 256;
    return (int)(b > 8192 ? 8192 : b);
}

extern "C" void kernel_launch(void* const* d_in, const int* in_sizes, int n_in,
                              void* d_out, int out_size)
{
    (void)in_sizes; (void)n_in; (void)out_size;

    cudaFuncSetAttribute(gemm_bf3_kernel<0, 0>, cudaFuncAttributeMaxDynamicSharedMemorySize, smem_bytes(0));
    cudaFuncSetAttribute(gemm_bf3_kernel<1, 0>, cudaFuncAttributeMaxDynamicSharedMemorySize, smem_bytes(0));
    cudaFuncSetAttribute(gemm_bf3_kernel<0, 1>, cudaFuncAttributeMaxDynamicSharedMemorySize, smem_bytes(1));
    cudaFuncSetAttribute(gemm_bf3_kernel<1, 1>, cudaFuncAttributeMaxDynamicSharedMemorySize, smem_bytes(1));

    const int*   tokens  = (const int*)  d_in[0];
    const float* xa      = (const float*)d_in[1];
    const float* tok_emb = (const float*)d_in[2];
    const float* pos_emb = (const float*)d_in[3];
    const float* Wq      = (const float*)d_in[4];
    const float* bq      = (const float*)d_in[5];
    const float* Wk      = (const float*)d_in[6];
    const float* Wv      = (const float*)d_in[7];
    const float* bv      = (const float*)d_in[8];
    const float* Wo      = (const float*)d_in[9];
    const float* bo      = (const float*)d_in[10];
    const float* ln1_g   = (const float*)d_in[11];
    const float* ln1_b   = (const float*)d_in[12];
    const float* Wcq     = (const float*)d_in[13];
    const float* bcq     = (const float*)d_in[14];
    const float* Wck     = (const float*)d_in[15];
    const float* Wcv     = (const float*)d_in[16];
    const float* bcv     = (const float*)d_in[17];
    const float* Wco     = (const float*)d_in[18];
    const float* bco     = (const float*)d_in[19];
    const float* ln2_g   = (const float*)d_in[20];
    const float* ln2_b   = (const float*)d_in[21];
    const float* W1      = (const float*)d_in[22];
    const float* b1      = (const float*)d_in[23];
    const float* W2      = (const float*)d_in[24];
    const float* b2      = (const float*)d_in[25];
    const float* ln3_g   = (const float*)d_in[26];
    const float* ln3_b   = (const float*)d_in[27];
    const float* lnf_g   = (const float*)d_in[28];
    const float* lnf_b   = (const float*)d_in[29];

    float* out = (float*)d_out;
    float* out_logits = out;
    float* out_chw    = out_logits + (size_t)BB * TT * VV;
    float* out_kv     = out_chw + (size_t)(LL / 2) * HH * TT * TAA;

    float *x, *q, *ckall, *cvall, *opart;
    float2* msum;
    uint2 *hP, *oP, *hidP, *xaP, *tokP;
    uint2 *WqP, *WkP, *WvP, *WoP, *WcqP, *WckP, *WcvP, *WcoP, *W1P, *W2P;
    cudaGetSymbolAddress((void**)&x,     g_x);
    cudaGetSymbolAddress((void**)&q,     g_q);
    cudaGetSymbolAddress((void**)&ckall, g_ckall);
    cudaGetSymbolAddress((void**)&cvall, g_cvall);
    cudaGetSymbolAddress((void**)&opart, g_opart);
    cudaGetSymbolAddress((void**)&msum,  g_msum);
    cudaGetSymbolAddress((void**)&hP,    g_hP);
    cudaGetSymbolAddress((void**)&oP,    g_oP);
    cudaGetSymbolAddress((void**)&hidP,  g_hidP);
    cudaGetSymbolAddress((void**)&xaP,   g_xaP);
    cudaGetSymbolAddress((void**)&tokP,  g_tokP);
    cudaGetSymbolAddress((void**)&WqP,   g_WqP);
    cudaGetSymbolAddress((void**)&WkP,   g_WkP);
    cudaGetSymbolAddress((void**)&WvP,   g_WvP);
    cudaGetSymbolAddress((void**)&WoP,   g_WoP);
    cudaGetSymbolAddress((void**)&WcqP,  g_WcqP);
    cudaGetSymbolAddress((void**)&WckP,  g_WckP);
    cudaGetSymbolAddress((void**)&WcvP,  g_WcvP);
    cudaGetSymbolAddress((void**)&WcoP,  g_WcoP);
    cudaGetSymbolAddress((void**)&W1P,   g_W1P);
    cudaGetSymbolAddress((void**)&W2P,   g_W2P);

    // ---- prepack weights / constants ----
    {
        long n;
        n = (long)BB * TAA * DP;
        pack_contig_kernel<<<pkblocks(n), 256>>>(xa, xaP, n);
        n = (long)VV * DP;
        pack_contig_kernel<<<pkblocks(n), 256>>>(tok_emb, tokP, n);
        long nw = (long)LL * DP * DD;
        pack_strideK_kernel<<<pkblocks(nw), 256>>>(Wq,  WqP,  DP, DD, nw);
        pack_strideK_kernel<<<pkblocks(nw), 256>>>(Wk,  WkP,  DP, DD, nw);
        pack_strideK_kernel<<<pkblocks(nw), 256>>>(Wv,  WvP,  DP, DD, nw);
        pack_strideK_kernel<<<pkblocks(nw), 256>>>(Wo,  WoP,  DP, DD, nw);
        pack_strideK_kernel<<<pkblocks(nw), 256>>>(Wcq, WcqP, DP, DD, nw);
        pack_strideK_kernel<<<pkblocks(nw), 256>>>(Wck, WckP, DP, DD, nw);
        pack_strideK_kernel<<<pkblocks(nw), 256>>>(Wcv, WcvP, DP, DD, nw);
        pack_strideK_kernel<<<pkblocks(nw), 256>>>(Wco, WcoP, DP, DD, nw);
        long n1 = (long)LL * DP * 4 * DD;
        pack_strideK_kernel<<<pkblocks(n1), 256>>>(W1, W1P, DP, 4 * DD, n1);
        long n2 = (long)LL * 2 * DD * DD;
        pack_strideK_kernel<<<pkblocks(n2), 256>>>(W2, W2P, 2 * DD, DD, n2);
    }

    embed_kernel<<<BT, 256>>>(tokens, tok_emb, pos_emb, x);

    const long DTD = (long)TT * DD;
    const long TAD = (long)TAA * DD;
    const size_t XBYTES = (size_t)BT * DD * sizeof(float);
    const int KVCH = ((TAA + NSPLIT * 64 - 1) / (NSPLIT * 64)) * 64;   // 384

    // cross K/V for ALL layers, batched over z=12 (BIG tiles)
    {
        GemmP p = base_p();
        p.A = xaP; p.ldap = DP;
        p.B0 = WckP; p.ldbp = DD; p.sB1 = (long)DP * DD;
        p.C0 = ckall; p.ldc = DD; p.sC1 = (long)BTAD;
        p.M = BB * TAA; p.N = DD; p.K = DD; p.Hd = LL;
        launch_g<0, 1>(p, LL);
        p.B0 = WcvP; p.C0 = cvall;
        p.bias0 = bcv; p.sBias = DD;
        launch_g<0, 1>(p, LL);
    }

    for (int l = 0; l < LL; l++) {
        float* kout = out_kv + (size_t)(2 * l) * BT * DD;
        float* vout = out_kv + (size_t)(2 * l + 1) * BT * DD;
        float* ck_l = ckall + (size_t)l * BTAD;
        float* cv_l = cvall + (size_t)l * BTAD;
        const long WOFF = (long)l * DP * DD;

        // ---- self attention ----
        ln_pack_kernel<<<BT, 256>>>(x, hP, ln1_g + l * DD, ln1_b + l * DD);
        {   // fused QKV (BIG)
            GemmP p = base_p();
            p.A = hP; p.ldap = DP;
            p.B0 = WqP + WOFF; p.B1 = WkP + WOFF; p.B2 = WvP + WOFF; p.ldbp = DD;
            p.C0 = q; p.C1 = kout; p.C2 = vout; p.ldc = DD;
            p.bias0 = bq + l * DD; p.bias1 = nullptr; p.bias2 = bv + l * DD;
            p.s0 = SCALE_Q; p.s1 = 1.f; p.s2 = 1.f;
            p.segW = DD;
            p.M = BT; p.N = 3 * DD; p.K = DD;
            launch_g<0, 1>(p, 1);
        }
        flash_kernel<<<dim3(TT / 64, BB * HH, 1), 128>>>(
            q, kout, vout, oP, nullptr, TT, DTD, 1, nullptr, nullptr, TT);
        {   // x += o @ Wo + bo  (small, split-K atomics)
            GemmP p = base_p();
            p.A = oP; p.ldap = DP;
            p.B0 = WoP + WOFF; p.ldbp = DD;
            p.C0 = x; p.ldc = DD;
            p.bias0 = bo + l * DD;
            p.M = BT; p.N = DD; p.K = DD;
            launch_g<0, 0>(p, 1, 4);
        }

        // ---- cross attention ----
        ln_pack_kernel<<<BT, 256>>>(x, hP, ln2_g + l * DD, ln2_b + l * DD);
        cudaMemsetAsync(q, 0, XBYTES);
        {   // q2 (small, split-K atomics)
            GemmP p = base_p();
            p.A = hP; p.ldap = DP;
            p.B0 = WcqP + WOFF; p.ldbp = DD;
            p.C0 = q; p.ldc = DD;
            p.bias0 = bcq + l * DD; p.s0 = SCALE_Q;
            p.M = BT; p.N = DD; p.K = DD;
            launch_g<0, 0>(p, 1, 4);
        }
        {
            float* mir = (l >= LL / 2)
                       ? out_chw + (size_t)(l - LL / 2) * HH * TT * TAA : nullptr;
            flash_kernel<<<dim3(TT / 64, BB * HH, NSPLIT), 128>>>(
                q, ck_l, cv_l, nullptr, mir, TAA, TAD, 0, opart, msum, KVCH);
            flash_merge_kernel<<<BT, 256>>>(opart, msum, oP);
        }
        {   // x += o @ Wco + bco  (small, split-K atomics)
            GemmP p = base_p();
            p.A = oP; p.ldap = DP;
            p.B0 = WcoP + WOFF; p.ldbp = DD;
            p.C0 = x; p.ldc = DD;
            p.bias0 = bco + l * DD;
            p.M = BT; p.N = DD; p.K = DD;
            launch_g<0, 0>(p, 1, 4);
        }

        // ---- MLP ----
        ln_pack_kernel<<<BT, 256>>>(x, hP, ln3_g + l * DD, ln3_b + l * DD);
        {   // hidP = pack(gelu(h @ W1 + b1))  (BIG, packed epilogue)
            GemmP p = base_p();
            p.A = hP; p.ldap = DP;
            p.B0 = W1P + (long)l * DP * 4 * DD; p.ldbp = 4 * DD;
            p.CP = hidP; p.ldc = 4 * DD;
            p.bias0 = b1 + (size_t)l * 4 * DD; p.act = 1;
            p.M = BT; p.N = 4 * DD; p.K = DD;
            launch_g<0, 1>(p, 1);
        }
        {   // x += hid @ W2 + b2  (BIG, split-K 8)
            GemmP p = base_p();
            p.A = hidP; p.ldap = 2 * DD;
            p.B0 = W2P + (long)l * 2 * DD * DD; p.ldbp = DD;
            p.C0 = x; p.ldc = DD;
            p.bias0 = b2 + l * DD;
            p.M = BT; p.N = DD; p.K = 4 * DD;
            launch_g<0, 1>(p, 1, 8);
        }
    }

    // final LN + tied-embedding logits (BIG NT)
    ln_pack_kernel<<<BT, 256>>>(x, hP, lnf_g, lnf_b);
    {
        GemmP p = base_p();
        p.A = hP; p.ldap = DP;
        p.B0 = tokP; p.ldbp = DP;
        p.C0 = out_logits; p.ldc = VV;
        p.M = BT; p.N = VV; p.K = DD;
        launch_g<1, 1>(p, 1);
    }
}

// round 14
// speedup vs baseline: 1.4148x; 1.3266x over previous
#include <cuda_runtime.h>
#include <cuda_bf16.h>
#include <cuda_fp16.h>
#include <math.h>
#include <stdint.h>

// ---------------- problem constants ----------------
#define BB   4
#define TT   256
#define TAA  1500
#define DD   768
#define HH   12
#define LL   12
#define VV   51865
#define DHH  64
#define BT   (BB*TT)          // 1024
#define DP   (DD/2)           // 384 pairs
#define SCALE_Q 0.125f
#define BTAD ((size_t)BB*TAA*DD)
#define NSPLIT 4

// ---------------- scratch ----------------
__device__ float g_x  [BT*DD];
__device__ float g_q  [BT*DD];
__device__ float g_ckall[(size_t)LL*BTAD];
__device__ float g_cvall[(size_t)LL*BTAD];
__device__ float g_opart[(size_t)NSPLIT*BT*DD];
__device__ float2 g_msum[(size_t)NSPLIT*BB*HH*TT];

// A-side packed fp16 hi/lo (uint2: x=hi pair, y=lo pair)
__device__ uint2 g_hP  [(size_t)BT*DP];
__device__ uint2 g_oP  [(size_t)BT*DP];
__device__ uint2 g_hidP[(size_t)BT*2*DD];
__device__ uint2 g_xaP [(size_t)BB*TAA*DP];
// B-side packed fp16 hi-only (uint32 pair)
__device__ uint32_t g_tokP[(size_t)VV*DP];
__device__ uint32_t g_WqP [(size_t)LL*DP*DD];
__device__ uint32_t g_WkP [(size_t)LL*DP*DD];
__device__ uint32_t g_WvP [(size_t)LL*DP*DD];
__device__ uint32_t g_WoP [(size_t)LL*DP*DD];
__device__ uint32_t g_WcqP[(size_t)LL*DP*DD];
__device__ uint32_t g_WckP[(size_t)LL*DP*DD];
__device__ uint32_t g_WcvP[(size_t)LL*DP*DD];
__device__ uint32_t g_WcoP[(size_t)LL*DP*DD];
__device__ uint32_t g_W1P [(size_t)LL*DP*4*DD];
__device__ uint32_t g_W2P [(size_t)LL*2*DD*DD];

// ---------------- helpers ----------------
__device__ __forceinline__ uint32_t h2pack(float a, float b) {
    __half2 t = __floats2half2_rn(a, b);
    return *(uint32_t*)&t;
}

__device__ __forceinline__ void splitf16(float2 v, uint32_t& hi, uint32_t& lo) {
    __half hx = __float2half_rn(v.x);
    __half hy = __float2half_rn(v.y);
    __half2 h; h.x = hx; h.y = hy;
    hi = *(uint32_t*)&h;
    lo = h2pack(v.x - __half2float(hx), v.y - __half2float(hy));
}

__device__ __forceinline__ uint2 split2(float a, float b) {
    uint32_t hi, lo;
    splitf16(make_float2(a, b), hi, lo);
    return make_uint2(hi, lo);
}

__device__ __forceinline__ uint32_t lo_pack(float a, float b) {
    float ra = a - __half2float(__float2half_rn(a));
    float rb = b - __half2float(__float2half_rn(b));
    return h2pack(ra, rb);
}

__device__ __forceinline__ void mma_f16(float* c, const uint32_t* a, const uint32_t* b) {
    asm volatile(
        "mma.sync.aligned.m16n8k16.row.col.f32.f16.f16.f32 "
        "{%0,%1,%2,%3}, {%4,%5,%6,%7}, {%8,%9}, {%0,%1,%2,%3};"
        : "+f"(c[0]), "+f"(c[1]), "+f"(c[2]), "+f"(c[3])
        : "r"(a[0]), "r"(a[1]), "r"(a[2]), "r"(a[3]), "r"(b[0]), "r"(b[1]));
}

// ---------------- prepack kernels ----------------
// A-side: contiguous fp32 pairs -> uint2 (hi,lo)
__global__ __launch_bounds__(256) void pack_contig_kernel(
    const float* __restrict__ in, uint2* __restrict__ out, long n)
{
    long i = blockIdx.x * 256L + threadIdx.x;
    long stride = (long)gridDim.x * 256;
    for (; i < n; i += stride) {
        float2 v = ((const float2*)in)[i];
        uint32_t hi, lo; splitf16(v, hi, lo);
        out[i] = make_uint2(hi, lo);
    }
}

// B-side NT: contiguous fp32 pairs -> uint32 hi
__global__ __launch_bounds__(256) void pack_contig_hi_kernel(
    const float* __restrict__ in, uint32_t* __restrict__ out, long n)
{
    long i = blockIdx.x * 256L + threadIdx.x;
    long stride = (long)gridDim.x * 256;
    for (; i < n; i += stride) {
        float2 v = ((const float2*)in)[i];
        out[i] = h2pack(v.x, v.y);
    }
}

// B-side NN: [B][K][N] fp32 -> [B][K/2][N] uint32 hi (pairs along K)
__global__ __launch_bounds__(256) void pack_strideK_hi_kernel(
    const float* __restrict__ in, uint32_t* __restrict__ out,
    int Khalf, int N, long total)
{
    long i = blockIdx.x * 256L + threadIdx.x;
    long stride = (long)gridDim.x * 256;
    for (; i < total; i += stride) {
        int n = (int)(i % N);
        long r = i / N;
        int kp = (int)(r % Khalf);
        long b = r / Khalf;
        const float* base = in + b * (long)Khalf * 2 * N;
        out[i] = h2pack(base[(long)(2 * kp) * N + n], base[(long)(2 * kp + 1) * N + n]);
    }
}

// ---------------- packed fp16 GEMM (2-term) + split-K, double-buffered ----------------
struct GemmP {
    const uint2 *A;
    const uint32_t *B0, *B1, *B2;
    float *C0, *C1, *C2;
    uint2 *CP;
    const float *bias0, *bias1, *bias2;
    int M, N, K, ldap, ldbp, ldc, Hd, segW, act, splitK, kc;
    long sA0, sA1, sB0, sB1, sC0, sC1, sBias;
    float s0, s1, s2;
};

template <int NT, int BIG>
__global__ __launch_bounds__(BIG ? 512 : 256, BIG ? 1 : 2) void gemm_f16_kernel(GemmP p)
{
    constexpr int BN    = BIG ? 128 : 64;
    constexpr int NTHR  = BIG ? 512 : 256;
    constexpr int TBKv  = BIG ? 64 : 32;
    constexpr int KP    = TBKv / 2;
    constexpr int ALD2  = BIG ? 36 : 20;      // uint2 stride, A
    constexpr int BLD1  = BIG ? 36 : 20;      // u32 stride, NT-B [n][kp]
    constexpr int BLDN1 = BIG ? 132 : 68;     // u32 stride, NN-B [kp][n]
    constexpr int AIT   = 128 * KP / NTHR;    // 8
    constexpr int BIT   = BN * KP / NTHR;     // 8 / 4
    constexpr int AAREA2 = 128 * ALD2;                    // uint2 units
    constexpr int BAREA1 = BIG ? 4608 : 1280;             // u32 units
    constexpr int STAGE1 = AAREA2 * 2 + BAREA1;           // u32 units

    extern __shared__ uint32_t dsm1[];

    int z = blockIdx.z;
    int sk = z % p.splitK;
    int zz = z / p.splitK;
    int zb = zz / p.Hd, zh = zz % p.Hd;
    int bm = blockIdx.y * 128, bn = blockIdx.x * BN;
    int seg = bn / p.segW;
    int bnl = bn - seg * p.segW;

    const uint2* A = p.A + zb * p.sA0 + zh * p.sA1;
    const uint32_t* B = (seg == 0 ? p.B0 : seg == 1 ? p.B1 : p.B2) + zb * p.sB0 + zh * p.sB1;
    float* C = (seg == 0 ? p.C0 : seg == 1 ? p.C1 : p.C2) + zb * p.sC0 + zh * p.sC1;
    const float* bias = (seg == 0 ? p.bias0 : seg == 1 ? p.bias1 : p.bias2);
    if (bias) bias += zh * p.sBias;
    float scl = seg == 0 ? p.s0 : seg == 1 ? p.s1 : p.s2;
    bool atom = p.splitK > 1;

    int M = p.M, N = p.N;
    int ldap = p.ldap, ldbp = p.ldbp, ldc = p.ldc;
    int kpstart = (sk * p.kc) >> 1;
    int kpend = min(p.K, sk * p.kc + p.kc) >> 1;

    int tid  = threadIdx.x;
    int lane = tid & 31;
    int warp = tid >> 5;
    int g    = lane >> 2;
    int tig  = lane & 3;
    int m0w  = (warp & 3) * 32;
    int n0w  = (warp >> 2) * 32;

    float c[2][4][4];
#pragma unroll
    for (int mi = 0; mi < 2; mi++)
#pragma unroll
        for (int ni = 0; ni < 4; ni++)
#pragma unroll
            for (int e = 0; e < 4; e++) c[mi][ni][e] = 0.f;

    int iters = (kpend - kpstart + KP - 1) / KP;
    uint2 ra[AIT];
    uint32_t rb[BIT];

    auto prefetch = [&](int kp0) {
#pragma unroll
        for (int i = 0; i < AIT; i++) {
            int pidx = i * NTHR + tid;
            int r = pidx / KP, kp = pidx % KP;
            int gr = bm + r, kpg = kp0 + kp;
            ra[i] = (gr < M && kpg < kpend) ? A[(long)gr * ldap + kpg] : make_uint2(0u, 0u);
        }
#pragma unroll
        for (int i = 0; i < BIT; i++) {
            int pidx = i * NTHR + tid;
            if (NT) {
                int n = pidx / KP, kp = pidx % KP;
                int kpg = kp0 + kp;
                rb[i] = (bn + n < N && kpg < kpend) ? B[(long)(bnl + n) * ldbp + kpg] : 0u;
            } else {
                int n = pidx % BN, kp = pidx / BN;
                int kpg = kp0 + kp;
                rb[i] = (bn + n < N && kpg < kpend) ? B[(long)kpg * ldbp + bnl + n] : 0u;
            }
        }
    };

    auto store_stage = [&](int s) {
        uint2* As = (uint2*)(dsm1 + s * STAGE1);
        uint32_t* Bs = dsm1 + s * STAGE1 + AAREA2 * 2;
#pragma unroll
        for (int i = 0; i < AIT; i++) {
            int pidx = i * NTHR + tid;
            int r = pidx / KP, kp = pidx % KP;
            As[r * ALD2 + kp] = ra[i];
        }
#pragma unroll
        for (int i = 0; i < BIT; i++) {
            int pidx = i * NTHR + tid;
            if (NT) {
                int n = pidx / KP, kp = pidx % KP;
                Bs[n * BLD1 + kp] = rb[i];
            } else {
                int n = pidx % BN, kp = pidx / BN;
                Bs[kp * BLDN1 + n] = rb[i];
            }
        }
    };

    prefetch(kpstart);
    store_stage(0);
    __syncthreads();

    for (int it = 0; it < iters; it++) {
        bool more = (it + 1 < iters);
        if (more) prefetch(kpstart + (it + 1) * KP);

        int s = it & 1;
        const uint2* As = (const uint2*)(dsm1 + s * STAGE1);
        const uint32_t* Bs = dsm1 + s * STAGE1 + AAREA2 * 2;

#pragma unroll
        for (int h = 0; h < TBKv / 16; h++) {
            int kb = h * 8;
            uint32_t aH4[2][4], aL4[2][4];
#pragma unroll
            for (int mi = 0; mi < 2; mi++) {
                int m = m0w + mi * 16 + g;
                uint2 t0 = As[(m    ) * ALD2 + kb + tig];
                uint2 t1 = As[(m + 8) * ALD2 + kb + tig];
                uint2 t2 = As[(m    ) * ALD2 + kb + tig + 4];
                uint2 t3 = As[(m + 8) * ALD2 + kb + tig + 4];
                aH4[mi][0] = t0.x; aH4[mi][1] = t1.x; aH4[mi][2] = t2.x; aH4[mi][3] = t3.x;
                aL4[mi][0] = t0.y; aL4[mi][1] = t1.y; aL4[mi][2] = t2.y; aL4[mi][3] = t3.y;
            }
            uint32_t bh2[4][2];
#pragma unroll
            for (int ni = 0; ni < 4; ni++) {
                int n = n0w + ni * 8 + g;
                if (NT) {
                    bh2[ni][0] = Bs[n * BLD1 + kb + tig];
                    bh2[ni][1] = Bs[n * BLD1 + kb + tig + 4];
                } else {
                    bh2[ni][0] = Bs[(kb + tig) * BLDN1 + n];
                    bh2[ni][1] = Bs[(kb + tig + 4) * BLDN1 + n];
                }
            }
#pragma unroll
            for (int mi = 0; mi < 2; mi++)
#pragma unroll
                for (int ni = 0; ni < 4; ni++) {
                    mma_f16(c[mi][ni], aL4[mi], bh2[ni]);
                    mma_f16(c[mi][ni], aH4[mi], bh2[ni]);
                }
        }

        if (more) store_stage(s ^ 1);
        __syncthreads();
    }

    // ---- epilogue ----
    if (p.CP) {
        int ldcp = ldc >> 1;
#pragma unroll
        for (int mi = 0; mi < 2; mi++) {
#pragma unroll
            for (int ni = 0; ni < 4; ni++) {
                float v[4];
#pragma unroll
                for (int e = 0; e < 4; e++) {
                    int lc = bn + n0w + ni * 8 + tig * 2 + (e & 1);
                    float t = c[mi][ni][e];
                    if (bias) t += bias[lc];
                    t *= scl;
                    if (p.act == 1) t = 0.5f * t * (1.f + erff(t * 0.70710678118654752f));
                    v[e] = t;
                }
                int row0 = bm + m0w + mi * 16 + g;
                int pc = (bn + n0w + ni * 8) / 2 + tig;
                if (row0 < M)     p.CP[(long)row0 * ldcp + pc]       = split2(v[0], v[1]);
                if (row0 + 8 < M) p.CP[(long)(row0 + 8) * ldcp + pc] = split2(v[2], v[3]);
            }
        }
    } else {
#pragma unroll
        for (int mi = 0; mi < 2; mi++) {
#pragma unroll
            for (int ni = 0; ni < 4; ni++) {
#pragma unroll
                for (int e = 0; e < 4; e++) {
                    int row = bm + m0w + mi * 16 + g + ((e >= 2) ? 8 : 0);
                    int gcol = bn + n0w + ni * 8 + tig * 2 + (e & 1);
                    if (row >= M || gcol >= N) continue;
                    int lc = gcol - seg * p.segW;
                    float v = c[mi][ni][e];
                    if (bias && (!atom || sk == 0)) v += bias[lc];
                    v *= scl;
                    long ci = (long)row * ldc + lc;
                    if (atom) {
                        atomicAdd(&C[ci], v);
                    } else {
                        if (p.act == 1) v = 0.5f * v * (1.f + erff(v * 0.70710678118654752f));
                        C[ci] = v;
                    }
                }
            }
        }
    }
}

// ---------------- fused flash attention (fp16 2-term) ----------------
__global__ __launch_bounds__(128) void flash_kernel(
    const float* __restrict__ Qb, const float* __restrict__ Kb,
    const float* __restrict__ Vb, uint2* __restrict__ OPk,
    float* __restrict__ mir, int lenKV, long kvBStride, int causal,
    float* __restrict__ Opart, float2* __restrict__ Msum, int kvChunk)
{
    __shared__ uint32_t Kh[64][36];
    __shared__ uint32_t Vh[64][33];

    int mt = blockIdx.x;
    int by = blockIdx.y;
    int sp = blockIdx.z;
    int b = by / HH, hh = by % HH;

    int kvStart = sp * kvChunk;
    int kvEnd = min(lenKV, kvStart + kvChunk);

    const float* Q = Qb + ((long)b * TT + mt * 64) * DD + hh * DHH;
    const float* K = Kb + (long)b * kvBStride + hh * DHH;
    const float* V = Vb + (long)b * kvBStride + hh * DHH;
    float* Mr = (mir && b == 0)
              ? mir + (size_t)hh * TT * TAA + (size_t)mt * 64 * TAA : nullptr;

    int tid = threadIdx.x;
    int lane = tid & 31, warp = tid >> 5;
    int g = lane >> 2, tig = lane & 3;
    int m0w = warp * 16;

    uint32_t Qah[4][4], Qal[4][4];
#pragma unroll
    for (int kb = 0; kb < 4; kb++) {
        int c0 = 16 * kb + 2 * tig;
        const float* r0 = Q + (long)(m0w + g) * DD;
        const float* r1 = Q + (long)(m0w + g + 8) * DD;
        float2 v;
        v = *(const float2*)(r0 + c0);     splitf16(v, Qah[kb][0], Qal[kb][0]);
        v = *(const float2*)(r1 + c0);     splitf16(v, Qah[kb][1], Qal[kb][1]);
        v = *(const float2*)(r0 + c0 + 8); splitf16(v, Qah[kb][2], Qal[kb][2]);
        v = *(const float2*)(r1 + c0 + 8); splitf16(v, Qah[kb][3], Qal[kb][3]);
    }

    float acc[8][4];
#pragma unroll
    for (int j = 0; j < 8; j++)
#pragma unroll
        for (int e = 0; e < 4; e++) acc[j][e] = 0.f;
    float m0 = -1e30f, m1 = -1e30f, sum0 = 0.f, sum1 = 0.f;

    int chBeg = kvStart >> 6;
    int chEnd = (kvEnd + 63) >> 6;
    if (causal) chEnd = min(chEnd, mt + 1);

    for (int ch = chBeg; ch < chEnd; ch++) {
        int n0 = ch * 64;
#pragma unroll
        for (int i = 0; i < 16; i++) {
            int idx = i * 128 + tid;
            int r = idx >> 5, c = idx & 31;
            float2 v = {0.f, 0.f};
            if (n0 + r < kvEnd) v = *(const float2*)(K + (long)(n0 + r) * DD + 2 * c);
            Kh[r][c] = h2pack(v.x, v.y);
        }
#pragma unroll
        for (int i = 0; i < 16; i++) {
            int idx = i * 128 + tid;
            int d = idx & 63, pr = idx >> 6;
            float2 v = {0.f, 0.f};
            int r0i = n0 + 2 * pr;
            if (r0i < kvEnd)     v.x = V[(long)r0i * DD + d];
            if (r0i + 1 < kvEnd) v.y = V[(long)(r0i + 1) * DD + d];
            Vh[d][pr] = h2pack(v.x, v.y);
        }
        __syncthreads();

        float s[8][4];
#pragma unroll
        for (int j = 0; j < 8; j++)
#pragma unroll
            for (int e = 0; e < 4; e++) s[j][e] = 0.f;
#pragma unroll
        for (int kb = 0; kb < 4; kb++) {
#pragma unroll
            for (int j = 0; j < 8; j++) {
                uint32_t bh[2] = { Kh[8 * j + g][8 * kb + tig], Kh[8 * j + g][8 * kb + tig + 4] };
                mma_f16(s[j], Qal[kb], bh);
                mma_f16(s[j], Qah[kb], bh);
            }
        }

        if (Mr) {
#pragma unroll
            for (int j = 0; j < 8; j++) {
                int col = n0 + 8 * j + 2 * tig;
                if (col < kvEnd) {
                    float2 v0 = { s[j][0], s[j][1] };
                    float2 v1 = { s[j][2], s[j][3] };
                    *(float2*)&Mr[(long)(m0w + g) * TAA + col] = v0;
                    *(float2*)&Mr[(long)(m0w + g + 8) * TAA + col] = v1;
                }
            }
        }

        if (causal && ch == mt) {
            int t0 = mt * 64 + m0w + g;
#pragma unroll
            for (int j = 0; j < 8; j++) {
                int col = n0 + 8 * j + 2 * tig;
                if (col     > t0)     s[j][0] = -1e30f;
                if (col + 1 > t0)     s[j][1] = -1e30f;
                if (col     > t0 + 8) s[j][2] = -1e30f;
                if (col + 1 > t0 + 8) s[j][3] = -1e30f;
            }
        }
        if (n0 + 64 > kvEnd) {
#pragma unroll
            for (int j = 0; j < 8; j++) {
                int col = n0 + 8 * j + 2 * tig;
                if (col     >= kvEnd) { s[j][0] = -1e30f; s[j][2] = -1e30f; }
                if (col + 1 >= kvEnd) { s[j][1] = -1e30f; s[j][3] = -1e30f; }
            }
        }

        float mx0 = -1e30f, mx1 = -1e30f;
#pragma unroll
        for (int j = 0; j < 8; j++) {
            mx0 = fmaxf(mx0, fmaxf(s[j][0], s[j][1]));
            mx1 = fmaxf(mx1, fmaxf(s[j][2], s[j][3]));
        }
        mx0 = fmaxf(mx0, __shfl_xor_sync(0xffffffffu, mx0, 1));
        mx0 = fmaxf(mx0, __shfl_xor_sync(0xffffffffu, mx0, 2));
        mx1 = fmaxf(mx1, __shfl_xor_sync(0xffffffffu, mx1, 1));
        mx1 = fmaxf(mx1, __shfl_xor_sync(0xffffffffu, mx1, 2));
        float mn0 = fmaxf(m0, mx0), mn1 = fmaxf(m1, mx1);
        float a0 = __expf(m0 - mn0), a1 = __expf(m1 - mn1);
        float ps0 = 0.f, ps1 = 0.f;
#pragma unroll
        for (int j = 0; j < 8; j++) {
            s[j][0] = __expf(s[j][0] - mn0);
            s[j][1] = __expf(s[j][1] - mn0);
            s[j][2] = __expf(s[j][2] - mn1);
            s[j][3] = __expf(s[j][3] - mn1);
            ps0 += s[j][0] + s[j][1];
            ps1 += s[j][2] + s[j][3];
        }
        ps0 += __shfl_xor_sync(0xffffffffu, ps0, 1);
        ps0 += __shfl_xor_sync(0xffffffffu, ps0, 2);
        ps1 += __shfl_xor_sync(0xffffffffu, ps1, 1);
        ps1 += __shfl_xor_sync(0xffffffffu, ps1, 2);
        sum0 = sum0 * a0 + ps0;
        sum1 = sum1 * a1 + ps1;
        m0 = mn0; m1 = mn1;
#pragma unroll
        for (int j = 0; j < 8; j++) {
            acc[j][0] *= a0; acc[j][1] *= a0;
            acc[j][2] *= a1; acc[j][3] *= a1;
        }

#pragma unroll
        for (int kb = 0; kb < 4; kb++) {
            int j0 = 2 * kb, j1 = 2 * kb + 1;
            uint32_t Ah[4], Al[4];
            Ah[0] = h2pack(s[j0][0], s[j0][1]);  Al[0] = lo_pack(s[j0][0], s[j0][1]);
            Ah[1] = h2pack(s[j0][2], s[j0][3]);  Al[1] = lo_pack(s[j0][2], s[j0][3]);
            Ah[2] = h2pack(s[j1][0], s[j1][1]);  Al[2] = lo_pack(s[j1][0], s[j1][1]);
            Ah[3] = h2pack(s[j1][2], s[j1][3]);  Al[3] = lo_pack(s[j1][2], s[j1][3]);
#pragma unroll
            for (int jd = 0; jd < 8; jd++) {
                uint32_t bh[2] = { Vh[8 * jd + g][8 * kb + tig], Vh[8 * jd + g][8 * kb + tig + 4] };
                mma_f16(acc[jd], Al, bh);
                mma_f16(acc[jd], Ah, bh);
            }
        }
        __syncthreads();
    }

    if (Opart) {
        float* OP = Opart + (((long)sp * BT) + (long)b * TT + mt * 64) * DD + hh * DHH;
#pragma unroll
        for (int jd = 0; jd < 8; jd++) {
            int col = 8 * jd + 2 * tig;
            float2 v0 = { acc[jd][0], acc[jd][1] };
            float2 v1 = { acc[jd][2], acc[jd][3] };
            *(float2*)&OP[(long)(m0w + g) * DD + col] = v0;
            *(float2*)&OP[(long)(m0w + g + 8) * DD + col] = v1;
        }
        if (tig == 0) {
            long base = (((long)sp * BB + b) * HH + hh) * TT + mt * 64;
            Msum[base + m0w + g]     = make_float2(m0, sum0);
            Msum[base + m0w + g + 8] = make_float2(m1, sum1);
        }
    } else {
        uint2* O2 = OPk + ((long)b * TT + mt * 64) * DP + hh * 32;
        float i0 = 1.f / sum0, i1 = 1.f / sum1;
#pragma unroll
        for (int jd = 0; jd < 8; jd++) {
            int pc = 4 * jd + tig;
            O2[(long)(m0w + g) * DP + pc]     = split2(acc[jd][0] * i0, acc[jd][1] * i0);
            O2[(long)(m0w + g + 8) * DP + pc] = split2(acc[jd][2] * i1, acc[jd][3] * i1);
        }
    }
}

__global__ __launch_bounds__(256) void flash_merge_kernel(
    const float* __restrict__ Opart, const float2* __restrict__ Msum,
    uint2* __restrict__ OPk)
{
    __shared__ float wgt[HH][NSPLIT];
    int row = blockIdx.x;
    int b = row / TT, t = row % TT;
    int tid = threadIdx.x;
    if (tid < HH) {
        int h = tid;
        float ms[NSPLIT], ss[NSPLIT];
        float m = -1e30f;
#pragma unroll
        for (int s = 0; s < NSPLIT; s++) {
            float2 v = Msum[(((long)s * BB + b) * HH + h) * TT + t];
            ms[s] = v.x; ss[s] = v.y;
            m = fmaxf(m, v.x);
        }
        float den = 0.f;
#pragma unroll
        for (int s = 0; s < NSPLIT; s++) den += ss[s] * __expf(ms[s] - m);
        float iden = 1.f / den;
#pragma unroll
        for (int s = 0; s < NSPLIT; s++) wgt[h][s] = __expf(ms[s] - m) * iden;
    }
    __syncthreads();
#pragma unroll
    for (int it = 0; it < 2; it++) {
        int pd = tid + it * 256;
        if (pd >= DP) break;
        int h = pd >> 5;
        float a0 = 0.f, a1 = 0.f;
#pragma unroll
        for (int s = 0; s < NSPLIT; s++) {
            const float* op = &Opart[(((long)s * BT) + row) * DD + 2 * pd];
            a0 += op[0] * wgt[h][s];
            a1 += op[1] * wgt[h][s];
        }
        OPk[(long)row * DP + pd] = split2(a0, a1);
    }
}

// ---------------- elementwise / row kernels ----------------
__global__ __launch_bounds__(256) void embed_kernel(
    const int* __restrict__ tokens, const float* __restrict__ tok_emb,
    const float* __restrict__ pos_emb, float* __restrict__ x)
{
    int row = blockIdx.x;
    int t = row % TT;
    int tok = tokens[row];
    const float* te = tok_emb + (long)tok * DD;
    const float* pe = pos_emb + (long)t * DD;
    float* xr = x + (long)row * DD;
#pragma unroll
    for (int it = 0; it < 3; it++) {
        int j = threadIdx.x + it * 256;
        xr[j] = te[j] + pe[j];
    }
}

__global__ __launch_bounds__(256) void ln_pack_kernel(
    const float* __restrict__ x, uint2* __restrict__ y,
    const float* __restrict__ g, const float* __restrict__ b)
{
    __shared__ float red[256];
    int row = blockIdx.x;
    const float* xr = x + (long)row * DD;
    uint2* yr = y + (long)row * DP;
    int tid = threadIdx.x;
    float v0 = xr[tid], v1 = xr[tid + 256], v2 = xr[tid + 512];
    float s = v0 + v1 + v2;
    red[tid] = s; __syncthreads();
    for (int st = 128; st > 0; st >>= 1) { if (tid < st) red[tid] += red[tid + st]; __syncthreads(); }
    float mean = red[0] * (1.f / DD);
    __syncthreads();
    float d0 = v0 - mean, d1 = v1 - mean, d2 = v2 - mean;
    red[tid] = d0 * d0 + d1 * d1 + d2 * d2; __syncthreads();
    for (int st = 128; st > 0; st >>= 1) { if (tid < st) red[tid] += red[tid + st]; __syncthreads(); }
    float inv = rsqrtf(red[0] * (1.f / DD) + 1e-5f);
    {
        int c0 = 2 * tid;
        float a = (xr[c0]     - mean) * inv * g[c0]     + b[c0];
        float c = (xr[c0 + 1] - mean) * inv * g[c0 + 1] + b[c0 + 1];
        yr[tid] = split2(a, c);
    }
    if (tid < 128) {
        int p1 = tid + 256;
        int c0 = 2 * p1;
        float a = (xr[c0]     - mean) * inv * g[c0]     + b[c0];
        float c = (xr[c0 + 1] - mean) * inv * g[c0 + 1] + b[c0 + 1];
        yr[p1] = split2(a, c);
    }
}

// ---------------- host-side launch helpers ----------------
static GemmP base_p() {
    GemmP p;
    p.A = nullptr; p.B0 = p.B1 = p.B2 = nullptr;
    p.C0 = p.C1 = p.C2 = nullptr; p.CP = nullptr;
    p.bias0 = p.bias1 = p.bias2 = nullptr;
    p.M = p.N = p.K = 0; p.ldap = p.ldbp = p.ldc = 0;
    p.Hd = 1; p.segW = 1 << 30; p.act = 0; p.splitK = 1; p.kc = 0;
    p.sA0 = p.sA1 = p.sB0 = p.sB1 = p.sC0 = p.sC1 = p.sBias = 0;
    p.s0 = p.s1 = p.s2 = 1.f;
    return p;
}

static inline int smem_bytes(int BIG) {
    int ALD2 = BIG ? 36 : 20;
    int AAREA2 = 128 * ALD2;
    int BAREA1 = BIG ? 4608 : 1280;
    return 2 * (AAREA2 * 2 + BAREA1) * 4;
}

template <int NT, int BIG>
static inline void launch_g(GemmP p, int batch, int splitK = 1) {
    p.splitK = splitK;
    constexpr int TBKv = BIG ? 64 : 32;
    int kc = (p.K + splitK - 1) / splitK;
    p.kc = ((kc + TBKv - 1) / TBKv) * TBKv;
    constexpr int BN = BIG ? 128 : 64;
    constexpr int NTHR = BIG ? 512 : 256;
    dim3 grd((p.N + BN - 1) / BN, (p.M + 127) / 128, batch * splitK);
    gemm_f16_kernel<NT, BIG><<<grd, NTHR, smem_bytes(BIG)>>>(p);
}

static inline int pkblocks(long n) {
    long b = (n + 255) / 256;
    return (int)(b > 8192 ? 8192 : b);
}

extern "C" void kernel_launch(void* const* d_in, const int* in_sizes, int n_in,
                              void* d_out, int out_size)
{
    (void)in_sizes; (void)n_in; (void)out_size;

    cudaFuncSetAttribute(gemm_f16_kernel<0, 0>, cudaFuncAttributeMaxDynamicSharedMemorySize, smem_bytes(0));
    cudaFuncSetAttribute(gemm_f16_kernel<1, 0>, cudaFuncAttributeMaxDynamicSharedMemorySize, smem_bytes(0));
    cudaFuncSetAttribute(gemm_f16_kernel<0, 1>, cudaFuncAttributeMaxDynamicSharedMemorySize, smem_bytes(1));
    cudaFuncSetAttribute(gemm_f16_kernel<1, 1>, cudaFuncAttributeMaxDynamicSharedMemorySize, smem_bytes(1));

    const int*   tokens  = (const int*)  d_in[0];
    const float* xa      = (const float*)d_in[1];
    const float* tok_emb = (const float*)d_in[2];
    const float* pos_emb = (const float*)d_in[3];
    const float* Wq      = (const float*)d_in[4];
    const float* bq      = (const float*)d_in[5];
    const float* Wk      = (const float*)d_in[6];
    const float* Wv      = (const float*)d_in[7];
    const float* bv      = (const float*)d_in[8];
    const float* Wo      = (const float*)d_in[9];
    const float* bo      = (const float*)d_in[10];
    const float* ln1_g   = (const float*)d_in[11];
    const float* ln1_b   = (const float*)d_in[12];
    const float* Wcq     = (const float*)d_in[13];
    const float* bcq     = (const float*)d_in[14];
    const float* Wck     = (const float*)d_in[15];
    const float* Wcv     = (const float*)d_in[16];
    const float* bcv     = (const float*)d_in[17];
    const float* Wco     = (const float*)d_in[18];
    const float* bco     = (const float*)d_in[19];
    const float* ln2_g   = (const float*)d_in[20];
    const float* ln2_b   = (const float*)d_in[21];
    const float* W1      = (const float*)d_in[22];
    const float* b1      = (const float*)d_in[23];
    const float* W2      = (const float*)d_in[24];
    const float* b2      = (const float*)d_in[25];
    const float* ln3_g   = (const float*)d_in[26];
    const float* ln3_b   = (const float*)d_in[27];
    const float* lnf_g   = (const float*)d_in[28];
    const float* lnf_b   = (const float*)d_in[29];

    float* out = (float*)d_out;
    float* out_logits = out;
    float* out_chw    = out_logits + (size_t)BB * TT * VV;
    float* out_kv     = out_chw + (size_t)(LL / 2) * HH * TT * TAA;

    float *x, *q, *ckall, *cvall, *opart;
    float2* msum;
    uint2 *hP, *oP, *hidP, *xaP;
    uint32_t *tokP, *WqP, *WkP, *WvP, *WoP, *WcqP, *WckP, *WcvP, *WcoP, *W1P, *W2P;
    cudaGetSymbolAddress((void**)&x,     g_x);
    cudaGetSymbolAddress((void**)&q,     g_q);
    cudaGetSymbolAddress((void**)&ckall, g_ckall);
    cudaGetSymbolAddress((void**)&cvall, g_cvall);
    cudaGetSymbolAddress((void**)&opart, g_opart);
    cudaGetSymbolAddress((void**)&msum,  g_msum);
    cudaGetSymbolAddress((void**)&hP,    g_hP);
    cudaGetSymbolAddress((void**)&oP,    g_oP);
    cudaGetSymbolAddress((void**)&hidP,  g_hidP);
    cudaGetSymbolAddress((void**)&xaP,   g_xaP);
    cudaGetSymbolAddress((void**)&tokP,  g_tokP);
    cudaGetSymbolAddress((void**)&WqP,   g_WqP);
    cudaGetSymbolAddress((void**)&WkP,   g_WkP);
    cudaGetSymbolAddress((void**)&WvP,   g_WvP);
    cudaGetSymbolAddress((void**)&WoP,   g_WoP);
    cudaGetSymbolAddress((void**)&WcqP,  g_WcqP);
    cudaGetSymbolAddress((void**)&WckP,  g_WckP);
    cudaGetSymbolAddress((void**)&WcvP,  g_WcvP);
    cudaGetSymbolAddress((void**)&WcoP,  g_WcoP);
    cudaGetSymbolAddress((void**)&W1P,   g_W1P);
    cudaGetSymbolAddress((void**)&W2P,   g_W2P);

    // ---- prepack ----
    {
        long n;
        n = (long)BB * TAA * DP;
        pack_contig_kernel<<<pkblocks(n), 256>>>(xa, xaP, n);
        n = (long)VV * DP;
        pack_contig_hi_kernel<<<pkblocks(n), 256>>>(tok_emb, tokP, n);
        long nw = (long)LL * DP * DD;
        pack_strideK_hi_kernel<<<pkblocks(nw), 256>>>(Wq,  WqP,  DP, DD, nw);
        pack_strideK_hi_kernel<<<pkblocks(nw), 256>>>(Wk,  WkP,  DP, DD, nw);
        pack_strideK_hi_kernel<<<pkblocks(nw), 256>>>(Wv,  WvP,  DP, DD, nw);
        pack_strideK_hi_kernel<<<pkblocks(nw), 256>>>(Wo,  WoP,  DP, DD, nw);
        pack_strideK_hi_kernel<<<pkblocks(nw), 256>>>(Wcq, WcqP, DP, DD, nw);
        pack_strideK_hi_kernel<<<pkblocks(nw), 256>>>(Wck, WckP, DP, DD, nw);
        pack_strideK_hi_kernel<<<pkblocks(nw), 256>>>(Wcv, WcvP, DP, DD, nw);
        pack_strideK_hi_kernel<<<pkblocks(nw), 256>>>(Wco, WcoP, DP, DD, nw);
        long n1 = (long)LL * DP * 4 * DD;
        pack_strideK_hi_kernel<<<pkblocks(n1), 256>>>(W1, W1P, DP, 4 * DD, n1);
        long n2 = (long)LL * 2 * DD * DD;
        pack_strideK_hi_kernel<<<pkblocks(n2), 256>>>(W2, W2P, 2 * DD, DD, n2);
    }

    embed_kernel<<<BT, 256>>>(tokens, tok_emb, pos_emb, x);

    const long DTD = (long)TT * DD;
    const long TAD = (long)TAA * DD;
    const size_t XBYTES = (size_t)BT * DD * sizeof(float);
    const int KVCH = ((TAA + NSPLIT * 64 - 1) / (NSPLIT * 64)) * 64;   // 384

    // cross K/V for ALL layers, batched over z=12 (BIG)
    {
        GemmP p = base_p();
        p.A = xaP; p.ldap = DP;
        p.B0 = WckP; p.ldbp = DD; p.sB1 = (long)DP * DD;
        p.C0 = ckall; p.ldc = DD; p.sC1 = (long)BTAD;
        p.M = BB * TAA; p.N = DD; p.K = DD; p.Hd = LL;
        launch_g<0, 1>(p, LL);
        p.B0 = WcvP; p.C0 = cvall;
        p.bias0 = bcv; p.sBias = DD;
        launch_g<0, 1>(p, LL);
    }

    for (int l = 0; l < LL; l++) {
        float* kout = out_kv + (size_t)(2 * l) * BT * DD;
        float* vout = out_kv + (size_t)(2 * l + 1) * BT * DD;
        float* ck_l = ckall + (size_t)l * BTAD;
        float* cv_l = cvall + (size_t)l * BTAD;
        const long WOFF = (long)l * DP * DD;

        // ---- self attention ----
        ln_pack_kernel<<<BT, 256>>>(x, hP, ln1_g + l * DD, ln1_b + l * DD);
        {   // fused QKV (BIG)
            GemmP p = base_p();
            p.A = hP; p.ldap = DP;
            p.B0 = WqP + WOFF; p.B1 = WkP + WOFF; p.B2 = WvP + WOFF; p.ldbp = DD;
            p.C0 = q; p.C1 = kout; p.C2 = vout; p.ldc = DD;
            p.bias0 = bq + l * DD; p.bias1 = nullptr; p.bias2 = bv + l * DD;
            p.s0 = SCALE_Q; p.s1 = 1.f; p.s2 = 1.f;
            p.segW = DD;
            p.M = BT; p.N = 3 * DD; p.K = DD;
            launch_g<0, 1>(p, 1);
        }
        flash_kernel<<<dim3(TT / 64, BB * HH, 1), 128>>>(
            q, kout, vout, oP, nullptr, TT, DTD, 1, nullptr, nullptr, TT);
        {   // x += o @ Wo + bo  (small, split-K atomics)
            GemmP p = base_p();
            p.A = oP; p.ldap = DP;
            p.B0 = WoP + WOFF; p.ldbp = DD;
            p.C0 = x; p.ldc = DD;
            p.bias0 = bo + l * DD;
            p.M = BT; p.N = DD; p.K = DD;
            launch_g<0, 0>(p, 1, 4);
        }

        // ---- cross attention ----
        ln_pack_kernel<<<BT, 256>>>(x, hP, ln2_g + l * DD, ln2_b + l * DD);
        cudaMemsetAsync(q, 0, XBYTES);
        {   // q2 (small, split-K atomics)
            GemmP p = base_p();
            p.A = hP; p.ldap = DP;
            p.B0 = WcqP + WOFF; p.ldbp = DD;
            p.C0 = q; p.ldc = DD;
            p.bias0 = bcq + l * DD; p.s0 = SCALE_Q;
            p.M = BT; p.N = DD; p.K = DD;
            launch_g<0, 0>(p, 1, 4);
        }
        {
            float* mir = (l >= LL / 2)
                       ? out_chw + (size_t)(l - LL / 2) * HH * TT * TAA : nullptr;
            flash_kernel<<<dim3(TT / 64, BB * HH, NSPLIT), 128>>>(
                q, ck_l, cv_l, nullptr, mir, TAA, TAD, 0, opart, msum, KVCH);
            flash_merge_kernel<<<BT, 256>>>(opart, msum, oP);
        }
        {   // x += o @ Wco + bco  (small, split-K atomics)
            GemmP p = base_p();
            p.A = oP; p.ldap = DP;
            p.B0 = WcoP + WOFF; p.ldbp = DD;
            p.C0 = x; p.ldc = DD;
            p.bias0 = bco + l * DD;
            p.M = BT; p.N = DD; p.K = DD;
            launch_g<0, 0>(p, 1, 4);
        }

        // ---- MLP ----
        ln_pack_kernel<<<BT, 256>>>(x, hP, ln3_g + l * DD, ln3_b + l * DD);
        {   // hidP = pack(gelu(h @ W1 + b1))  (BIG, packed epilogue)
            GemmP p = base_p();
            p.A = hP; p.ldap = DP;
            p.B0 = W1P + (long)l * DP * 4 * DD; p.ldbp = 4 * DD;
            p.CP = hidP; p.ldc = 4 * DD;
            p.bias0 = b1 + (size_t)l * 4 * DD; p.act = 1;
            p.M = BT; p.N = 4 * DD; p.K = DD;
            launch_g<0, 1>(p, 1);
        }
        {   // x += hid @ W2 + b2  (BIG, split-K 8)
            GemmP p = base_p();
            p.A = hidP; p.ldap = 2 * DD;
            p.B0 = W2P + (long)l * 2 * DD * DD; p.ldbp = DD;
            p.C0 = x; p.ldc = DD;
            p.bias0 = b2 + l * DD;
            p.M = BT; p.N = DD; p.K = 4 * DD;
            launch_g<0, 1>(p, 1, 8);
        }
    }

    // final LN + tied-embedding logits (BIG NT)
    ln_pack_kernel<<<BT, 256>>>(x, hP, lnf_g, lnf_b);
    {
        GemmP p = base_p();
        p.A = hP; p.ldap = DP;
        p.B0 = tokP; p.ldbp = DP;
        p.C0 = out_logits; p.ldc = VV;
        p.M = BT; p.N = VV; p.K = DD;
        launch_g<1, 1>(p, 1);
    }
}

// round 15
// speedup vs baseline: 1.5209x; 1.0750x over previous
#include <cuda_runtime.h>
#include <cuda_bf16.h>
#include <cuda_fp16.h>
#include <math.h>
#include <stdint.h>

// ---------------- problem constants ----------------
#define BB   4
#define TT   256
#define TAA  1500
#define DD   768
#define HH   12
#define LL   12
#define VV   51865
#define DHH  64
#define BT   (BB*TT)          // 1024
#define DP   (DD/2)           // 384 pairs
#define SCALE_Q 0.125f
#define BTAD ((size_t)BB*TAA*DD)
#define NSPLIT 4

// ---------------- scratch ----------------
__device__ float g_x  [BT*DD];
__device__ float g_q  [BT*DD];
__device__ float g_ckall[(size_t)LL*BTAD];
__device__ float g_cvall[(size_t)LL*BTAD];
__device__ float g_opart[(size_t)NSPLIT*BT*DD];
__device__ float2 g_msum[(size_t)NSPLIT*BB*HH*TT];

// A-side packed fp16 hi/lo (uint2: x=hi pair, y=lo pair)
__device__ uint2 g_hP  [(size_t)BT*DP];
__device__ uint2 g_oP  [(size_t)BT*DP];
__device__ uint2 g_hidP[(size_t)BT*2*DD];
__device__ uint2 g_xaP [(size_t)BB*TAA*DP];
// B-side packed fp16 hi-only (uint32 pair)
__device__ uint32_t g_tokP[(size_t)VV*DP];
__device__ uint32_t g_WqP [(size_t)LL*DP*DD];
__device__ uint32_t g_WkP [(size_t)LL*DP*DD];
__device__ uint32_t g_WvP [(size_t)LL*DP*DD];
__device__ uint32_t g_WoP [(size_t)LL*DP*DD];
__device__ uint32_t g_WcqP[(size_t)LL*DP*DD];
__device__ uint32_t g_WckP[(size_t)LL*DP*DD];
__device__ uint32_t g_WcvP[(size_t)LL*DP*DD];
__device__ uint32_t g_WcoP[(size_t)LL*DP*DD];
__device__ uint32_t g_W1P [(size_t)LL*DP*4*DD];
__device__ uint32_t g_W2P [(size_t)LL*2*DD*DD];

// ---------------- helpers ----------------
__device__ __forceinline__ uint32_t h2pack(float a, float b) {
    __half2 t = __floats2half2_rn(a, b);
    return *(uint32_t*)&t;
}

__device__ __forceinline__ void splitf16(float2 v, uint32_t& hi, uint32_t& lo) {
    __half hx = __float2half_rn(v.x);
    __half hy = __float2half_rn(v.y);
    __half2 h; h.x = hx; h.y = hy;
    hi = *(uint32_t*)&h;
    lo = h2pack(v.x - __half2float(hx), v.y - __half2float(hy));
}

__device__ __forceinline__ uint2 split2(float a, float b) {
    uint32_t hi, lo;
    splitf16(make_float2(a, b), hi, lo);
    return make_uint2(hi, lo);
}

__device__ __forceinline__ uint32_t lo_pack(float a, float b) {
    float ra = a - __half2float(__float2half_rn(a));
    float rb = b - __half2float(__float2half_rn(b));
    return h2pack(ra, rb);
}

__device__ __forceinline__ void mma_f16(float* c, const uint32_t* a, const uint32_t* b) {
    asm volatile(
        "mma.sync.aligned.m16n8k16.row.col.f32.f16.f16.f32 "
        "{%0,%1,%2,%3}, {%4,%5,%6,%7}, {%8,%9}, {%0,%1,%2,%3};"
        : "+f"(c[0]), "+f"(c[1]), "+f"(c[2]), "+f"(c[3])
        : "r"(a[0]), "r"(a[1]), "r"(a[2]), "r"(a[3]), "r"(b[0]), "r"(b[1]));
}

__device__ __forceinline__ void cp16(uint32_t saddr, const void* gptr, bool pred) {
    int sz = pred ? 16 : 0;
    asm volatile("cp.async.cg.shared.global [%0], [%1], 16, %2;"
                 :: "r"(saddr), "l"(gptr), "r"(sz));
}
#define CP_COMMIT() asm volatile("cp.async.commit_group;")
#define CP_WAIT(n)  asm volatile("cp.async.wait_group %0;" :: "n"(n))

// ---------------- prepack kernels ----------------
__global__ __launch_bounds__(256) void pack_contig_kernel(
    const float* __restrict__ in, uint2* __restrict__ out, long n)
{
    long i = blockIdx.x * 256L + threadIdx.x;
    long stride = (long)gridDim.x * 256;
    for (; i < n; i += stride) {
        float2 v = ((const float2*)in)[i];
        uint32_t hi, lo; splitf16(v, hi, lo);
        out[i] = make_uint2(hi, lo);
    }
}

__global__ __launch_bounds__(256) void pack_contig_hi_kernel(
    const float* __restrict__ in, uint32_t* __restrict__ out, long n)
{
    long i = blockIdx.x * 256L + threadIdx.x;
    long stride = (long)gridDim.x * 256;
    for (; i < n; i += stride) {
        float2 v = ((const float2*)in)[i];
        out[i] = h2pack(v.x, v.y);
    }
}

__global__ __launch_bounds__(256) void pack_strideK_hi_kernel(
    const float* __restrict__ in, uint32_t* __restrict__ out,
    int Khalf, int N, long total)
{
    long i = blockIdx.x * 256L + threadIdx.x;
    long stride = (long)gridDim.x * 256;
    for (; i < total; i += stride) {
        int n = (int)(i % N);
        long r = i / N;
        int kp = (int)(r % Khalf);
        long b = r / Khalf;
        const float* base = in + b * (long)Khalf * 2 * N;
        out[i] = h2pack(base[(long)(2 * kp) * N + n], base[(long)(2 * kp + 1) * N + n]);
    }
}

// batched prepack for the 8 [LL][768][768] weight tensors, grid.y selects tensor
struct PackW { const float* src[8]; uint32_t* dst[8]; };
__global__ __launch_bounds__(256) void pack_w8_kernel(PackW p, long total)
{
    const float* in = p.src[blockIdx.y];
    uint32_t* out = p.dst[blockIdx.y];
    long i = blockIdx.x * 256L + threadIdx.x;
    long stride = (long)gridDim.x * 256;
    for (; i < total; i += stride) {
        int n = (int)(i % DD);
        long r = i / DD;
        int kp = (int)(r % DP);
        long b = r / DP;
        const float* base = in + b * (long)DD * DD;
        out[i] = h2pack(base[(long)(2 * kp) * DD + n], base[(long)(2 * kp + 1) * DD + n]);
    }
}

// ---------------- packed fp16 GEMM (2-term) + split-K, cp.async double-buffered ----------------
struct GemmP {
    const uint2 *A;
    const uint32_t *B0, *B1, *B2;
    float *C0, *C1, *C2;
    uint2 *CP;
    const float *bias0, *bias1, *bias2;
    int M, N, K, ldap, ldbp, ldc, Hd, segW, act, splitK, kc;
    long sA0, sA1, sB0, sB1, sC0, sC1, sBias;
    float s0, s1, s2;
};

template <int NT, int BIG>
__global__ __launch_bounds__(BIG ? 512 : 256, BIG ? 1 : 2) void gemm_f16_kernel(GemmP p)
{
    constexpr int BN    = BIG ? 128 : 64;
    constexpr int NTHR  = BIG ? 512 : 256;
    constexpr int TBKv  = BIG ? 64 : 32;
    constexpr int KP    = TBKv / 2;
    constexpr int ALD2  = BIG ? 36 : 20;      // uint2 stride, A
    constexpr int BLD1  = BIG ? 36 : 20;      // u32 stride, NT-B [n][kp]
    constexpr int BLDN1 = BIG ? 132 : 68;     // u32 stride, NN-B [kp][n]
    constexpr int ACH   = 128 * (KP / 2) / NTHR;          // 16B chunks: 4
    constexpr int BCHT  = BN * (KP / 4) / NTHR;           // NT: BIG 2 / small 1
    constexpr int BCHN  = (KP * (BN / 4)) / NTHR;         // NN: BIG 2 / small 1
    constexpr int AAREA2 = 128 * ALD2;
    constexpr int BAREA1 = BIG ? 4608 : 1280;
    constexpr int STAGE1 = AAREA2 * 2 + BAREA1;

    extern __shared__ uint32_t dsm1[];

    int z = blockIdx.z;
    int sk = z % p.splitK;
    int zz = z / p.splitK;
    int zb = zz / p.Hd, zh = zz % p.Hd;
    int bm = blockIdx.y * 128, bn = blockIdx.x * BN;
    int seg = bn / p.segW;
    int bnl = bn - seg * p.segW;

    const uint2* A = p.A + zb * p.sA0 + zh * p.sA1;
    const uint32_t* B = (seg == 0 ? p.B0 : seg == 1 ? p.B1 : p.B2) + zb * p.sB0 + zh * p.sB1;
    float* C = (seg == 0 ? p.C0 : seg == 1 ? p.C1 : p.C2) + zb * p.sC0 + zh * p.sC1;
    const float* bias = (seg == 0 ? p.bias0 : seg == 1 ? p.bias1 : p.bias2);
    if (bias) bias += zh * p.sBias;
    float scl = seg == 0 ? p.s0 : seg == 1 ? p.s1 : p.s2;
    bool atom = p.splitK > 1;

    int M = p.M, N = p.N;
    int ldap = p.ldap, ldbp = p.ldbp, ldc = p.ldc;
    int kpstart = (sk * p.kc) >> 1;
    int kpend = min(p.K, sk * p.kc + p.kc) >> 1;

    int tid  = threadIdx.x;
    int lane = tid & 31;
    int warp = tid >> 5;
    int g    = lane >> 2;
    int tig  = lane & 3;
    int m0w  = (warp & 3) * 32;
    int n0w  = (warp >> 2) * 32;

    uint32_t smemBase = (uint32_t)__cvta_generic_to_shared(dsm1);

    float c[2][4][4];
#pragma unroll
    for (int mi = 0; mi < 2; mi++)
#pragma unroll
        for (int ni = 0; ni < 4; ni++)
#pragma unroll
            for (int e = 0; e < 4; e++) c[mi][ni][e] = 0.f;

    int iters = (kpend - kpstart + KP - 1) / KP;

    auto issue_stage = [&](int it, int s) {
        int kp0 = kpstart + it * KP;
        uint32_t aBase = smemBase + (uint32_t)s * STAGE1 * 4u;
        uint32_t bBase = aBase + (uint32_t)AAREA2 * 8u;
        // A: 16B = 2 consecutive kp pairs
#pragma unroll
        for (int i = 0; i < ACH; i++) {
            int cix = i * NTHR + tid;
            int r, k2;
            if (BIG) { r = cix >> 4; k2 = cix & 15; }
            else     { r = cix >> 3; k2 = cix & 7; }
            int kp = 2 * k2;
            int gr = bm + r, kpg = kp0 + kp;
            bool ok = (gr < M) && (kpg < kpend);
            cp16(aBase + (uint32_t)(r * ALD2 + kp) * 8u,
                 A + (long)gr * ldap + kpg, ok);
        }
        if (NT) {
#pragma unroll
            for (int i = 0; i < BCHT; i++) {
                int cix = i * NTHR + tid;
                int n, k4;
                if (BIG) { n = cix >> 3; k4 = cix & 7; }
                else     { n = cix >> 2; k4 = cix & 3; }
                int kp = 4 * k4;
                int kpg = kp0 + kp;
                bool ok = (bn + n < N) && (kpg < kpend);
                cp16(bBase + (uint32_t)(n * BLD1 + kp) * 4u,
                     B + (long)(bnl + n) * ldbp + kpg, ok);
            }
        } else {
#pragma unroll
            for (int i = 0; i < BCHN; i++) {
                int cix = i * NTHR + tid;
                int kp, n4;
                if (BIG) { kp = cix >> 5; n4 = cix & 31; }
                else     { kp = cix >> 4; n4 = cix & 15; }
                int n = 4 * n4;
                int kpg = kp0 + kp;
                bool ok = (bn + n < N) && (kpg < kpend);
                cp16(bBase + (uint32_t)(kp * BLDN1 + n) * 4u,
                     B + (long)kpg * ldbp + bnl + n, ok);
            }
        }
        CP_COMMIT();
    };

    if (iters > 0) issue_stage(0, 0);

    for (int it = 0; it < iters; it++) {
        bool more = (it + 1 < iters);
        if (more) {
            issue_stage(it + 1, (it + 1) & 1);
            CP_WAIT(1);
        } else {
            CP_WAIT(0);
        }
        __syncthreads();

        int s = it & 1;
        const uint2* As = (const uint2*)(dsm1 + s * STAGE1);
        const uint32_t* Bs = dsm1 + s * STAGE1 + AAREA2 * 2;

#pragma unroll
        for (int h = 0; h < TBKv / 16; h++) {
            int kb = h * 8;
            uint32_t aH4[2][4], aL4[2][4];
#pragma unroll
            for (int mi = 0; mi < 2; mi++) {
                int m = m0w + mi * 16 + g;
                uint2 t0 = As[(m    ) * ALD2 + kb + tig];
                uint2 t1 = As[(m + 8) * ALD2 + kb + tig];
                uint2 t2 = As[(m    ) * ALD2 + kb + tig + 4];
                uint2 t3 = As[(m + 8) * ALD2 + kb + tig + 4];
                aH4[mi][0] = t0.x; aH4[mi][1] = t1.x; aH4[mi][2] = t2.x; aH4[mi][3] = t3.x;
                aL4[mi][0] = t0.y; aL4[mi][1] = t1.y; aL4[mi][2] = t2.y; aL4[mi][3] = t3.y;
            }
            uint32_t bh2[4][2];
#pragma unroll
            for (int ni = 0; ni < 4; ni++) {
                int n = n0w + ni * 8 + g;
                if (NT) {
                    bh2[ni][0] = Bs[n * BLD1 + kb + tig];
                    bh2[ni][1] = Bs[n * BLD1 + kb + tig + 4];
                } else {
                    bh2[ni][0] = Bs[(kb + tig) * BLDN1 + n];
                    bh2[ni][1] = Bs[(kb + tig + 4) * BLDN1 + n];
                }
            }
#pragma unroll
            for (int mi = 0; mi < 2; mi++)
#pragma unroll
                for (int ni = 0; ni < 4; ni++) {
                    mma_f16(c[mi][ni], aL4[mi], bh2[ni]);
                    mma_f16(c[mi][ni], aH4[mi], bh2[ni]);
                }
        }
        __syncthreads();
    }

    // ---- epilogue ----
    if (p.CP) {
        int ldcp = ldc >> 1;
#pragma unroll
        for (int mi = 0; mi < 2; mi++) {
#pragma unroll
            for (int ni = 0; ni < 4; ni++) {
                float v[4];
#pragma unroll
                for (int e = 0; e < 4; e++) {
                    int lc = bn + n0w + ni * 8 + tig * 2 + (e & 1);
                    float t = c[mi][ni][e];
                    if (bias) t += bias[lc];
                    t *= scl;
                    if (p.act == 1) t = 0.5f * t * (1.f + erff(t * 0.70710678118654752f));
                    v[e] = t;
                }
                int row0 = bm + m0w + mi * 16 + g;
                int pc = (bn + n0w + ni * 8) / 2 + tig;
                if (row0 < M)     p.CP[(long)row0 * ldcp + pc]       = split2(v[0], v[1]);
                if (row0 + 8 < M) p.CP[(long)(row0 + 8) * ldcp + pc] = split2(v[2], v[3]);
            }
        }
    } else {
#pragma unroll
        for (int mi = 0; mi < 2; mi++) {
#pragma unroll
            for (int ni = 0; ni < 4; ni++) {
#pragma unroll
                for (int e = 0; e < 4; e++) {
                    int row = bm + m0w + mi * 16 + g + ((e >= 2) ? 8 : 0);
                    int gcol = bn + n0w + ni * 8 + tig * 2 + (e & 1);
                    if (row >= M || gcol >= N) continue;
                    int lc = gcol - seg * p.segW;
                    float v = c[mi][ni][e];
                    if (bias && (!atom || sk == 0)) v += bias[lc];
                    v *= scl;
                    long ci = (long)row * ldc + lc;
                    if (atom) {
                        atomicAdd(&C[ci], v);
                    } else {
                        if (p.act == 1) v = 0.5f * v * (1.f + erff(v * 0.70710678118654752f));
                        C[ci] = v;
                    }
                }
            }
        }
    }
}

// ---------------- fused flash attention (fp16 2-term) ----------------
__global__ __launch_bounds__(128) void flash_kernel(
    const float* __restrict__ Qb, const float* __restrict__ Kb,
    const float* __restrict__ Vb, uint2* __restrict__ OPk,
    float* __restrict__ mir, int lenKV, long kvBStride, int causal,
    float* __restrict__ Opart, float2* __restrict__ Msum, int kvChunk)
{
    __shared__ uint32_t Kh[64][36];
    __shared__ uint32_t Vh[64][33];

    int mt = blockIdx.x;
    int by = blockIdx.y;
    int sp = blockIdx.z;
    int b = by / HH, hh = by % HH;

    int kvStart = sp * kvChunk;
    int kvEnd = min(lenKV, kvStart + kvChunk);

    const float* Q = Qb + ((long)b * TT + mt * 64) * DD + hh * DHH;
    const float* K = Kb + (long)b * kvBStride + hh * DHH;
    const float* V = Vb + (long)b * kvBStride + hh * DHH;
    float* Mr = (mir && b == 0)
              ? mir + (size_t)hh * TT * TAA + (size_t)mt * 64 * TAA : nullptr;

    int tid = threadIdx.x;
    int lane = tid & 31, warp = tid >> 5;
    int g = lane >> 2, tig = lane & 3;
    int m0w = warp * 16;

    uint32_t Qah[4][4], Qal[4][4];
#pragma unroll
    for (int kb = 0; kb < 4; kb++) {
        int c0 = 16 * kb + 2 * tig;
        const float* r0 = Q + (long)(m0w + g) * DD;
        const float* r1 = Q + (long)(m0w + g + 8) * DD;
        float2 v;
        v = *(const float2*)(r0 + c0);     splitf16(v, Qah[kb][0], Qal[kb][0]);
        v = *(const float2*)(r1 + c0);     splitf16(v, Qah[kb][1], Qal[kb][1]);
        v = *(const float2*)(r0 + c0 + 8); splitf16(v, Qah[kb][2], Qal[kb][2]);
        v = *(const float2*)(r1 + c0 + 8); splitf16(v, Qah[kb][3], Qal[kb][3]);
    }

    float acc[8][4];
#pragma unroll
    for (int j = 0; j < 8; j++)
#pragma unroll
        for (int e = 0; e < 4; e++) acc[j][e] = 0.f;
    float m0 = -1e30f, m1 = -1e30f, sum0 = 0.f, sum1 = 0.f;

    int chBeg = kvStart >> 6;
    int chEnd = (kvEnd + 63) >> 6;
    if (causal) chEnd = min(chEnd, mt + 1);

    for (int ch = chBeg; ch < chEnd; ch++) {
        int n0 = ch * 64;
#pragma unroll
        for (int i = 0; i < 16; i++) {
            int idx = i * 128 + tid;
            int r = idx >> 5, c = idx & 31;
            float2 v = {0.f, 0.f};
            if (n0 + r < kvEnd) v = *(const float2*)(K + (long)(n0 + r) * DD + 2 * c);
            Kh[r][c] = h2pack(v.x, v.y);
        }
#pragma unroll
        for (int i = 0; i < 16; i++) {
            int idx = i * 128 + tid;
            int d = idx & 63, pr = idx >> 6;
            float2 v = {0.f, 0.f};
            int r0i = n0 + 2 * pr;
            if (r0i < kvEnd)     v.x = V[(long)r0i * DD + d];
            if (r0i + 1 < kvEnd) v.y = V[(long)(r0i + 1) * DD + d];
            Vh[d][pr] = h2pack(v.x, v.y);
        }
        __syncthreads();

        float s[8][4];
#pragma unroll
        for (int j = 0; j < 8; j++)
#pragma unroll
            for (int e = 0; e < 4; e++) s[j][e] = 0.f;
#pragma unroll
        for (int kb = 0; kb < 4; kb++) {
#pragma unroll
            for (int j = 0; j < 8; j++) {
                uint32_t bh[2] = { Kh[8 * j + g][8 * kb + tig], Kh[8 * j + g][8 * kb + tig + 4] };
                mma_f16(s[j], Qal[kb], bh);
                mma_f16(s[j], Qah[kb], bh);
            }
        }

        if (Mr) {
#pragma unroll
            for (int j = 0; j < 8; j++) {
                int col = n0 + 8 * j + 2 * tig;
                if (col < kvEnd) {
                    float2 v0 = { s[j][0], s[j][1] };
                    float2 v1 = { s[j][2], s[j][3] };
                    *(float2*)&Mr[(long)(m0w + g) * TAA + col] = v0;
                    *(float2*)&Mr[(long)(m0w + g + 8) * TAA + col] = v1;
                }
            }
        }

        if (causal && ch == mt) {
            int t0 = mt * 64 + m0w + g;
#pragma unroll
            for (int j = 0; j < 8; j++) {
                int col = n0 + 8 * j + 2 * tig;
                if (col     > t0)     s[j][0] = -1e30f;
                if (col + 1 > t0)     s[j][1] = -1e30f;
                if (col     > t0 + 8) s[j][2] = -1e30f;
                if (col + 1 > t0 + 8) s[j][3] = -1e30f;
            }
        }
        if (n0 + 64 > kvEnd) {
#pragma unroll
            for (int j = 0; j < 8; j++) {
                int col = n0 + 8 * j + 2 * tig;
                if (col     >= kvEnd) { s[j][0] = -1e30f; s[j][2] = -1e30f; }
                if (col + 1 >= kvEnd) { s[j][1] = -1e30f; s[j][3] = -1e30f; }
            }
        }

        float mx0 = -1e30f, mx1 = -1e30f;
#pragma unroll
        for (int j = 0; j < 8; j++) {
            mx0 = fmaxf(mx0, fmaxf(s[j][0], s[j][1]));
            mx1 = fmaxf(mx1, fmaxf(s[j][2], s[j][3]));
        }
        mx0 = fmaxf(mx0, __shfl_xor_sync(0xffffffffu, mx0, 1));
        mx0 = fmaxf(mx0, __shfl_xor_sync(0xffffffffu, mx0, 2));
        mx1 = fmaxf(mx1, __shfl_xor_sync(0xffffffffu, mx1, 1));
        mx1 = fmaxf(mx1, __shfl_xor_sync(0xffffffffu, mx1, 2));
        float mn0 = fmaxf(m0, mx0), mn1 = fmaxf(m1, mx1);
        float a0 = __expf(m0 - mn0), a1 = __expf(m1 - mn1);
        float ps0 = 0.f, ps1 = 0.f;
#pragma unroll
        for (int j = 0; j < 8; j++) {
            s[j][0] = __expf(s[j][0] - mn0);
            s[j][1] = __expf(s[j][1] - mn0);
            s[j][2] = __expf(s[j][2] - mn1);
            s[j][3] = __expf(s[j][3] - mn1);
            ps0 += s[j][0] + s[j][1];
            ps1 += s[j][2] + s[j][3];
        }
        ps0 += __shfl_xor_sync(0xffffffffu, ps0, 1);
        ps0 += __shfl_xor_sync(0xffffffffu, ps0, 2);
        ps1 += __shfl_xor_sync(0xffffffffu, ps1, 1);
        ps1 += __shfl_xor_sync(0xffffffffu, ps1, 2);
        sum0 = sum0 * a0 + ps0;
        sum1 = sum1 * a1 + ps1;
        m0 = mn0; m1 = mn1;
#pragma unroll
        for (int j = 0; j < 8; j++) {
            acc[j][0] *= a0; acc[j][1] *= a0;
            acc[j][2] *= a1; acc[j][3] *= a1;
        }

#pragma unroll
        for (int kb = 0; kb < 4; kb++) {
            int j0 = 2 * kb, j1 = 2 * kb + 1;
            uint32_t Ah[4], Al[4];
            Ah[0] = h2pack(s[j0][0], s[j0][1]);  Al[0] = lo_pack(s[j0][0], s[j0][1]);
            Ah[1] = h2pack(s[j0][2], s[j0][3]);  Al[1] = lo_pack(s[j0][2], s[j0][3]);
            Ah[2] = h2pack(s[j1][0], s[j1][1]);  Al[2] = lo_pack(s[j1][0], s[j1][1]);
            Ah[3] = h2pack(s[j1][2], s[j1][3]);  Al[3] = lo_pack(s[j1][2], s[j1][3]);
#pragma unroll
            for (int jd = 0; jd < 8; jd++) {
                uint32_t bh[2] = { Vh[8 * jd + g][8 * kb + tig], Vh[8 * jd + g][8 * kb + tig + 4] };
                mma_f16(acc[jd], Al, bh);
                mma_f16(acc[jd], Ah, bh);
            }
        }
        __syncthreads();
    }

    if (Opart) {
        float* OP = Opart + (((long)sp * BT) + (long)b * TT + mt * 64) * DD + hh * DHH;
#pragma unroll
        for (int jd = 0; jd < 8; jd++) {
            int col = 8 * jd + 2 * tig;
            float2 v0 = { acc[jd][0], acc[jd][1] };
            float2 v1 = { acc[jd][2], acc[jd][3] };
            *(float2*)&OP[(long)(m0w + g) * DD + col] = v0;
            *(float2*)&OP[(long)(m0w + g + 8) * DD + col] = v1;
        }
        if (tig == 0) {
            long base = (((long)sp * BB + b) * HH + hh) * TT + mt * 64;
            Msum[base + m0w + g]     = make_float2(m0, sum0);
            Msum[base + m0w + g + 8] = make_float2(m1, sum1);
        }
    } else {
        uint2* O2 = OPk + ((long)b * TT + mt * 64) * DP + hh * 32;
        float i0 = 1.f / sum0, i1 = 1.f / sum1;
#pragma unroll
        for (int jd = 0; jd < 8; jd++) {
            int pc = 4 * jd + tig;
            O2[(long)(m0w + g) * DP + pc]     = split2(acc[jd][0] * i0, acc[jd][1] * i0);
            O2[(long)(m0w + g + 8) * DP + pc] = split2(acc[jd][2] * i1, acc[jd][3] * i1);
        }
    }
}

__global__ __launch_bounds__(256) void flash_merge_kernel(
    const float* __restrict__ Opart, const float2* __restrict__ Msum,
    uint2* __restrict__ OPk)
{
    __shared__ float wgt[HH][NSPLIT];
    int row = blockIdx.x;
    int b = row / TT, t = row % TT;
    int tid = threadIdx.x;
    if (tid < HH) {
        int h = tid;
        float ms[NSPLIT], ss[NSPLIT];
        float m = -1e30f;
#pragma unroll
        for (int s = 0; s < NSPLIT; s++) {
            float2 v = Msum[(((long)s * BB + b) * HH + h) * TT + t];
            ms[s] = v.x; ss[s] = v.y;
            m = fmaxf(m, v.x);
        }
        float den = 0.f;
#pragma unroll
        for (int s = 0; s < NSPLIT; s++) den += ss[s] * __expf(ms[s] - m);
        float iden = 1.f / den;
#pragma unroll
        for (int s = 0; s < NSPLIT; s++) wgt[h][s] = __expf(ms[s] - m) * iden;
    }
    __syncthreads();
#pragma unroll
    for (int it = 0; it < 2; it++) {
        int pd = tid + it * 256;
        if (pd >= DP) break;
        int h = pd >> 5;
        float a0 = 0.f, a1 = 0.f;
#pragma unroll
        for (int s = 0; s < NSPLIT; s++) {
            const float* op = &Opart[(((long)s * BT) + row) * DD + 2 * pd];
            a0 += op[0] * wgt[h][s];
            a1 += op[1] * wgt[h][s];
        }
        OPk[(long)row * DP + pd] = split2(a0, a1);
    }
}

// ---------------- elementwise / row kernels ----------------
__global__ __launch_bounds__(256) void embed_kernel(
    const int* __restrict__ tokens, const float* __restrict__ tok_emb,
    const float* __restrict__ pos_emb, float* __restrict__ x)
{
    int row = blockIdx.x;
    int t = row % TT;
    int tok = tokens[row];
    const float* te = tok_emb + (long)tok * DD;
    const float* pe = pos_emb + (long)t * DD;
    float* xr = x + (long)row * DD;
#pragma unroll
    for (int it = 0; it < 3; it++) {
        int j = threadIdx.x + it * 256;
        xr[j] = te[j] + pe[j];
    }
}

__global__ __launch_bounds__(256) void ln_pack_kernel(
    const float* __restrict__ x, uint2* __restrict__ y,
    const float* __restrict__ g, const float* __restrict__ b)
{
    __shared__ float red[256];
    int row = blockIdx.x;
    const float* xr = x + (long)row * DD;
    uint2* yr = y + (long)row * DP;
    int tid = threadIdx.x;
    float v0 = xr[tid], v1 = xr[tid + 256], v2 = xr[tid + 512];
    float s = v0 + v1 + v2;
    red[tid] = s; __syncthreads();
    for (int st = 128; st > 0; st >>= 1) { if (tid < st) red[tid] += red[tid + st]; __syncthreads(); }
    float mean = red[0] * (1.f / DD);
    __syncthreads();
    float d0 = v0 - mean, d1 = v1 - mean, d2 = v2 - mean;
    red[tid] = d0 * d0 + d1 * d1 + d2 * d2; __syncthreads();
    for (int st = 128; st > 0; st >>= 1) { if (tid < st) red[tid] += red[tid + st]; __syncthreads(); }
    float inv = rsqrtf(red[0] * (1.f / DD) + 1e-5f);
    {
        int c0 = 2 * tid;
        float a = (xr[c0]     - mean) * inv * g[c0]     + b[c0];
        float c = (xr[c0 + 1] - mean) * inv * g[c0 + 1] + b[c0 + 1];
        yr[tid] = split2(a, c);
    }
    if (tid < 128) {
        int p1 = tid + 256;
        int c0 = 2 * p1;
        float a = (xr[c0]     - mean) * inv * g[c0]     + b[c0];
        float c = (xr[c0 + 1] - mean) * inv * g[c0 + 1] + b[c0 + 1];
        yr[p1] = split2(a, c);
    }
}

// ---------------- host-side launch helpers ----------------
static GemmP base_p() {
    GemmP p;
    p.A = nullptr; p.B0 = p.B1 = p.B2 = nullptr;
    p.C0 = p.C1 = p.C2 = nullptr; p.CP = nullptr;
    p.bias0 = p.bias1 = p.bias2 = nullptr;
    p.M = p.N = p.K = 0; p.ldap = p.ldbp = p.ldc = 0;
    p.Hd = 1; p.segW = 1 << 30; p.act = 0; p.splitK = 1; p.kc = 0;
    p.sA0 = p.sA1 = p.sB0 = p.sB1 = p.sC0 = p.sC1 = p.sBias = 0;
    p.s0 = p.s1 = p.s2 = 1.f;
    return p;
}

static inline int smem_bytes(int BIG) {
    int ALD2 = BIG ? 36 : 20;
    int AAREA2 = 128 * ALD2;
    int BAREA1 = BIG ? 4608 : 1280;
    return 2 * (AAREA2 * 2 + BAREA1) * 4;
}

template <int NT, int BIG>
static inline void launch_g(GemmP p, int batch, int splitK = 1) {
    p.splitK = splitK;
    constexpr int TBKv = BIG ? 64 : 32;
    int kc = (p.K + splitK - 1) / splitK;
    p.kc = ((kc + TBKv - 1) / TBKv) * TBKv;
    constexpr int BN = BIG ? 128 : 64;
    constexpr int NTHR = BIG ? 512 : 256;
    dim3 grd((p.N + BN - 1) / BN, (p.M + 127) / 128, batch * splitK);
    gemm_f16_kernel<NT, BIG><<<grd, NTHR, smem_bytes(BIG)>>>(p);
}

static inline int pkblocks(long n) {
    long b = (n + 255) / 256;
    return (int)(b > 8192 ? 8192 : b);
}

extern "C" void kernel_launch(void* const* d_in, const int* in_sizes, int n_in,
                              void* d_out, int out_size)
{
    (void)in_sizes; (void)n_in; (void)out_size;

    cudaFuncSetAttribute(gemm_f16_kernel<0, 0>, cudaFuncAttributeMaxDynamicSharedMemorySize, smem_bytes(0));
    cudaFuncSetAttribute(gemm_f16_kernel<1, 0>, cudaFuncAttributeMaxDynamicSharedMemorySize, smem_bytes(0));
    cudaFuncSetAttribute(gemm_f16_kernel<0, 1>, cudaFuncAttributeMaxDynamicSharedMemorySize, smem_bytes(1));
    cudaFuncSetAttribute(gemm_f16_kernel<1, 1>, cudaFuncAttributeMaxDynamicSharedMemorySize, smem_bytes(1));

    const int*   tokens  = (const int*)  d_in[0];
    const float* xa      = (const float*)d_in[1];
    const float* tok_emb = (const float*)d_in[2];
    const float* pos_emb = (const float*)d_in[3];
    const float* Wq      = (const float*)d_in[4];
    const float* bq      = (const float*)d_in[5];
    const float* Wk      = (const float*)d_in[6];
    const float* Wv      = (const float*)d_in[7];
    const float* bv      = (const float*)d_in[8];
    const float* Wo      = (const float*)d_in[9];
    const float* bo      = (const float*)d_in[10];
    const float* ln1_g   = (const float*)d_in[11];
    const float* ln1_b   = (const float*)d_in[12];
    const float* Wcq     = (const float*)d_in[13];
    const float* bcq     = (const float*)d_in[14];
    const float* Wck     = (const float*)d_in[15];
    const float* Wcv     = (const float*)d_in[16];
    const float* bcv     = (const float*)d_in[17];
    const float* Wco     = (const float*)d_in[18];
    const float* bco     = (const float*)d_in[19];
    const float* ln2_g   = (const float*)d_in[20];
    const float* ln2_b   = (const float*)d_in[21];
    const float* W1      = (const float*)d_in[22];
    const float* b1      = (const float*)d_in[23];
    const float* W2      = (const float*)d_in[24];
    const float* b2      = (const float*)d_in[25];
    const float* ln3_g   = (const float*)d_in[26];
    const float* ln3_b   = (const float*)d_in[27];
    const float* lnf_g   = (const float*)d_in[28];
    const float* lnf_b   = (const float*)d_in[29];

    float* out = (float*)d_out;
    float* out_logits = out;
    float* out_chw    = out_logits + (size_t)BB * TT * VV;
    float* out_kv     = out_chw + (size_t)(LL / 2) * HH * TT * TAA;

    float *x, *q, *ckall, *cvall, *opart;
    float2* msum;
    uint2 *hP, *oP, *hidP, *xaP;
    uint32_t *tokP, *WqP, *WkP, *WvP, *WoP, *WcqP, *WckP, *WcvP, *WcoP, *W1P, *W2P;
    cudaGetSymbolAddress((void**)&x,     g_x);
    cudaGetSymbolAddress((void**)&q,     g_q);
    cudaGetSymbolAddress((void**)&ckall, g_ckall);
    cudaGetSymbolAddress((void**)&cvall, g_cvall);
    cudaGetSymbolAddress((void**)&opart, g_opart);
    cudaGetSymbolAddress((void**)&msum,  g_msum);
    cudaGetSymbolAddress((void**)&hP,    g_hP);
    cudaGetSymbolAddress((void**)&oP,    g_oP);
    cudaGetSymbolAddress((void**)&hidP,  g_hidP);
    cudaGetSymbolAddress((void**)&xaP,   g_xaP);
    cudaGetSymbolAddress((void**)&tokP,  g_tokP);
    cudaGetSymbolAddress((void**)&WqP,   g_WqP);
    cudaGetSymbolAddress((void**)&WkP,   g_WkP);
    cudaGetSymbolAddress((void**)&WvP,   g_WvP);
    cudaGetSymbolAddress((void**)&WoP,   g_WoP);
    cudaGetSymbolAddress((void**)&WcqP,  g_WcqP);
    cudaGetSymbolAddress((void**)&WckP,  g_WckP);
    cudaGetSymbolAddress((void**)&WcvP,  g_WcvP);
    cudaGetSymbolAddress((void**)&WcoP,  g_WcoP);
    cudaGetSymbolAddress((void**)&W1P,   g_W1P);
    cudaGetSymbolAddress((void**)&W2P,   g_W2P);

    // ---- prepack ----
    {
        long n;
        n = (long)BB * TAA * DP;
        pack_contig_kernel<<<pkblocks(n), 256>>>(xa, xaP, n);
        n = (long)VV * DP;
        pack_contig_hi_kernel<<<pkblocks(n), 256>>>(tok_emb, tokP, n);

        PackW pw;
        pw.src[0] = Wq;  pw.dst[0] = WqP;
        pw.src[1] = Wk;  pw.dst[1] = WkP;
        pw.src[2] = Wv;  pw.dst[2] = WvP;
        pw.src[3] = Wo;  pw.dst[3] = WoP;
        pw.src[4] = Wcq; pw.dst[4] = WcqP;
        pw.src[5] = Wck; pw.dst[5] = WckP;
        pw.src[6] = Wcv; pw.dst[6] = WcvP;
        pw.src[7] = Wco; pw.dst[7] = WcoP;
        long nw = (long)LL * DP * DD;
        pack_w8_kernel<<<dim3(pkblocks(nw), 8), 256>>>(pw, nw);

        long n1 = (long)LL * DP * 4 * DD;
        pack_strideK_hi_kernel<<<pkblocks(n1), 256>>>(W1, W1P, DP, 4 * DD, n1);
        long n2 = (long)LL * 2 * DD * DD;
        pack_strideK_hi_kernel<<<pkblocks(n2), 256>>>(W2, W2P, 2 * DD, DD, n2);
    }

    embed_kernel<<<BT, 256>>>(tokens, tok_emb, pos_emb, x);

    const long DTD = (long)TT * DD;
    const long TAD = (long)TAA * DD;
    const size_t XBYTES = (size_t)BT * DD * sizeof(float);
    const int KVCH = ((TAA + NSPLIT * 64 - 1) / (NSPLIT * 64)) * 64;   // 384

    // cross K/V for ALL layers, batched over z=12 (BIG)
    {
        GemmP p = base_p();
        p.A = xaP; p.ldap = DP;
        p.B0 = WckP; p.ldbp = DD; p.sB1 = (long)DP * DD;
        p.C0 = ckall; p.ldc = DD; p.sC1 = (long)BTAD;
        p.M = BB * TAA; p.N = DD; p.K = DD; p.Hd = LL;
        launch_g<0, 1>(p, LL);
        p.B0 = WcvP; p.C0 = cvall;
        p.bias0 = bcv; p.sBias = DD;
        launch_g<0, 1>(p, LL);
    }

    for (int l = 0; l < LL; l++) {
        float* kout = out_kv + (size_t)(2 * l) * BT * DD;
        float* vout = out_kv + (size_t)(2 * l + 1) * BT * DD;
        float* ck_l = ckall + (size_t)l * BTAD;
        float* cv_l = cvall + (size_t)l * BTAD;
        const long WOFF = (long)l * DP * DD;

        // ---- self attention ----
        ln_pack_kernel<<<BT, 256>>>(x, hP, ln1_g + l * DD, ln1_b + l * DD);
        {   // fused QKV (BIG)
            GemmP p = base_p();
            p.A = hP; p.ldap = DP;
            p.B0 = WqP + WOFF; p.B1 = WkP + WOFF; p.B2 = WvP + WOFF; p.ldbp = DD;
            p.C0 = q; p.C1 = kout; p.C2 = vout; p.ldc = DD;
            p.bias0 = bq + l * DD; p.bias1 = nullptr; p.bias2 = bv + l * DD;
            p.s0 = SCALE_Q; p.s1 = 1.f; p.s2 = 1.f;
            p.segW = DD;
            p.M = BT; p.N = 3 * DD; p.K = DD;
            launch_g<0, 1>(p, 1);
        }
        flash_kernel<<<dim3(TT / 64, BB * HH, 1), 128>>>(
            q, kout, vout, oP, nullptr, TT, DTD, 1, nullptr, nullptr, TT);
        {   // x += o @ Wo + bo  (small, split-K atomics)
            GemmP p = base_p();
            p.A = oP; p.ldap = DP;
            p.B0 = WoP + WOFF; p.ldbp = DD;
            p.C0 = x; p.ldc = DD;
            p.bias0 = bo + l * DD;
            p.M = BT; p.N = DD; p.K = DD;
            launch_g<0, 0>(p, 1, 4);
        }

        // ---- cross attention ----
        ln_pack_kernel<<<BT, 256>>>(x, hP, ln2_g + l * DD, ln2_b + l * DD);
        cudaMemsetAsync(q, 0, XBYTES);
        {   // q2 (small, split-K atomics)
            GemmP p = base_p();
            p.A = hP; p.ldap = DP;
            p.B0 = WcqP + WOFF; p.ldbp = DD;
            p.C0 = q; p.ldc = DD;
            p.bias0 = bcq + l * DD; p.s0 = SCALE_Q;
            p.M = BT; p.N = DD; p.K = DD;
            launch_g<0, 0>(p, 1, 4);
        }
        {
            float* mir = (l >= LL / 2)
                       ? out_chw + (size_t)(l - LL / 2) * HH * TT * TAA : nullptr;
            flash_kernel<<<dim3(TT / 64, BB * HH, NSPLIT), 128>>>(
                q, ck_l, cv_l, nullptr, mir, TAA, TAD, 0, opart, msum, KVCH);
            flash_merge_kernel<<<BT, 256>>>(opart, msum, oP);
        }
        {   // x += o @ Wco + bco  (small, split-K atomics)
            GemmP p = base_p();
            p.A = oP; p.ldap = DP;
            p.B0 = WcoP + WOFF; p.ldbp = DD;
            p.C0 = x; p.ldc = DD;
            p.bias0 = bco + l * DD;
            p.M = BT; p.N = DD; p.K = DD;
            launch_g<0, 0>(p, 1, 4);
        }

        // ---- MLP ----
        ln_pack_kernel<<<BT, 256>>>(x, hP, ln3_g + l * DD, ln3_b + l * DD);
        {   // hidP = pack(gelu(h @ W1 + b1))  (BIG, packed epilogue)
            GemmP p = base_p();
            p.A = hP; p.ldap = DP;
            p.B0 = W1P + (long)l * DP * 4 * DD; p.ldbp = 4 * DD;
            p.CP = hidP; p.ldc = 4 * DD;
            p.bias0 = b1 + (size_t)l * 4 * DD; p.act = 1;
            p.M = BT; p.N = 4 * DD; p.K = DD;
            launch_g<0, 1>(p, 1);
        }
        {   // x += hid @ W2 + b2  (BIG, split-K 8)
            GemmP p = base_p();
            p.A = hidP; p.ldap = 2 * DD;
            p.B0 = W2P + (long)l * 2 * DD * DD; p.ldbp = DD;
            p.C0 = x; p.ldc = DD;
            p.bias0 = b2 + l * DD;
            p.M = BT; p.N = DD; p.K = 4 * DD;
            launch_g<0, 1>(p, 1, 8);
        }
    }

    // final LN + tied-embedding logits (BIG NT)
    ln_pack_kernel<<<BT, 256>>>(x, hP, lnf_g, lnf_b);
    {
        GemmP p = base_p();
        p.A = hP; p.ldap = DP;
        p.B0 = tokP; p.ldbp = DP;
        p.C0 = out_logits; p.ldc = VV;
        p.M = BT; p.N = VV; p.K = DD;
        launch_g<1, 1>(p, 1);
    }
}

// round 16
// speedup vs baseline: 1.6225x; 1.0668x over previous
#include <cuda_runtime.h>
#include <cuda_bf16.h>
#include <cuda_fp16.h>
#include <math.h>
#include <stdint.h>

// ---------------- problem constants ----------------
#define BB   4
#define TT   256
#define TAA  1500
#define DD   768
#define HH   12
#define LL   12
#define VV   51865
#define DHH  64
#define BT   (BB*TT)          // 1024
#define DP   (DD/2)           // 384 pairs
#define SCALE_Q 0.125f
#define BTAD ((size_t)BB*TAA*DD)
#define NSPLIT 4

// ---------------- scratch ----------------
__device__ float g_x  [BT*DD];
__device__ float g_q  [BT*DD];
__device__ uint32_t g_ckP[(size_t)LL*BB*TAA*DP];   // cross K, fp16-hi packed
__device__ float g_cvall[(size_t)LL*BTAD];
__device__ float g_opart[(size_t)NSPLIT*BT*DD];
__device__ float2 g_msum[(size_t)NSPLIT*BB*HH*TT];

// A-side packed fp16 hi/lo (uint2: x=hi pair, y=lo pair)
__device__ uint2 g_hP  [(size_t)BT*DP];
__device__ uint2 g_oP  [(size_t)BT*DP];
__device__ uint2 g_hidP[(size_t)BT*2*DD];
__device__ uint2 g_xaP [(size_t)BB*TAA*DP];
// B-side packed fp16 hi-only
__device__ uint32_t g_tokP[(size_t)VV*DP];
__device__ uint32_t g_WqP [(size_t)LL*DP*DD];
__device__ uint32_t g_WkP [(size_t)LL*DP*DD];
__device__ uint32_t g_WvP [(size_t)LL*DP*DD];
__device__ uint32_t g_WoP [(size_t)LL*DP*DD];
__device__ uint32_t g_WcqP[(size_t)LL*DP*DD];
__device__ uint32_t g_WckP[(size_t)LL*DP*DD];
__device__ uint32_t g_WcvP[(size_t)LL*DP*DD];
__device__ uint32_t g_WcoP[(size_t)LL*DP*DD];
__device__ uint32_t g_W1P [(size_t)LL*DP*4*DD];
__device__ uint32_t g_W2P [(size_t)LL*2*DD*DD];

// ---------------- helpers ----------------
__device__ __forceinline__ uint32_t h2pack(float a, float b) {
    __half2 t = __floats2half2_rn(a, b);
    return *(uint32_t*)&t;
}

__device__ __forceinline__ void splitf16(float2 v, uint32_t& hi, uint32_t& lo) {
    __half hx = __float2half_rn(v.x);
    __half hy = __float2half_rn(v.y);
    __half2 h; h.x = hx; h.y = hy;
    hi = *(uint32_t*)&h;
    lo = h2pack(v.x - __half2float(hx), v.y - __half2float(hy));
}

__device__ __forceinline__ uint2 split2(float a, float b) {
    uint32_t hi, lo;
    splitf16(make_float2(a, b), hi, lo);
    return make_uint2(hi, lo);
}

__device__ __forceinline__ uint32_t lo_pack(float a, float b) {
    float ra = a - __half2float(__float2half_rn(a));
    float rb = b - __half2float(__float2half_rn(b));
    return h2pack(ra, rb);
}

__device__ __forceinline__ void mma_f16(float* c, const uint32_t* a, const uint32_t* b) {
    asm volatile(
        "mma.sync.aligned.m16n8k16.row.col.f32.f16.f16.f32 "
        "{%0,%1,%2,%3}, {%4,%5,%6,%7}, {%8,%9}, {%0,%1,%2,%3};"
        : "+f"(c[0]), "+f"(c[1]), "+f"(c[2]), "+f"(c[3])
        : "r"(a[0]), "r"(a[1]), "r"(a[2]), "r"(a[3]), "r"(b[0]), "r"(b[1]));
}

__device__ __forceinline__ void cp16(uint32_t saddr, const void* gptr, bool pred) {
    int sz = pred ? 16 : 0;
    asm volatile("cp.async.cg.shared.global [%0], [%1], 16, %2;"
                 :: "r"(saddr), "l"(gptr), "r"(sz));
}
#define CP_COMMIT() asm volatile("cp.async.commit_group;")
#define CP_WAIT(n)  asm volatile("cp.async.wait_group %0;" :: "n"(n))

// ---------------- prepack kernels (div/mod free) ----------------
__global__ __launch_bounds__(256) void pack_contig_kernel(
    const float* __restrict__ in, uint2* __restrict__ out, long n)
{
    long i = blockIdx.x * 256L + threadIdx.x;
    long stride = (long)gridDim.x * 256;
    for (; i < n; i += stride) {
        float2 v = ((const float2*)in)[i];
        uint32_t hi, lo; splitf16(v, hi, lo);
        out[i] = make_uint2(hi, lo);
    }
}

__global__ __launch_bounds__(256) void pack_contig_hi_kernel(
    const float* __restrict__ in, uint32_t* __restrict__ out, long n)
{
    long i = blockIdx.x * 256L + threadIdx.x;
    long stride = (long)gridDim.x * 256;
    for (; i < n; i += stride) {
        float2 v = ((const float2*)in)[i];
        out[i] = h2pack(v.x, v.y);
    }
}

// one (layer,kp) row per block; threads cover N columns. in: [L][Khalf*2][N]
template <int NCOLS>
__global__ __launch_bounds__(256) void pack_rows_hi_kernel(
    const float* __restrict__ in, uint32_t* __restrict__ out, int Khalf)
{
    long row = blockIdx.x;                 // l*Khalf + kp
    long l = row / Khalf;                  // one div per block, not per element
    int kp = (int)(row - l * Khalf);
    const float* r0 = in + (l * (long)Khalf * 2 + 2 * kp) * NCOLS;
    const float* r1 = r0 + NCOLS;
    uint32_t* o = out + row * NCOLS;
#pragma unroll
    for (int it = 0; it < NCOLS / 256; it++) {
        int n = threadIdx.x + it * 256;
        o[n] = h2pack(r0[n], r1[n]);
    }
}

struct PackW { const float* src[8]; uint32_t* dst[8]; };
__global__ __launch_bounds__(256) void pack_w8_kernel(PackW p)
{
    const float* in = p.src[blockIdx.y];
    uint32_t* out = p.dst[blockIdx.y];
    long row = blockIdx.x;                 // l*DP + kp
    long l = row / DP;
    int kp = (int)(row - l * DP);
    const float* r0 = in + (l * (long)DD + 2 * kp) * DD;
    const float* r1 = r0 + DD;
    uint32_t* o = out + row * DD;
#pragma unroll
    for (int it = 0; it < 3; it++) {
        int n = threadIdx.x + it * 256;
        o[n] = h2pack(r0[n], r1[n]);
    }
}

// ---------------- packed fp16 GEMM (2-term) + split-K, cp.async double-buffered ----------------
struct GemmP {
    const uint2 *A;
    const uint32_t *B0, *B1, *B2;
    float *C0, *C1, *C2;
    uint2 *CP;
    uint32_t *CPh;
    const float *bias0, *bias1, *bias2;
    int M, N, K, ldap, ldbp, ldc, Hd, segW, act, splitK, kc;
    long sA0, sA1, sB0, sB1, sC0, sC1, sBias;
    float s0, s1, s2;
};

template <int NT, int BIG>
__global__ __launch_bounds__(BIG ? 512 : 256, BIG ? 1 : 2) void gemm_f16_kernel(GemmP p)
{
    constexpr int BN    = BIG ? 128 : 64;
    constexpr int NTHR  = BIG ? 512 : 256;
    constexpr int TBKv  = BIG ? 64 : 32;
    constexpr int KP    = TBKv / 2;
    constexpr int ALD2  = BIG ? 36 : 20;
    constexpr int BLD1  = BIG ? 36 : 20;
    constexpr int BLDN1 = BIG ? 132 : 68;
    constexpr int ACH   = 128 * (KP / 2) / NTHR;
    constexpr int BCHT  = BN * (KP / 4) / NTHR;
    constexpr int BCHN  = (KP * (BN / 4)) / NTHR;
    constexpr int AAREA2 = 128 * ALD2;
    constexpr int BAREA1 = BIG ? 4608 : 1280;
    constexpr int STAGE1 = AAREA2 * 2 + BAREA1;

    extern __shared__ uint32_t dsm1[];

    int z = blockIdx.z;
    int sk = z % p.splitK;
    int zz = z / p.splitK;
    int zb = zz / p.Hd, zh = zz % p.Hd;
    int bm = blockIdx.y * 128, bn = blockIdx.x * BN;
    int seg = bn / p.segW;
    int bnl = bn - seg * p.segW;

    const uint2* A = p.A + zb * p.sA0 + zh * p.sA1;
    const uint32_t* B = (seg == 0 ? p.B0 : seg == 1 ? p.B1 : p.B2) + zb * p.sB0 + zh * p.sB1;
    float* C = (seg == 0 ? p.C0 : seg == 1 ? p.C1 : p.C2) + zb * p.sC0 + zh * p.sC1;
    uint32_t* Ch = p.CPh ? p.CPh + ((zb * p.sC0 + zh * p.sC1) >> 1) : nullptr;
    const float* bias = (seg == 0 ? p.bias0 : seg == 1 ? p.bias1 : p.bias2);
    if (bias) bias += zh * p.sBias;
    float scl = seg == 0 ? p.s0 : seg == 1 ? p.s1 : p.s2;
    bool atom = p.splitK > 1;

    int M = p.M, N = p.N;
    int ldap = p.ldap, ldbp = p.ldbp, ldc = p.ldc;
    int kpstart = (sk * p.kc) >> 1;
    int kpend = min(p.K, sk * p.kc + p.kc) >> 1;

    int tid  = threadIdx.x;
    int lane = tid & 31;
    int warp = tid >> 5;
    int g    = lane >> 2;
    int tig  = lane & 3;
    int m0w  = (warp & 3) * 32;
    int n0w  = (warp >> 2) * 32;

    uint32_t smemBase = (uint32_t)__cvta_generic_to_shared(dsm1);

    float c[2][4][4];
#pragma unroll
    for (int mi = 0; mi < 2; mi++)
#pragma unroll
        for (int ni = 0; ni < 4; ni++)
#pragma unroll
            for (int e = 0; e < 4; e++) c[mi][ni][e] = 0.f;

    int iters = (kpend - kpstart + KP - 1) / KP;

    auto issue_stage = [&](int it, int s) {
        int kp0 = kpstart + it * KP;
        uint32_t aBase = smemBase + (uint32_t)s * STAGE1 * 4u;
        uint32_t bBase = aBase + (uint32_t)AAREA2 * 8u;
#pragma unroll
        for (int i = 0; i < ACH; i++) {
            int cix = i * NTHR + tid;
            int r, k2;
            if (BIG) { r = cix >> 4; k2 = cix & 15; }
            else     { r = cix >> 3; k2 = cix & 7; }
            int kp = 2 * k2;
            int gr = bm + r, kpg = kp0 + kp;
            bool ok = (gr < M) && (kpg < kpend);
            cp16(aBase + (uint32_t)(r * ALD2 + kp) * 8u,
                 A + (long)gr * ldap + kpg, ok);
        }
        if (NT) {
#pragma unroll
            for (int i = 0; i < BCHT; i++) {
                int cix = i * NTHR + tid;
                int n, k4;
                if (BIG) { n = cix >> 3; k4 = cix & 7; }
                else     { n = cix >> 2; k4 = cix & 3; }
                int kp = 4 * k4;
                int kpg = kp0 + kp;
                bool ok = (bn + n < N) && (kpg < kpend);
                cp16(bBase + (uint32_t)(n * BLD1 + kp) * 4u,
                     B + (long)(bnl + n) * ldbp + kpg, ok);
            }
        } else {
#pragma unroll
            for (int i = 0; i < BCHN; i++) {
                int cix = i * NTHR + tid;
                int kp, n4;
                if (BIG) { kp = cix >> 5; n4 = cix & 31; }
                else     { kp = cix >> 4; n4 = cix & 15; }
                int n = 4 * n4;
                int kpg = kp0 + kp;
                bool ok = (bn + n < N) && (kpg < kpend);
                cp16(bBase + (uint32_t)(kp * BLDN1 + n) * 4u,
                     B + (long)kpg * ldbp + bnl + n, ok);
            }
        }
        CP_COMMIT();
    };

    if (iters > 0) issue_stage(0, 0);

    for (int it = 0; it < iters; it++) {
        bool more = (it + 1 < iters);
        if (more) {
            issue_stage(it + 1, (it + 1) & 1);
            CP_WAIT(1);
        } else {
            CP_WAIT(0);
        }
        __syncthreads();

        int s = it & 1;
        const uint2* As = (const uint2*)(dsm1 + s * STAGE1);
        const uint32_t* Bs = dsm1 + s * STAGE1 + AAREA2 * 2;

#pragma unroll
        for (int h = 0; h < TBKv / 16; h++) {
            int kb = h * 8;
            uint32_t aH4[2][4], aL4[2][4];
#pragma unroll
            for (int mi = 0; mi < 2; mi++) {
                int m = m0w + mi * 16 + g;
                uint2 t0 = As[(m    ) * ALD2 + kb + tig];
                uint2 t1 = As[(m + 8) * ALD2 + kb + tig];
                uint2 t2 = As[(m    ) * ALD2 + kb + tig + 4];
                uint2 t3 = As[(m + 8) * ALD2 + kb + tig + 4];
                aH4[mi][0] = t0.x; aH4[mi][1] = t1.x; aH4[mi][2] = t2.x; aH4[mi][3] = t3.x;
                aL4[mi][0] = t0.y; aL4[mi][1] = t1.y; aL4[mi][2] = t2.y; aL4[mi][3] = t3.y;
            }
            uint32_t bh2[4][2];
#pragma unroll
            for (int ni = 0; ni < 4; ni++) {
                int n = n0w + ni * 8 + g;
                if (NT) {
                    bh2[ni][0] = Bs[n * BLD1 + kb + tig];
                    bh2[ni][1] = Bs[n * BLD1 + kb + tig + 4];
                } else {
                    bh2[ni][0] = Bs[(kb + tig) * BLDN1 + n];
                    bh2[ni][1] = Bs[(kb + tig + 4) * BLDN1 + n];
                }
            }
#pragma unroll
            for (int mi = 0; mi < 2; mi++)
#pragma unroll
                for (int ni = 0; ni < 4; ni++) {
                    mma_f16(c[mi][ni], aL4[mi], bh2[ni]);
                    mma_f16(c[mi][ni], aH4[mi], bh2[ni]);
                }
        }
        __syncthreads();
    }

    // ---- epilogue ----
    if (p.CP || Ch) {
        int ldcp = ldc >> 1;
#pragma unroll
        for (int mi = 0; mi < 2; mi++) {
#pragma unroll
            for (int ni = 0; ni < 4; ni++) {
                float v[4];
#pragma unroll
                for (int e = 0; e < 4; e++) {
                    int lc = bn + n0w + ni * 8 + tig * 2 + (e & 1);
                    float t = c[mi][ni][e];
                    if (bias) t += bias[lc];
                    t *= scl;
                    if (p.act == 1) t = 0.5f * t * (1.f + erff(t * 0.70710678118654752f));
                    v[e] = t;
                }
                int row0 = bm + m0w + mi * 16 + g;
                int pc = (bn + n0w + ni * 8) / 2 + tig;
                if (p.CP) {
                    if (row0 < M)     p.CP[(long)row0 * ldcp + pc]       = split2(v[0], v[1]);
                    if (row0 + 8 < M) p.CP[(long)(row0 + 8) * ldcp + pc] = split2(v[2], v[3]);
                } else {
                    if (row0 < M)     Ch[(long)row0 * ldcp + pc]       = h2pack(v[0], v[1]);
                    if (row0 + 8 < M) Ch[(long)(row0 + 8) * ldcp + pc] = h2pack(v[2], v[3]);
                }
            }
        }
    } else {
#pragma unroll
        for (int mi = 0; mi < 2; mi++) {
#pragma unroll
            for (int ni = 0; ni < 4; ni++) {
#pragma unroll
                for (int e = 0; e < 4; e++) {
                    int row = bm + m0w + mi * 16 + g + ((e >= 2) ? 8 : 0);
                    int gcol = bn + n0w + ni * 8 + tig * 2 + (e & 1);
                    if (row >= M || gcol >= N) continue;
                    int lc = gcol - seg * p.segW;
                    float v = c[mi][ni][e];
                    if (bias && (!atom || sk == 0)) v += bias[lc];
                    v *= scl;
                    long ci = (long)row * ldc + lc;
                    if (atom) {
                        atomicAdd(&C[ci], v);
                    } else {
                        if (p.act == 1) v = 0.5f * v * (1.f + erff(v * 0.70710678118654752f));
                        C[ci] = v;
                    }
                }
            }
        }
    }
}

// ---------------- fused flash attention (fp16 2-term; K optionally pre-packed) ----------------
__global__ __launch_bounds__(128) void flash_kernel(
    const float* __restrict__ Qb, const float* __restrict__ Kb,
    const uint32_t* __restrict__ KbP,
    const float* __restrict__ Vb, uint2* __restrict__ OPk,
    float* __restrict__ mir, int lenKV, long kvBStride, int causal,
    float* __restrict__ Opart, float2* __restrict__ Msum, int kvChunk)
{
    __shared__ uint32_t Kh[64][36];
    __shared__ uint32_t Vh[64][33];

    int mt = blockIdx.x;
    int by = blockIdx.y;
    int sp = blockIdx.z;
    int b = by / HH, hh = by % HH;

    int kvStart = sp * kvChunk;
    int kvEnd = min(lenKV, kvStart + kvChunk);

    const float* Q = Qb + ((long)b * TT + mt * 64) * DD + hh * DHH;
    const float* K = Kb ? Kb + (long)b * kvBStride + hh * DHH : nullptr;
    const uint32_t* KP2 = KbP ? KbP + (long)b * TAA * DP + hh * 32 : nullptr;
    const float* V = Vb + (long)b * kvBStride + hh * DHH;
    float* Mr = (mir && b == 0)
              ? mir + (size_t)hh * TT * TAA + (size_t)mt * 64 * TAA : nullptr;

    int tid = threadIdx.x;
    int lane = tid & 31, warp = tid >> 5;
    int g = lane >> 2, tig = lane & 3;
    int m0w = warp * 16;

    uint32_t Qah[4][4], Qal[4][4];
#pragma unroll
    for (int kb = 0; kb < 4; kb++) {
        int c0 = 16 * kb + 2 * tig;
        const float* r0 = Q + (long)(m0w + g) * DD;
        const float* r1 = Q + (long)(m0w + g + 8) * DD;
        float2 v;
        v = *(const float2*)(r0 + c0);     splitf16(v, Qah[kb][0], Qal[kb][0]);
        v = *(const float2*)(r1 + c0);     splitf16(v, Qah[kb][1], Qal[kb][1]);
        v = *(const float2*)(r0 + c0 + 8); splitf16(v, Qah[kb][2], Qal[kb][2]);
        v = *(const float2*)(r1 + c0 + 8); splitf16(v, Qah[kb][3], Qal[kb][3]);
    }

    float acc[8][4];
#pragma unroll
    for (int j = 0; j < 8; j++)
#pragma unroll
        for (int e = 0; e < 4; e++) acc[j][e] = 0.f;
    float m0 = -1e30f, m1 = -1e30f, sum0 = 0.f, sum1 = 0.f;

    int chBeg = kvStart >> 6;
    int chEnd = (kvEnd + 63) >> 6;
    if (causal) chEnd = min(chEnd, mt + 1);

    for (int ch = chBeg; ch < chEnd; ch++) {
        int n0 = ch * 64;
        if (KP2) {
#pragma unroll
            for (int i = 0; i < 16; i++) {
                int idx = i * 128 + tid;
                int r = idx >> 5, c = idx & 31;
                Kh[r][c] = (n0 + r < kvEnd) ? KP2[(long)(n0 + r) * DP + c] : 0u;
            }
        } else {
#pragma unroll
            for (int i = 0; i < 16; i++) {
                int idx = i * 128 + tid;
                int r = idx >> 5, c = idx & 31;
                float2 v = {0.f, 0.f};
                if (n0 + r < kvEnd) v = *(const float2*)(K + (long)(n0 + r) * DD + 2 * c);
                Kh[r][c] = h2pack(v.x, v.y);
            }
        }
#pragma unroll
        for (int i = 0; i < 16; i++) {
            int idx = i * 128 + tid;
            int d = idx & 63, pr = idx >> 6;
            float2 v = {0.f, 0.f};
            int r0i = n0 + 2 * pr;
            if (r0i < kvEnd)     v.x = V[(long)r0i * DD + d];
            if (r0i + 1 < kvEnd) v.y = V[(long)(r0i + 1) * DD + d];
            Vh[d][pr] = h2pack(v.x, v.y);
        }
        __syncthreads();

        float s[8][4];
#pragma unroll
        for (int j = 0; j < 8; j++)
#pragma unroll
            for (int e = 0; e < 4; e++) s[j][e] = 0.f;
#pragma unroll
        for (int kb = 0; kb < 4; kb++) {
#pragma unroll
            for (int j = 0; j < 8; j++) {
                uint32_t bh[2] = { Kh[8 * j + g][8 * kb + tig], Kh[8 * j + g][8 * kb + tig + 4] };
                mma_f16(s[j], Qal[kb], bh);
                mma_f16(s[j], Qah[kb], bh);
            }
        }

        if (Mr) {
#pragma unroll
            for (int j = 0; j < 8; j++) {
                int col = n0 + 8 * j + 2 * tig;
                if (col < kvEnd) {
                    float2 v0 = { s[j][0], s[j][1] };
                    float2 v1 = { s[j][2], s[j][3] };
                    *(float2*)&Mr[(long)(m0w + g) * TAA + col] = v0;
                    *(float2*)&Mr[(long)(m0w + g + 8) * TAA + col] = v1;
                }
            }
        }

        if (causal && ch == mt) {
            int t0 = mt * 64 + m0w + g;
#pragma unroll
            for (int j = 0; j < 8; j++) {
                int col = n0 + 8 * j + 2 * tig;
                if (col     > t0)     s[j][0] = -1e30f;
                if (col + 1 > t0)     s[j][1] = -1e30f;
                if (col     > t0 + 8) s[j][2] = -1e30f;
                if (col + 1 > t0 + 8) s[j][3] = -1e30f;
            }
        }
        if (n0 + 64 > kvEnd) {
#pragma unroll
            for (int j = 0; j < 8; j++) {
                int col = n0 + 8 * j + 2 * tig;
                if (col     >= kvEnd) { s[j][0] = -1e30f; s[j][2] = -1e30f; }
                if (col + 1 >= kvEnd) { s[j][1] = -1e30f; s[j][3] = -1e30f; }
            }
        }

        float mx0 = -1e30f, mx1 = -1e30f;
#pragma unroll
        for (int j = 0; j < 8; j++) {
            mx0 = fmaxf(mx0, fmaxf(s[j][0], s[j][1]));
            mx1 = fmaxf(mx1, fmaxf(s[j][2], s[j][3]));
        }
        mx0 = fmaxf(mx0, __shfl_xor_sync(0xffffffffu, mx0, 1));
        mx0 = fmaxf(mx0, __shfl_xor_sync(0xffffffffu, mx0, 2));
        mx1 = fmaxf(mx1, __shfl_xor_sync(0xffffffffu, mx1, 1));
        mx1 = fmaxf(mx1, __shfl_xor_sync(0xffffffffu, mx1, 2));
        float mn0 = fmaxf(m0, mx0), mn1 = fmaxf(m1, mx1);
        float a0 = __expf(m0 - mn0), a1 = __expf(m1 - mn1);
        float ps0 = 0.f, ps1 = 0.f;
#pragma unroll
        for (int j = 0; j < 8; j++) {
            s[j][0] = __expf(s[j][0] - mn0);
            s[j][1] = __expf(s[j][1] - mn0);
            s[j][2] = __expf(s[j][2] - mn1);
            s[j][3] = __expf(s[j][3] - mn1);
            ps0 += s[j][0] + s[j][1];
            ps1 += s[j][2] + s[j][3];
        }
        ps0 += __shfl_xor_sync(0xffffffffu, ps0, 1);
        ps0 += __shfl_xor_sync(0xffffffffu, ps0, 2);
        ps1 += __shfl_xor_sync(0xffffffffu, ps1, 1);
        ps1 += __shfl_xor_sync(0xffffffffu, ps1, 2);
        sum0 = sum0 * a0 + ps0;
        sum1 = sum1 * a1 + ps1;
        m0 = mn0; m1 = mn1;
#pragma unroll
        for (int j = 0; j < 8; j++) {
            acc[j][0] *= a0; acc[j][1] *= a0;
            acc[j][2] *= a1; acc[j][3] *= a1;
        }

#pragma unroll
        for (int kb = 0; kb < 4; kb++) {
            int j0 = 2 * kb, j1 = 2 * kb + 1;
            uint32_t Ah[4], Al[4];
            Ah[0] = h2pack(s[j0][0], s[j0][1]);  Al[0] = lo_pack(s[j0][0], s[j0][1]);
            Ah[1] = h2pack(s[j0][2], s[j0][3]);  Al[1] = lo_pack(s[j0][2], s[j0][3]);
            Ah[2] = h2pack(s[j1][0], s[j1][1]);  Al[2] = lo_pack(s[j1][0], s[j1][1]);
            Ah[3] = h2pack(s[j1][2], s[j1][3]);  Al[3] = lo_pack(s[j1][2], s[j1][3]);
#pragma unroll
            for (int jd = 0; jd < 8; jd++) {
                uint32_t bh[2] = { Vh[8 * jd + g][8 * kb + tig], Vh[8 * jd + g][8 * kb + tig + 4] };
                mma_f16(acc[jd], Al, bh);
                mma_f16(acc[jd], Ah, bh);
            }
        }
        __syncthreads();
    }

    if (Opart) {
        float* OP = Opart + (((long)sp * BT) + (long)b * TT + mt * 64) * DD + hh * DHH;
#pragma unroll
        for (int jd = 0; jd < 8; jd++) {
            int col = 8 * jd + 2 * tig;
            float2 v0 = { acc[jd][0], acc[jd][1] };
            float2 v1 = { acc[jd][2], acc[jd][3] };
            *(float2*)&OP[(long)(m0w + g) * DD + col] = v0;
            *(float2*)&OP[(long)(m0w + g + 8) * DD + col] = v1;
        }
        if (tig == 0) {
            long base = (((long)sp * BB + b) * HH + hh) * TT + mt * 64;
            Msum[base + m0w + g]     = make_float2(m0, sum0);
            Msum[base + m0w + g + 8] = make_float2(m1, sum1);
        }
    } else {
        uint2* O2 = OPk + ((long)b * TT + mt * 64) * DP + hh * 32;
        float i0 = 1.f / sum0, i1 = 1.f / sum1;
#pragma unroll
        for (int jd = 0; jd < 8; jd++) {
            int pc = 4 * jd + tig;
            O2[(long)(m0w + g) * DP + pc]     = split2(acc[jd][0] * i0, acc[jd][1] * i0);
            O2[(long)(m0w + g + 8) * DP + pc] = split2(acc[jd][2] * i1, acc[jd][3] * i1);
        }
    }
}

__global__ __launch_bounds__(256) void flash_merge_kernel(
    const float* __restrict__ Opart, const float2* __restrict__ Msum,
    uint2* __restrict__ OPk)
{
    __shared__ float wgt[HH][NSPLIT];
    int row = blockIdx.x;
    int b = row / TT, t = row % TT;
    int tid = threadIdx.x;
    if (tid < HH) {
        int h = tid;
        float ms[NSPLIT], ss[NSPLIT];
        float m = -1e30f;
#pragma unroll
        for (int s = 0; s < NSPLIT; s++) {
            float2 v = Msum[(((long)s * BB + b) * HH + h) * TT + t];
            ms[s] = v.x; ss[s] = v.y;
            m = fmaxf(m, v.x);
        }
        float den = 0.f;
#pragma unroll
        for (int s = 0; s < NSPLIT; s++) den += ss[s] * __expf(ms[s] - m);
        float iden = 1.f / den;
#pragma unroll
        for (int s = 0; s < NSPLIT; s++) wgt[h][s] = __expf(ms[s] - m) * iden;
    }
    __syncthreads();
#pragma unroll
    for (int it = 0; it < 2; it++) {
        int pd = tid + it * 256;
        if (pd >= DP) break;
        int h = pd >> 5;
        float a0 = 0.f, a1 = 0.f;
#pragma unroll
        for (int s = 0; s < NSPLIT; s++) {
            const float* op = &Opart[(((long)s * BT) + row) * DD + 2 * pd];
            a0 += op[0] * wgt[h][s];
            a1 += op[1] * wgt[h][s];
        }
        OPk[(long)row * DP + pd] = split2(a0, a1);
    }
}

// ---------------- elementwise / row kernels ----------------
__global__ __launch_bounds__(256) void embed_kernel(
    const int* __restrict__ tokens, const float* __restrict__ tok_emb,
    const float* __restrict__ pos_emb, float* __restrict__ x)
{
    int row = blockIdx.x;
    int t = row % TT;
    int tok = tokens[row];
    const float* te = tok_emb + (long)tok * DD;
    const float* pe = pos_emb + (long)t * DD;
    float* xr = x + (long)row * DD;
#pragma unroll
    for (int it = 0; it < 3; it++) {
        int j = threadIdx.x + it * 256;
        xr[j] = te[j] + pe[j];
    }
}

__global__ __launch_bounds__(256) void ln_pack_kernel(
    const float* __restrict__ x, uint2* __restrict__ y,
    const float* __restrict__ g, const float* __restrict__ b)
{
    __shared__ float red[256];
    int row = blockIdx.x;
    const float* xr = x + (long)row * DD;
    uint2* yr = y + (long)row * DP;
    int tid = threadIdx.x;
    float v0 = xr[tid], v1 = xr[tid + 256], v2 = xr[tid + 512];
    float s = v0 + v1 + v2;
    red[tid] = s; __syncthreads();
    for (int st = 128; st > 0; st >>= 1) { if (tid < st) red[tid] += red[tid + st]; __syncthreads(); }
    float mean = red[0] * (1.f / DD);
    __syncthreads();
    float d0 = v0 - mean, d1 = v1 - mean, d2 = v2 - mean;
    red[tid] = d0 * d0 + d1 * d1 + d2 * d2; __syncthreads();
    for (int st = 128; st > 0; st >>= 1) { if (tid < st) red[tid] += red[tid + st]; __syncthreads(); }
    float inv = rsqrtf(red[0] * (1.f / DD) + 1e-5f);
    {
        int c0 = 2 * tid;
        float a = (xr[c0]     - mean) * inv * g[c0]     + b[c0];
        float c = (xr[c0 + 1] - mean) * inv * g[c0 + 1] + b[c0 + 1];
        yr[tid] = split2(a, c);
    }
    if (tid < 128) {
        int p1 = tid + 256;
        int c0 = 2 * p1;
        float a = (xr[c0]     - mean) * inv * g[c0]     + b[c0];
        float c = (xr[c0 + 1] - mean) * inv * g[c0 + 1] + b[c0 + 1];
        yr[p1] = split2(a, c);
    }
}

// ---------------- host-side launch helpers ----------------
static GemmP base_p() {
    GemmP p;
    p.A = nullptr; p.B0 = p.B1 = p.B2 = nullptr;
    p.C0 = p.C1 = p.C2 = nullptr; p.CP = nullptr; p.CPh = nullptr;
    p.bias0 = p.bias1 = p.bias2 = nullptr;
    p.M = p.N = p.K = 0; p.ldap = p.ldbp = p.ldc = 0;
    p.Hd = 1; p.segW = 1 << 30; p.act = 0; p.splitK = 1; p.kc = 0;
    p.sA0 = p.sA1 = p.sB0 = p.sB1 = p.sC0 = p.sC1 = p.sBias = 0;
    p.s0 = p.s1 = p.s2 = 1.f;
    return p;
}

static inline int smem_bytes(int BIG) {
    int ALD2 = BIG ? 36 : 20;
    int AAREA2 = 128 * ALD2;
    int BAREA1 = BIG ? 4608 : 1280;
    return 2 * (AAREA2 * 2 + BAREA1) * 4;
}

template <int NT, int BIG>
static inline void launch_g(GemmP p, int batch, int splitK = 1) {
    p.splitK = splitK;
    constexpr int TBKv = BIG ? 64 : 32;
    int kc = (p.K + splitK - 1) / splitK;
    p.kc = ((kc + TBKv - 1) / TBKv) * TBKv;
    constexpr int BN = BIG ? 128 : 64;
    constexpr int NTHR = BIG ? 512 : 256;
    dim3 grd((p.N + BN - 1) / BN, (p.M + 127) / 128, batch * splitK);
    gemm_f16_kernel<NT, BIG><<<grd, NTHR, smem_bytes(BIG)>>>(p);
}

static inline int pkblocks(long n) {
    long b = (n + 255) / 256;
    return (int)(b > 8192 ? 8192 : b);
}

extern "C" void kernel_launch(void* const* d_in, const int* in_sizes, int n_in,
                              void* d_out, int out_size)
{
    (void)in_sizes; (void)n_in; (void)out_size;

    cudaFuncSetAttribute(gemm_f16_kernel<0, 0>, cudaFuncAttributeMaxDynamicSharedMemorySize, smem_bytes(0));
    cudaFuncSetAttribute(gemm_f16_kernel<1, 0>, cudaFuncAttributeMaxDynamicSharedMemorySize, smem_bytes(0));
    cudaFuncSetAttribute(gemm_f16_kernel<0, 1>, cudaFuncAttributeMaxDynamicSharedMemorySize, smem_bytes(1));
    cudaFuncSetAttribute(gemm_f16_kernel<1, 1>, cudaFuncAttributeMaxDynamicSharedMemorySize, smem_bytes(1));

    const int*   tokens  = (const int*)  d_in[0];
    const float* xa      = (const float*)d_in[1];
    const float* tok_emb = (const float*)d_in[2];
    const float* pos_emb = (const float*)d_in[3];
    const float* Wq      = (const float*)d_in[4];
    const float* bq      = (const float*)d_in[5];
    const float* Wk      = (const float*)d_in[6];
    const float* Wv      = (const float*)d_in[7];
    const float* bv      = (const float*)d_in[8];
    const float* Wo      = (const float*)d_in[9];
    const float* bo      = (const float*)d_in[10];
    const float* ln1_g   = (const float*)d_in[11];
    const float* ln1_b   = (const float*)d_in[12];
    const float* Wcq     = (const float*)d_in[13];
    const float* bcq     = (const float*)d_in[14];
    const float* Wck     = (const float*)d_in[15];
    const float* Wcv     = (const float*)d_in[16];
    const float* bcv     = (const float*)d_in[17];
    const float* Wco     = (const float*)d_in[18];
    const float* bco     = (const float*)d_in[19];
    const float* ln2_g   = (const float*)d_in[20];
    const float* ln2_b   = (const float*)d_in[21];
    const float* W1      = (const float*)d_in[22];
    const float* b1      = (const float*)d_in[23];
    const float* W2      = (const float*)d_in[24];
    const float* b2      = (const float*)d_in[25];
    const float* ln3_g   = (const float*)d_in[26];
    const float* ln3_b   = (const float*)d_in[27];
    const float* lnf_g   = (const float*)d_in[28];
    const float* lnf_b   = (const float*)d_in[29];

    float* out = (float*)d_out;
    float* out_logits = out;
    float* out_chw    = out_logits + (size_t)BB * TT * VV;
    float* out_kv     = out_chw + (size_t)(LL / 2) * HH * TT * TAA;

    float *x, *q, *cvall, *opart;
    float2* msum;
    uint2 *hP, *oP, *hidP, *xaP;
    uint32_t *ckP, *tokP, *WqP, *WkP, *WvP, *WoP, *WcqP, *WckP, *WcvP, *WcoP, *W1P, *W2P;
    cudaGetSymbolAddress((void**)&x,     g_x);
    cudaGetSymbolAddress((void**)&q,     g_q);
    cudaGetSymbolAddress((void**)&ckP,   g_ckP);
    cudaGetSymbolAddress((void**)&cvall, g_cvall);
    cudaGetSymbolAddress((void**)&opart, g_opart);
    cudaGetSymbolAddress((void**)&msum,  g_msum);
    cudaGetSymbolAddress((void**)&hP,    g_hP);
    cudaGetSymbolAddress((void**)&oP,    g_oP);
    cudaGetSymbolAddress((void**)&hidP,  g_hidP);
    cudaGetSymbolAddress((void**)&xaP,   g_xaP);
    cudaGetSymbolAddress((void**)&tokP,  g_tokP);
    cudaGetSymbolAddress((void**)&WqP,   g_WqP);
    cudaGetSymbolAddress((void**)&WkP,   g_WkP);
    cudaGetSymbolAddress((void**)&WvP,   g_WvP);
    cudaGetSymbolAddress((void**)&WoP,   g_WoP);
    cudaGetSymbolAddress((void**)&WcqP,  g_WcqP);
    cudaGetSymbolAddress((void**)&WckP,  g_WckP);
    cudaGetSymbolAddress((void**)&WcvP,  g_WcvP);
    cudaGetSymbolAddress((void**)&WcoP,  g_WcoP);
    cudaGetSymbolAddress((void**)&W1P,   g_W1P);
    cudaGetSymbolAddress((void**)&W2P,   g_W2P);

    // ---- prepack ----
    {
        long n;
        n = (long)BB * TAA * DP;
        pack_contig_kernel<<<pkblocks(n), 256>>>(xa, xaP, n);
        n = (long)VV * DP;
        pack_contig_hi_kernel<<<pkblocks(n), 256>>>(tok_emb, tokP, n);

        PackW pw;
        pw.src[0] = Wq;  pw.dst[0] = WqP;
        pw.src[1] = Wk;  pw.dst[1] = WkP;
        pw.src[2] = Wv;  pw.dst[2] = WvP;
        pw.src[3] = Wo;  pw.dst[3] = WoP;
        pw.src[4] = Wcq; pw.dst[4] = WcqP;
        pw.src[5] = Wck; pw.dst[5] = WckP;
        pw.src[6] = Wcv; pw.dst[6] = WcvP;
        pw.src[7] = Wco; pw.dst[7] = WcoP;
        pack_w8_kernel<<<dim3(LL * DP, 8), 256>>>(pw);

        pack_rows_hi_kernel<4 * DD><<<LL * DP, 256>>>(W1, W1P, DP);
        pack_rows_hi_kernel<DD><<<LL * 2 * DD, 256>>>(W2, W2P, 2 * DD);
    }

    embed_kernel<<<BT, 256>>>(tokens, tok_emb, pos_emb, x);

    const long DTD = (long)TT * DD;
    const size_t XBYTES = (size_t)BT * DD * sizeof(float);
    const int KVCH = ((TAA + NSPLIT * 64 - 1) / (NSPLIT * 64)) * 64;   // 384

    // cross K/V for ALL layers, batched over z=12 (BIG)
    {
        GemmP p = base_p();
        p.A = xaP; p.ldap = DP;
        p.B0 = WckP; p.ldbp = DD; p.sB1 = (long)DP * DD;
        p.CPh = ckP; p.ldc = DD; p.sC1 = (long)BB * TAA * DD;  // halved inside for packed
        p.M = BB * TAA; p.N = DD; p.K = DD; p.Hd = LL;
        launch_g<0, 1>(p, LL);

        GemmP pv = base_p();
        pv.A = xaP; pv.ldap = DP;
        pv.B0 = WcvP; pv.ldbp = DD; pv.sB1 = (long)DP * DD;
        pv.C0 = cvall; pv.ldc = DD; pv.sC1 = (long)BTAD;
        pv.bias0 = bcv; pv.sBias = DD;
        pv.M = BB * TAA; pv.N = DD; pv.K = DD; pv.Hd = LL;
        launch_g<0, 1>(pv, LL);
    }

    for (int l = 0; l < LL; l++) {
        float* kout = out_kv + (size_t)(2 * l) * BT * DD;
        float* vout = out_kv + (size_t)(2 * l + 1) * BT * DD;
        uint32_t* ckP_l = ckP + (size_t)l * BB * TAA * DP;
        float* cv_l = cvall + (size_t)l * BTAD;
        const long WOFF = (long)l * DP * DD;

        // ---- self attention ----
        ln_pack_kernel<<<BT, 256>>>(x, hP, ln1_g + l * DD, ln1_b + l * DD);
        {   // fused QKV (small tiles, 2 CTAs/SM)
            GemmP p = base_p();
            p.A = hP; p.ldap = DP;
            p.B0 = WqP + WOFF; p.B1 = WkP + WOFF; p.B2 = WvP + WOFF; p.ldbp = DD;
            p.C0 = q; p.C1 = kout; p.C2 = vout; p.ldc = DD;
            p.bias0 = bq + l * DD; p.bias1 = nullptr; p.bias2 = bv + l * DD;
            p.s0 = SCALE_Q; p.s1 = 1.f; p.s2 = 1.f;
            p.segW = DD;
            p.M = BT; p.N = 3 * DD; p.K = DD;
            launch_g<0, 0>(p, 1);
        }
        flash_kernel<<<dim3(TT / 64, BB * HH, 1), 128>>>(
            q, kout, nullptr, vout, oP, nullptr, TT, DTD, 1, nullptr, nullptr, TT);
        {   // x += o @ Wo + bo
            GemmP p = base_p();
            p.A = oP; p.ldap = DP;
            p.B0 = WoP + WOFF; p.ldbp = DD;
            p.C0 = x; p.ldc = DD;
            p.bias0 = bo + l * DD;
            p.M = BT; p.N = DD; p.K = DD;
            launch_g<0, 0>(p, 1, 4);
        }

        // ---- cross attention ----
        ln_pack_kernel<<<BT, 256>>>(x, hP, ln2_g + l * DD, ln2_b + l * DD);
        cudaMemsetAsync(q, 0, XBYTES);
        {   // q2
            GemmP p = base_p();
            p.A = hP; p.ldap = DP;
            p.B0 = WcqP + WOFF; p.ldbp = DD;
            p.C0 = q; p.ldc = DD;
            p.bias0 = bcq + l * DD; p.s0 = SCALE_Q;
            p.M = BT; p.N = DD; p.K = DD;
            launch_g<0, 0>(p, 1, 4);
        }
        {
            float* mir = (l >= LL / 2)
                       ? out_chw + (size_t)(l - LL / 2) * HH * TT * TAA : nullptr;
            flash_kernel<<<dim3(TT / 64, BB * HH, NSPLIT), 128>>>(
                q, nullptr, ckP_l, cv_l, nullptr, mir, TAA, (long)TAA * DD, 0,
                opart, msum, KVCH);
            flash_merge_kernel<<<BT, 256>>>(opart, msum, oP);
        }
        {   // x += o @ Wco + bco
            GemmP p = base_p();
            p.A = oP; p.ldap = DP;
            p.B0 = WcoP + WOFF; p.ldbp = DD;
            p.C0 = x; p.ldc = DD;
            p.bias0 = bco + l * DD;
            p.M = BT; p.N = DD; p.K = DD;
            launch_g<0, 0>(p, 1, 4);
        }

        // ---- MLP ----
        ln_pack_kernel<<<BT, 256>>>(x, hP, ln3_g + l * DD, ln3_b + l * DD);
        {   // hidP (small tiles, packed epilogue)
            GemmP p = base_p();
            p.A = hP; p.ldap = DP;
            p.B0 = W1P + (long)l * DP * 4 * DD; p.ldbp = 4 * DD;
            p.CP = hidP; p.ldc = 4 * DD;
            p.bias0 = b1 + (size_t)l * 4 * DD; p.act = 1;
            p.M = BT; p.N = 4 * DD; p.K = DD;
            launch_g<0, 0>(p, 1);
        }
        {   // x += hid @ W2 + b2 (BIG, split-K 8)
            GemmP p = base_p();
            p.A = hidP; p.ldap = 2 * DD;
            p.B0 = W2P + (long)l * 2 * DD * DD; p.ldbp = DD;
            p.C0 = x; p.ldc = DD;
            p.bias0 = b2 + l * DD;
            p.M = BT; p.N = DD; p.K = 4 * DD;
            launch_g<0, 1>(p, 1, 8);
        }
    }

    // final LN + tied-embedding logits (BIG NT)
    ln_pack_kernel<<<BT, 256>>>(x, hP, lnf_g, lnf_b);
    {
        GemmP p = base_p();
        p.A = hP; p.ldap = DP;
        p.B0 = tokP; p.ldbp = DP;
        p.C0 = out_logits; p.ldc = VV;
        p.M = BT; p.N = VV; p.K = DD;
        launch_g<1, 1>(p, 1);
    }
}

// round 17
// speedup vs baseline: 1.6231x; 1.0004x over previous
#include <cuda_runtime.h>
#include <cuda_bf16.h>
#include <cuda_fp16.h>
#include <math.h>
#include <stdint.h>

// ---------------- problem constants ----------------
#define BB   4
#define TT   256
#define TAA  1500
#define DD   768
#define HH   12
#define LL   12
#define VV   51865
#define DHH  64
#define BT   (BB*TT)          // 1024
#define DP   (DD/2)           // 384 pairs
#define SCALE_Q 0.125f
#define BTAD ((size_t)BB*TAA*DD)
#define NSPLIT 6

// ---------------- scratch ----------------
__device__ float g_x  [BT*DD];
__device__ float g_q  [BT*DD];
__device__ uint32_t g_ckP[(size_t)LL*BB*TAA*DP];   // cross K, fp16-hi packed
__device__ float g_cvall[(size_t)LL*BTAD];
__device__ float g_opart[(size_t)NSPLIT*BT*DD];
__device__ float2 g_msum[(size_t)NSPLIT*BB*HH*TT];

// A-side packed fp16 hi/lo (uint2: x=hi pair, y=lo pair)
__device__ uint2 g_hP  [(size_t)BT*DP];
__device__ uint2 g_oP  [(size_t)BT*DP];
__device__ uint2 g_hidP[(size_t)BT*2*DD];
__device__ uint2 g_xaP [(size_t)BB*TAA*DP];
// B-side packed fp16 hi-only
__device__ uint32_t g_tokP[(size_t)VV*DP];
__device__ uint32_t g_WqP [(size_t)LL*DP*DD];
__device__ uint32_t g_WkP [(size_t)LL*DP*DD];
__device__ uint32_t g_WvP [(size_t)LL*DP*DD];
__device__ uint32_t g_WoP [(size_t)LL*DP*DD];
__device__ uint32_t g_WcqP[(size_t)LL*DP*DD];
__device__ uint32_t g_WckP[(size_t)LL*DP*DD];
__device__ uint32_t g_WcvP[(size_t)LL*DP*DD];
__device__ uint32_t g_WcoP[(size_t)LL*DP*DD];
__device__ uint32_t g_W1P [(size_t)LL*DP*4*DD];
__device__ uint32_t g_W2P [(size_t)LL*2*DD*DD];

// ---------------- helpers ----------------
__device__ __forceinline__ uint32_t h2pack(float a, float b) {
    __half2 t = __floats2half2_rn(a, b);
    return *(uint32_t*)&t;
}

__device__ __forceinline__ void splitf16(float2 v, uint32_t& hi, uint32_t& lo) {
    __half hx = __float2half_rn(v.x);
    __half hy = __float2half_rn(v.y);
    __half2 h; h.x = hx; h.y = hy;
    hi = *(uint32_t*)&h;
    lo = h2pack(v.x - __half2float(hx), v.y - __half2float(hy));
}

__device__ __forceinline__ uint2 split2(float a, float b) {
    uint32_t hi, lo;
    splitf16(make_float2(a, b), hi, lo);
    return make_uint2(hi, lo);
}

__device__ __forceinline__ uint32_t lo_pack(float a, float b) {
    float ra = a - __half2float(__float2half_rn(a));
    float rb = b - __half2float(__float2half_rn(b));
    return h2pack(ra, rb);
}

__device__ __forceinline__ void mma_f16(float* c, const uint32_t* a, const uint32_t* b) {
    asm volatile(
        "mma.sync.aligned.m16n8k16.row.col.f32.f16.f16.f32 "
        "{%0,%1,%2,%3}, {%4,%5,%6,%7}, {%8,%9}, {%0,%1,%2,%3};"
        : "+f"(c[0]), "+f"(c[1]), "+f"(c[2]), "+f"(c[3])
        : "r"(a[0]), "r"(a[1]), "r"(a[2]), "r"(a[3]), "r"(b[0]), "r"(b[1]));
}

__device__ __forceinline__ void cp16(uint32_t saddr, const void* gptr, bool pred) {
    int sz = pred ? 16 : 0;
    asm volatile("cp.async.cg.shared.global [%0], [%1], 16, %2;"
                 :: "r"(saddr), "l"(gptr), "r"(sz));
}
#define CP_COMMIT() asm volatile("cp.async.commit_group;")
#define CP_WAIT(n)  asm volatile("cp.async.wait_group %0;" :: "n"(n))

// ---------------- prepack kernels (div/mod free) ----------------
__global__ __launch_bounds__(256) void pack_contig_kernel(
    const float* __restrict__ in, uint2* __restrict__ out, long n)
{
    long i = blockIdx.x * 256L + threadIdx.x;
    long stride = (long)gridDim.x * 256;
    for (; i < n; i += stride) {
        float2 v = ((const float2*)in)[i];
        uint32_t hi, lo; splitf16(v, hi, lo);
        out[i] = make_uint2(hi, lo);
    }
}

__global__ __launch_bounds__(256) void pack_contig_hi_kernel(
    const float* __restrict__ in, uint32_t* __restrict__ out, long n)
{
    long i = blockIdx.x * 256L + threadIdx.x;
    long stride = (long)gridDim.x * 256;
    for (; i < n; i += stride) {
        float2 v = ((const float2*)in)[i];
        out[i] = h2pack(v.x, v.y);
    }
}

template <int NCOLS>
__global__ __launch_bounds__(256) void pack_rows_hi_kernel(
    const float* __restrict__ in, uint32_t* __restrict__ out, int Khalf)
{
    long row = blockIdx.x;
    long l = row / Khalf;
    int kp = (int)(row - l * Khalf);
    const float* r0 = in + (l * (long)Khalf * 2 + 2 * kp) * NCOLS;
    const float* r1 = r0 + NCOLS;
    uint32_t* o = out + row * NCOLS;
#pragma unroll
    for (int it = 0; it < NCOLS / 256; it++) {
        int n = threadIdx.x + it * 256;
        o[n] = h2pack(r0[n], r1[n]);
    }
}

struct PackW { const float* src[8]; uint32_t* dst[8]; };
__global__ __launch_bounds__(256) void pack_w8_kernel(PackW p)
{
    const float* in = p.src[blockIdx.y];
    uint32_t* out = p.dst[blockIdx.y];
    long row = blockIdx.x;
    long l = row / DP;
    int kp = (int)(row - l * DP);
    const float* r0 = in + (l * (long)DD + 2 * kp) * DD;
    const float* r1 = r0 + DD;
    uint32_t* o = out + row * DD;
#pragma unroll
    for (int it = 0; it < 3; it++) {
        int n = threadIdx.x + it * 256;
        o[n] = h2pack(r0[n], r1[n]);
    }
}

// ---------------- packed fp16 GEMM (2-term) + split-K, 3-stage cp.async ----------------
struct GemmP {
    const uint2 *A;
    const uint32_t *B0, *B1, *B2;
    float *C0, *C1, *C2;
    uint2 *CP;
    uint32_t *CPh;
    const float *bias0, *bias1, *bias2;
    int M, N, K, ldap, ldbp, ldc, Hd, segW, act, splitK, kc;
    long sA0, sA1, sB0, sB1, sC0, sC1, sBias;
    float s0, s1, s2;
};

template <int NT, int BIG>
__global__ __launch_bounds__(BIG ? 512 : 256, BIG ? 1 : 2) void gemm_f16_kernel(GemmP p)
{
    constexpr int BN    = BIG ? 128 : 64;
    constexpr int NTHR  = BIG ? 512 : 256;
    constexpr int TBKv  = BIG ? 64 : 32;
    constexpr int KP    = TBKv / 2;
    constexpr int ALD2  = BIG ? 36 : 20;
    constexpr int BLD1  = BIG ? 36 : 20;
    constexpr int BLDN1 = BIG ? 132 : 68;
    constexpr int ACH   = 128 * (KP / 2) / NTHR;
    constexpr int BCHT  = BN * (KP / 4) / NTHR;
    constexpr int BCHN  = (KP * (BN / 4)) / NTHR;
    constexpr int AAREA2 = 128 * ALD2;
    constexpr int BAREA1 = BIG ? 4608 : 1280;
    constexpr int STAGE1 = AAREA2 * 2 + BAREA1;

    extern __shared__ uint32_t dsm1[];

    int z = blockIdx.z;
    int sk = z % p.splitK;
    int zz = z / p.splitK;
    int zb = zz / p.Hd, zh = zz % p.Hd;
    int bm = blockIdx.y * 128, bn = blockIdx.x * BN;
    int seg = bn / p.segW;
    int bnl = bn - seg * p.segW;

    const uint2* A = p.A + zb * p.sA0 + zh * p.sA1;
    const uint32_t* B = (seg == 0 ? p.B0 : seg == 1 ? p.B1 : p.B2) + zb * p.sB0 + zh * p.sB1;
    float* C = (seg == 0 ? p.C0 : seg == 1 ? p.C1 : p.C2) + zb * p.sC0 + zh * p.sC1;
    uint32_t* Ch = p.CPh ? p.CPh + ((zb * p.sC0 + zh * p.sC1) >> 1) : nullptr;
    const float* bias = (seg == 0 ? p.bias0 : seg == 1 ? p.bias1 : p.bias2);
    if (bias) bias += zh * p.sBias;
    float scl = seg == 0 ? p.s0 : seg == 1 ? p.s1 : p.s2;
    bool atom = p.splitK > 1;

    int M = p.M, N = p.N;
    int ldap = p.ldap, ldbp = p.ldbp, ldc = p.ldc;
    int kpstart = (sk * p.kc) >> 1;
    int kpend = min(p.K, sk * p.kc + p.kc) >> 1;

    int tid  = threadIdx.x;
    int lane = tid & 31;
    int warp = tid >> 5;
    int g    = lane >> 2;
    int tig  = lane & 3;
    int m0w  = (warp & 3) * 32;
    int n0w  = (warp >> 2) * 32;

    uint32_t smemBase = (uint32_t)__cvta_generic_to_shared(dsm1);

    float c[2][4][4];
#pragma unroll
    for (int mi = 0; mi < 2; mi++)
#pragma unroll
        for (int ni = 0; ni < 4; ni++)
#pragma unroll
            for (int e = 0; e < 4; e++) c[mi][ni][e] = 0.f;

    int iters = (kpend - kpstart + KP - 1) / KP;

    auto issue_stage = [&](int it, int s) {
        int kp0 = kpstart + it * KP;
        uint32_t aBase = smemBase + (uint32_t)s * STAGE1 * 4u;
        uint32_t bBase = aBase + (uint32_t)AAREA2 * 8u;
#pragma unroll
        for (int i = 0; i < ACH; i++) {
            int cix = i * NTHR + tid;
            int r, k2;
            if (BIG) { r = cix >> 4; k2 = cix & 15; }
            else     { r = cix >> 3; k2 = cix & 7; }
            int kp = 2 * k2;
            int gr = bm + r, kpg = kp0 + kp;
            bool ok = (gr < M) && (kpg < kpend);
            cp16(aBase + (uint32_t)(r * ALD2 + kp) * 8u,
                 A + (long)gr * ldap + kpg, ok);
        }
        if (NT) {
#pragma unroll
            for (int i = 0; i < BCHT; i++) {
                int cix = i * NTHR + tid;
                int n, k4;
                if (BIG) { n = cix >> 3; k4 = cix & 7; }
                else     { n = cix >> 2; k4 = cix & 3; }
                int kp = 4 * k4;
                int kpg = kp0 + kp;
                bool ok = (bn + n < N) && (kpg < kpend);
                cp16(bBase + (uint32_t)(n * BLD1 + kp) * 4u,
                     B + (long)(bnl + n) * ldbp + kpg, ok);
            }
        } else {
#pragma unroll
            for (int i = 0; i < BCHN; i++) {
                int cix = i * NTHR + tid;
                int kp, n4;
                if (BIG) { kp = cix >> 5; n4 = cix & 31; }
                else     { kp = cix >> 4; n4 = cix & 15; }
                int n = 4 * n4;
                int kpg = kp0 + kp;
                bool ok = (bn + n < N) && (kpg < kpend);
                cp16(bBase + (uint32_t)(kp * BLDN1 + n) * 4u,
                     B + (long)kpg * ldbp + bnl + n, ok);
            }
        }
        CP_COMMIT();
    };

    if (iters > 0) issue_stage(0, 0);
    if (iters > 1) issue_stage(1, 1);

    for (int it = 0; it < iters; it++) {
        if (it + 2 < iters) issue_stage(it + 2, (it + 2) % 3);
        int rem = iters - 1 - it;
        if (rem >= 2)      CP_WAIT(2);
        else if (rem == 1) CP_WAIT(1);
        else               CP_WAIT(0);
        __syncthreads();

        int s = it % 3;
        const uint2* As = (const uint2*)(dsm1 + s * STAGE1);
        const uint32_t* Bs = dsm1 + s * STAGE1 + AAREA2 * 2;

#pragma unroll
        for (int h = 0; h < TBKv / 16; h++) {
            int kb = h * 8;
            uint32_t aH4[2][4], aL4[2][4];
#pragma unroll
            for (int mi = 0; mi < 2; mi++) {
                int m = m0w + mi * 16 + g;
                uint2 t0 = As[(m    ) * ALD2 + kb + tig];
                uint2 t1 = As[(m + 8) * ALD2 + kb + tig];
                uint2 t2 = As[(m    ) * ALD2 + kb + tig + 4];
                uint2 t3 = As[(m + 8) * ALD2 + kb + tig + 4];
                aH4[mi][0] = t0.x; aH4[mi][1] = t1.x; aH4[mi][2] = t2.x; aH4[mi][3] = t3.x;
                aL4[mi][0] = t0.y; aL4[mi][1] = t1.y; aL4[mi][2] = t2.y; aL4[mi][3] = t3.y;
            }
            uint32_t bh2[4][2];
#pragma unroll
            for (int ni = 0; ni < 4; ni++) {
                int n = n0w + ni * 8 + g;
                if (NT) {
                    bh2[ni][0] = Bs[n * BLD1 + kb + tig];
                    bh2[ni][1] = Bs[n * BLD1 + kb + tig + 4];
                } else {
                    bh2[ni][0] = Bs[(kb + tig) * BLDN1 + n];
                    bh2[ni][1] = Bs[(kb + tig + 4) * BLDN1 + n];
                }
            }
#pragma unroll
            for (int mi = 0; mi < 2; mi++)
#pragma unroll
                for (int ni = 0; ni < 4; ni++) {
                    mma_f16(c[mi][ni], aL4[mi], bh2[ni]);
                    mma_f16(c[mi][ni], aH4[mi], bh2[ni]);
                }
        }
        __syncthreads();
    }

    // ---- epilogue ----
    if (p.CP || Ch) {
        int ldcp = ldc >> 1;
#pragma unroll
        for (int mi = 0; mi < 2; mi++) {
#pragma unroll
            for (int ni = 0; ni < 4; ni++) {
                float v[4];
#pragma unroll
                for (int e = 0; e < 4; e++) {
                    int lc = bn + n0w + ni * 8 + tig * 2 + (e & 1);
                    float t = c[mi][ni][e];
                    if (bias) t += bias[lc];
                    t *= scl;
                    if (p.act == 1) t = 0.5f * t * (1.f + erff(t * 0.70710678118654752f));
                    v[e] = t;
                }
                int row0 = bm + m0w + mi * 16 + g;
                int pc = (bn + n0w + ni * 8) / 2 + tig;
                if (p.CP) {
                    if (row0 < M)     p.CP[(long)row0 * ldcp + pc]       = split2(v[0], v[1]);
                    if (row0 + 8 < M) p.CP[(long)(row0 + 8) * ldcp + pc] = split2(v[2], v[3]);
                } else {
                    if (row0 < M)     Ch[(long)row0 * ldcp + pc]       = h2pack(v[0], v[1]);
                    if (row0 + 8 < M) Ch[(long)(row0 + 8) * ldcp + pc] = h2pack(v[2], v[3]);
                }
            }
        }
    } else {
#pragma unroll
        for (int mi = 0; mi < 2; mi++) {
#pragma unroll
            for (int ni = 0; ni < 4; ni++) {
#pragma unroll
                for (int e = 0; e < 4; e++) {
                    int row = bm + m0w + mi * 16 + g + ((e >= 2) ? 8 : 0);
                    int gcol = bn + n0w + ni * 8 + tig * 2 + (e & 1);
                    if (row >= M || gcol >= N) continue;
                    int lc = gcol - seg * p.segW;
                    float v = c[mi][ni][e];
                    if (bias && (!atom || sk == 0)) v += bias[lc];
                    v *= scl;
                    long ci = (long)row * ldc + lc;
                    if (atom) {
                        atomicAdd(&C[ci], v);
                    } else {
                        if (p.act == 1) v = 0.5f * v * (1.f + erff(v * 0.70710678118654752f));
                        C[ci] = v;
                    }
                }
            }
        }
    }
}

// ---------------- fused flash attention (fp16 2-term; K optionally pre-packed) ----------------
__global__ __launch_bounds__(128) void flash_kernel(
    const float* __restrict__ Qb, const float* __restrict__ Kb,
    const uint32_t* __restrict__ KbP,
    const float* __restrict__ Vb, uint2* __restrict__ OPk,
    float* __restrict__ mir, int lenKV, long kvBStride, int causal,
    float* __restrict__ Opart, float2* __restrict__ Msum, int kvChunk)
{
    __shared__ uint32_t Kh[64][36];
    __shared__ uint32_t Vh[64][33];

    int mt = blockIdx.x;
    int by = blockIdx.y;
    int sp = blockIdx.z;
    int b = by / HH, hh = by % HH;

    int kvStart = sp * kvChunk;
    int kvEnd = min(lenKV, kvStart + kvChunk);

    const float* Q = Qb + ((long)b * TT + mt * 64) * DD + hh * DHH;
    const float* K = Kb ? Kb + (long)b * kvBStride + hh * DHH : nullptr;
    const uint32_t* KP2 = KbP ? KbP + (long)b * TAA * DP + hh * 32 : nullptr;
    const float* V = Vb + (long)b * kvBStride + hh * DHH;
    float* Mr = (mir && b == 0)
              ? mir + (size_t)hh * TT * TAA + (size_t)mt * 64 * TAA : nullptr;

    int tid = threadIdx.x;
    int lane = tid & 31, warp = tid >> 5;
    int g = lane >> 2, tig = lane & 3;
    int m0w = warp * 16;

    uint32_t Qah[4][4], Qal[4][4];
#pragma unroll
    for (int kb = 0; kb < 4; kb++) {
        int c0 = 16 * kb + 2 * tig;
        const float* r0 = Q + (long)(m0w + g) * DD;
        const float* r1 = Q + (long)(m0w + g + 8) * DD;
        float2 v;
        v = *(const float2*)(r0 + c0);     splitf16(v, Qah[kb][0], Qal[kb][0]);
        v = *(const float2*)(r1 + c0);     splitf16(v, Qah[kb][1], Qal[kb][1]);
        v = *(const float2*)(r0 + c0 + 8); splitf16(v, Qah[kb][2], Qal[kb][2]);
        v = *(const float2*)(r1 + c0 + 8); splitf16(v, Qah[kb][3], Qal[kb][3]);
    }

    float acc[8][4];
#pragma unroll
    for (int j = 0; j < 8; j++)
#pragma unroll
        for (int e = 0; e < 4; e++) acc[j][e] = 0.f;
    float m0 = -1e30f, m1 = -1e30f, sum0 = 0.f, sum1 = 0.f;

    int chBeg = kvStart >> 6;
    int chEnd = (kvEnd + 63) >> 6;
    if (causal) chEnd = min(chEnd, mt + 1);

    for (int ch = chBeg; ch < chEnd; ch++) {
        int n0 = ch * 64;
        if (KP2) {
#pragma unroll
            for (int i = 0; i < 16; i++) {
                int idx = i * 128 + tid;
                int r = idx >> 5, c = idx & 31;
                Kh[r][c] = (n0 + r < kvEnd) ? KP2[(long)(n0 + r) * DP + c] : 0u;
            }
        } else {
#pragma unroll
            for (int i = 0; i < 16; i++) {
                int idx = i * 128 + tid;
                int r = idx >> 5, c = idx & 31;
                float2 v = {0.f, 0.f};
                if (n0 + r < kvEnd) v = *(const float2*)(K + (long)(n0 + r) * DD + 2 * c);
                Kh[r][c] = h2pack(v.x, v.y);
            }
        }
#pragma unroll
        for (int i = 0; i < 16; i++) {
            int idx = i * 128 + tid;
            int d = idx & 63, pr = idx >> 6;
            float2 v = {0.f, 0.f};
            int r0i = n0 + 2 * pr;
            if (r0i < kvEnd)     v.x = V[(long)r0i * DD + d];
            if (r0i + 1 < kvEnd) v.y = V[(long)(r0i + 1) * DD + d];
            Vh[d][pr] = h2pack(v.x, v.y);
        }
        __syncthreads();

        float s[8][4];
#pragma unroll
        for (int j = 0; j < 8; j++)
#pragma unroll
            for (int e = 0; e < 4; e++) s[j][e] = 0.f;
#pragma unroll
        for (int kb = 0; kb < 4; kb++) {
#pragma unroll
            for (int j = 0; j < 8; j++) {
                uint32_t bh[2] = { Kh[8 * j + g][8 * kb + tig], Kh[8 * j + g][8 * kb + tig + 4] };
                mma_f16(s[j], Qal[kb], bh);
                mma_f16(s[j], Qah[kb], bh);
            }
        }

        if (Mr) {
#pragma unroll
            for (int j = 0; j < 8; j++) {
                int col = n0 + 8 * j + 2 * tig;
                if (col < kvEnd) {
                    float2 v0 = { s[j][0], s[j][1] };
                    float2 v1 = { s[j][2], s[j][3] };
                    *(float2*)&Mr[(long)(m0w + g) * TAA + col] = v0;
                    *(float2*)&Mr[(long)(m0w + g + 8) * TAA + col] = v1;
                }
            }
        }

        if (causal && ch == mt) {
            int t0 = mt * 64 + m0w + g;
#pragma unroll
            for (int j = 0; j < 8; j++) {
                int col = n0 + 8 * j + 2 * tig;
                if (col     > t0)     s[j][0] = -1e30f;
                if (col + 1 > t0)     s[j][1] = -1e30f;
                if (col     > t0 + 8) s[j][2] = -1e30f;
                if (col + 1 > t0 + 8) s[j][3] = -1e30f;
            }
        }
        if (n0 + 64 > kvEnd) {
#pragma unroll
            for (int j = 0; j < 8; j++) {
                int col = n0 + 8 * j + 2 * tig;
                if (col     >= kvEnd) { s[j][0] = -1e30f; s[j][2] = -1e30f; }
                if (col + 1 >= kvEnd) { s[j][1] = -1e30f; s[j][3] = -1e30f; }
            }
        }

        float mx0 = -1e30f, mx1 = -1e30f;
#pragma unroll
        for (int j = 0; j < 8; j++) {
            mx0 = fmaxf(mx0, fmaxf(s[j][0], s[j][1]));
            mx1 = fmaxf(mx1, fmaxf(s[j][2], s[j][3]));
        }
        mx0 = fmaxf(mx0, __shfl_xor_sync(0xffffffffu, mx0, 1));
        mx0 = fmaxf(mx0, __shfl_xor_sync(0xffffffffu, mx0, 2));
        mx1 = fmaxf(mx1, __shfl_xor_sync(0xffffffffu, mx1, 1));
        mx1 = fmaxf(mx1, __shfl_xor_sync(0xffffffffu, mx1, 2));
        float mn0 = fmaxf(m0, mx0), mn1 = fmaxf(m1, mx1);
        float a0 = __expf(m0 - mn0), a1 = __expf(m1 - mn1);
        float ps0 = 0.f, ps1 = 0.f;
#pragma unroll
        for (int j = 0; j < 8; j++) {
            s[j][0] = __expf(s[j][0] - mn0);
            s[j][1] = __expf(s[j][1] - mn0);
            s[j][2] = __expf(s[j][2] - mn1);
            s[j][3] = __expf(s[j][3] - mn1);
            ps0 += s[j][0] + s[j][1];
            ps1 += s[j][2] + s[j][3];
        }
        ps0 += __shfl_xor_sync(0xffffffffu, ps0, 1);
        ps0 += __shfl_xor_sync(0xffffffffu, ps0, 2);
        ps1 += __shfl_xor_sync(0xffffffffu, ps1, 1);
        ps1 += __shfl_xor_sync(0xffffffffu, ps1, 2);
        sum0 = sum0 * a0 + ps0;
        sum1 = sum1 * a1 + ps1;
        m0 = mn0; m1 = mn1;
#pragma unroll
        for (int j = 0; j < 8; j++) {
            acc[j][0] *= a0; acc[j][1] *= a0;
            acc[j][2] *= a1; acc[j][3] *= a1;
        }

#pragma unroll
        for (int kb = 0; kb < 4; kb++) {
            int j0 = 2 * kb, j1 = 2 * kb + 1;
            uint32_t Ah[4], Al[4];
            Ah[0] = h2pack(s[j0][0], s[j0][1]);  Al[0] = lo_pack(s[j0][0], s[j0][1]);
            Ah[1] = h2pack(s[j0][2], s[j0][3]);  Al[1] = lo_pack(s[j0][2], s[j0][3]);
            Ah[2] = h2pack(s[j1][0], s[j1][1]);  Al[2] = lo_pack(s[j1][0], s[j1][1]);
            Ah[3] = h2pack(s[j1][2], s[j1][3]);  Al[3] = lo_pack(s[j1][2], s[j1][3]);
#pragma unroll
            for (int jd = 0; jd < 8; jd++) {
                uint32_t bh[2] = { Vh[8 * jd + g][8 * kb + tig], Vh[8 * jd + g][8 * kb + tig + 4] };
                mma_f16(acc[jd], Al, bh);
                mma_f16(acc[jd], Ah, bh);
            }
        }
        __syncthreads();
    }

    if (Opart) {
        float* OP = Opart + (((long)sp * BT) + (long)b * TT + mt * 64) * DD + hh * DHH;
#pragma unroll
        for (int jd = 0; jd < 8; jd++) {
            int col = 8 * jd + 2 * tig;
            float2 v0 = { acc[jd][0], acc[jd][1] };
            float2 v1 = { acc[jd][2], acc[jd][3] };
            *(float2*)&OP[(long)(m0w + g) * DD + col] = v0;
            *(float2*)&OP[(long)(m0w + g + 8) * DD + col] = v1;
        }
        if (tig == 0) {
            long base = (((long)sp * BB + b) * HH + hh) * TT + mt * 64;
            Msum[base + m0w + g]     = make_float2(m0, sum0);
            Msum[base + m0w + g + 8] = make_float2(m1, sum1);
        }
    } else {
        uint2* O2 = OPk + ((long)b * TT + mt * 64) * DP + hh * 32;
        float i0 = 1.f / sum0, i1 = 1.f / sum1;
#pragma unroll
        for (int jd = 0; jd < 8; jd++) {
            int pc = 4 * jd + tig;
            O2[(long)(m0w + g) * DP + pc]     = split2(acc[jd][0] * i0, acc[jd][1] * i0);
            O2[(long)(m0w + g + 8) * DP + pc] = split2(acc[jd][2] * i1, acc[jd][3] * i1);
        }
    }
}

__global__ __launch_bounds__(256) void flash_merge_kernel(
    const float* __restrict__ Opart, const float2* __restrict__ Msum,
    uint2* __restrict__ OPk)
{
    __shared__ float wgt[HH][NSPLIT];
    int row = blockIdx.x;
    int b = row / TT, t = row % TT;
    int tid = threadIdx.x;
    if (tid < HH) {
        int h = tid;
        float ms[NSPLIT], ss[NSPLIT];
        float m = -1e30f;
#pragma unroll
        for (int s = 0; s < NSPLIT; s++) {
            float2 v = Msum[(((long)s * BB + b) * HH + h) * TT + t];
            ms[s] = v.x; ss[s] = v.y;
            m = fmaxf(m, v.x);
        }
        float den = 0.f;
#pragma unroll
        for (int s = 0; s < NSPLIT; s++) den += ss[s] * __expf(ms[s] - m);
        float iden = 1.f / den;
#pragma unroll
        for (int s = 0; s < NSPLIT; s++) wgt[h][s] = __expf(ms[s] - m) * iden;
    }
    __syncthreads();
#pragma unroll
    for (int it = 0; it < 2; it++) {
        int pd = tid + it * 256;
        if (pd >= DP) break;
        int h = pd >> 5;
        float a0 = 0.f, a1 = 0.f;
#pragma unroll
        for (int s = 0; s < NSPLIT; s++) {
            const float* op = &Opart[(((long)s * BT) + row) * DD + 2 * pd];
            a0 += op[0] * wgt[h][s];
            a1 += op[1] * wgt[h][s];
        }
        OPk[(long)row * DP + pd] = split2(a0, a1);
    }
}

// ---------------- elementwise / row kernels ----------------
__global__ __launch_bounds__(256) void embed_kernel(
    const int* __restrict__ tokens, const float* __restrict__ tok_emb,
    const float* __restrict__ pos_emb, float* __restrict__ x)
{
    int row = blockIdx.x;
    int t = row % TT;
    int tok = tokens[row];
    const float* te = tok_emb + (long)tok * DD;
    const float* pe = pos_emb + (long)t * DD;
    float* xr = x + (long)row * DD;
#pragma unroll
    for (int it = 0; it < 3; it++) {
        int j = threadIdx.x + it * 256;
        xr[j] = te[j] + pe[j];
    }
}

__global__ __launch_bounds__(256) void ln_pack_kernel(
    const float* __restrict__ x, uint2* __restrict__ y,
    const float* __restrict__ g, const float* __restrict__ b)
{
    __shared__ float red[256];
    int row = blockIdx.x;
    const float* xr = x + (long)row * DD;
    uint2* yr = y + (long)row * DP;
    int tid = threadIdx.x;
    float v0 = xr[tid], v1 = xr[tid + 256], v2 = xr[tid + 512];
    float s = v0 + v1 + v2;
    red[tid] = s; __syncthreads();
    for (int st = 128; st > 0; st >>= 1) { if (tid < st) red[tid] += red[tid + st]; __syncthreads(); }
    float mean = red[0] * (1.f / DD);
    __syncthreads();
    float d0 = v0 - mean, d1 = v1 - mean, d2 = v2 - mean;
    red[tid] = d0 * d0 + d1 * d1 + d2 * d2; __syncthreads();
    for (int st = 128; st > 0; st >>= 1) { if (tid < st) red[tid] += red[tid + st]; __syncthreads(); }
    float inv = rsqrtf(red[0] * (1.f / DD) + 1e-5f);
    {
        int c0 = 2 * tid;
        float a = (xr[c0]     - mean) * inv * g[c0]     + b[c0];
        float c = (xr[c0 + 1] - mean) * inv * g[c0 + 1] + b[c0 + 1];
        yr[tid] = split2(a, c);
    }
    if (tid < 128) {
        int p1 = tid + 256;
        int c0 = 2 * p1;
        float a = (xr[c0]     - mean) * inv * g[c0]     + b[c0];
        float c = (xr[c0 + 1] - mean) * inv * g[c0 + 1] + b[c0 + 1];
        yr[p1] = split2(a, c);
    }
}

// ---------------- host-side launch helpers ----------------
static GemmP base_p() {
    GemmP p;
    p.A = nullptr; p.B0 = p.B1 = p.B2 = nullptr;
    p.C0 = p.C1 = p.C2 = nullptr; p.CP = nullptr; p.CPh = nullptr;
    p.bias0 = p.bias1 = p.bias2 = nullptr;
    p.M = p.N = p.K = 0; p.ldap = p.ldbp = p.ldc = 0;
    p.Hd = 1; p.segW = 1 << 30; p.act = 0; p.splitK = 1; p.kc = 0;
    p.sA0 = p.sA1 = p.sB0 = p.sB1 = p.sC0 = p.sC1 = p.sBias = 0;
    p.s0 = p.s1 = p.s2 = 1.f;
    return p;
}

static inline int smem_bytes(int BIG) {
    int ALD2 = BIG ? 36 : 20;
    int AAREA2 = 128 * ALD2;
    int BAREA1 = BIG ? 4608 : 1280;
    return 3 * (AAREA2 * 2 + BAREA1) * 4;
}

template <int NT, int BIG>
static inline void launch_g(GemmP p, int batch, int splitK = 1) {
    p.splitK = splitK;
    constexpr int TBKv = BIG ? 64 : 32;
    int kc = (p.K + splitK - 1) / splitK;
    p.kc = ((kc + TBKv - 1) / TBKv) * TBKv;
    constexpr int BN = BIG ? 128 : 64;
    constexpr int NTHR = BIG ? 512 : 256;
    dim3 grd((p.N + BN - 1) / BN, (p.M + 127) / 128, batch * splitK);
    gemm_f16_kernel<NT, BIG><<<grd, NTHR, smem_bytes(BIG)>>>(p);
}

static inline int pkblocks(long n) {
    long b = (n + 255) / 256;
    return (int)(b > 8192 ? 8192 : b);
}

extern "C" void kernel_launch(void* const* d_in, const int* in_sizes, int n_in,
                              void* d_out, int out_size)
{
    (void)in_sizes; (void)n_in; (void)out_size;

    cudaFuncSetAttribute(gemm_f16_kernel<0, 0>, cudaFuncAttributeMaxDynamicSharedMemorySize, smem_bytes(0));
    cudaFuncSetAttribute(gemm_f16_kernel<1, 0>, cudaFuncAttributeMaxDynamicSharedMemorySize, smem_bytes(0));
    cudaFuncSetAttribute(gemm_f16_kernel<0, 1>, cudaFuncAttributeMaxDynamicSharedMemorySize, smem_bytes(1));
    cudaFuncSetAttribute(gemm_f16_kernel<1, 1>, cudaFuncAttributeMaxDynamicSharedMemorySize, smem_bytes(1));

    const int*   tokens  = (const int*)  d_in[0];
    const float* xa      = (const float*)d_in[1];
    const float* tok_emb = (const float*)d_in[2];
    const float* pos_emb = (const float*)d_in[3];
    const float* Wq      = (const float*)d_in[4];
    const float* bq      = (const float*)d_in[5];
    const float* Wk      = (const float*)d_in[6];
    const float* Wv      = (const float*)d_in[7];
    const float* bv      = (const float*)d_in[8];
    const float* Wo      = (const float*)d_in[9];
    const float* bo      = (const float*)d_in[10];
    const float* ln1_g   = (const float*)d_in[11];
    const float* ln1_b   = (const float*)d_in[12];
    const float* Wcq     = (const float*)d_in[13];
    const float* bcq     = (const float*)d_in[14];
    const float* Wck     = (const float*)d_in[15];
    const float* Wcv     = (const float*)d_in[16];
    const float* bcv     = (const float*)d_in[17];
    const float* Wco     = (const float*)d_in[18];
    const float* bco     = (const float*)d_in[19];
    const float* ln2_g   = (const float*)d_in[20];
    const float* ln2_b   = (const float*)d_in[21];
    const float* W1      = (const float*)d_in[22];
    const float* b1      = (const float*)d_in[23];
    const float* W2      = (const float*)d_in[24];
    const float* b2      = (const float*)d_in[25];
    const float* ln3_g   = (const float*)d_in[26];
    const float* ln3_b   = (const float*)d_in[27];
    const float* lnf_g   = (const float*)d_in[28];
    const float* lnf_b   = (const float*)d_in[29];

    float* out = (float*)d_out;
    float* out_logits = out;
    float* out_chw    = out_logits + (size_t)BB * TT * VV;
    float* out_kv     = out_chw + (size_t)(LL / 2) * HH * TT * TAA;

    float *x, *q, *cvall, *opart;
    float2* msum;
    uint2 *hP, *oP, *hidP, *xaP;
    uint32_t *ckP, *tokP, *WqP, *WkP, *WvP, *WoP, *WcqP, *WckP, *WcvP, *WcoP, *W1P, *W2P;
    cudaGetSymbolAddress((void**)&x,     g_x);
    cudaGetSymbolAddress((void**)&q,     g_q);
    cudaGetSymbolAddress((void**)&ckP,   g_ckP);
    cudaGetSymbolAddress((void**)&cvall, g_cvall);
    cudaGetSymbolAddress((void**)&opart, g_opart);
    cudaGetSymbolAddress((void**)&msum,  g_msum);
    cudaGetSymbolAddress((void**)&hP,    g_hP);
    cudaGetSymbolAddress((void**)&oP,    g_oP);
    cudaGetSymbolAddress((void**)&hidP,  g_hidP);
    cudaGetSymbolAddress((void**)&xaP,   g_xaP);
    cudaGetSymbolAddress((void**)&tokP,  g_tokP);
    cudaGetSymbolAddress((void**)&WqP,   g_WqP);
    cudaGetSymbolAddress((void**)&WkP,   g_WkP);
    cudaGetSymbolAddress((void**)&WvP,   g_WvP);
    cudaGetSymbolAddress((void**)&WoP,   g_WoP);
    cudaGetSymbolAddress((void**)&WcqP,  g_WcqP);
    cudaGetSymbolAddress((void**)&WckP,  g_WckP);
    cudaGetSymbolAddress((void**)&WcvP,  g_WcvP);
    cudaGetSymbolAddress((void**)&WcoP,  g_WcoP);
    cudaGetSymbolAddress((void**)&W1P,   g_W1P);
    cudaGetSymbolAddress((void**)&W2P,   g_W2P);

    // ---- prepack ----
    {
        long n;
        n = (long)BB * TAA * DP;
        pack_contig_kernel<<<pkblocks(n), 256>>>(xa, xaP, n);
        n = (long)VV * DP;
        pack_contig_hi_kernel<<<pkblocks(n), 256>>>(tok_emb, tokP, n);

        PackW pw;
        pw.src[0] = Wq;  pw.dst[0] = WqP;
        pw.src[1] = Wk;  pw.dst[1] = WkP;
        pw.src[2] = Wv;  pw.dst[2] = WvP;
        pw.src[3] = Wo;  pw.dst[3] = WoP;
        pw.src[4] = Wcq; pw.dst[4] = WcqP;
        pw.src[5] = Wck; pw.dst[5] = WckP;
        pw.src[6] = Wcv; pw.dst[6] = WcvP;
        pw.src[7] = Wco; pw.dst[7] = WcoP;
        pack_w8_kernel<<<dim3(LL * DP, 8), 256>>>(pw);

        pack_rows_hi_kernel<4 * DD><<<LL * DP, 256>>>(W1, W1P, DP);
        pack_rows_hi_kernel<DD><<<LL * 2 * DD, 256>>>(W2, W2P, 2 * DD);
    }

    embed_kernel<<<BT, 256>>>(tokens, tok_emb, pos_emb, x);

    const long DTD = (long)TT * DD;
    const size_t XBYTES = (size_t)BT * DD * sizeof(float);
    const int KVCH = ((TAA + NSPLIT * 64 - 1) / (NSPLIT * 64)) * 64;   // 256

    // cross K/V for ALL layers, batched over z=12 (BIG)
    {
        GemmP p = base_p();
        p.A = xaP; p.ldap = DP;
        p.B0 = WckP; p.ldbp = DD; p.sB1 = (long)DP * DD;
        p.CPh = ckP; p.ldc = DD; p.sC1 = (long)BB * TAA * DD;
        p.M = BB * TAA; p.N = DD; p.K = DD; p.Hd = LL;
        launch_g<0, 1>(p, LL);

        GemmP pv = base_p();
        pv.A = xaP; pv.ldap = DP;
        pv.B0 = WcvP; pv.ldbp = DD; pv.sB1 = (long)DP * DD;
        pv.C0 = cvall; pv.ldc = DD; pv.sC1 = (long)BTAD;
        pv.bias0 = bcv; pv.sBias = DD;
        pv.M = BB * TAA; pv.N = DD; pv.K = DD; pv.Hd = LL;
        launch_g<0, 1>(pv, LL);
    }

    for (int l = 0; l < LL; l++) {
        float* kout = out_kv + (size_t)(2 * l) * BT * DD;
        float* vout = out_kv + (size_t)(2 * l + 1) * BT * DD;
        uint32_t* ckP_l = ckP + (size_t)l * BB * TAA * DP;
        float* cv_l = cvall + (size_t)l * BTAD;
        const long WOFF = (long)l * DP * DD;

        // ---- self attention ----
        ln_pack_kernel<<<BT, 256>>>(x, hP, ln1_g + l * DD, ln1_b + l * DD);
        {   // fused QKV (small tiles, 2 CTAs/SM)
            GemmP p = base_p();
            p.A = hP; p.ldap = DP;
            p.B0 = WqP + WOFF; p.B1 = WkP + WOFF; p.B2 = WvP + WOFF; p.ldbp = DD;
            p.C0 = q; p.C1 = kout; p.C2 = vout; p.ldc = DD;
            p.bias0 = bq + l * DD; p.bias1 = nullptr; p.bias2 = bv + l * DD;
            p.s0 = SCALE_Q; p.s1 = 1.f; p.s2 = 1.f;
            p.segW = DD;
            p.M = BT; p.N = 3 * DD; p.K = DD;
            launch_g<0, 0>(p, 1);
        }
        flash_kernel<<<dim3(TT / 64, BB * HH, 1), 128>>>(
            q, kout, nullptr, vout, oP, nullptr, TT, DTD, 1, nullptr, nullptr, TT);
        {   // x += o @ Wo + bo
            GemmP p = base_p();
            p.A = oP; p.ldap = DP;
            p.B0 = WoP + WOFF; p.ldbp = DD;
            p.C0 = x; p.ldc = DD;
            p.bias0 = bo + l * DD;
            p.M = BT; p.N = DD; p.K = DD;
            launch_g<0, 0>(p, 1, 4);
        }

        // ---- cross attention ----
        ln_pack_kernel<<<BT, 256>>>(x, hP, ln2_g + l * DD, ln2_b + l * DD);
        cudaMemsetAsync(q, 0, XBYTES);
        {   // q2
            GemmP p = base_p();
            p.A = hP; p.ldap = DP;
            p.B0 = WcqP + WOFF; p.ldbp = DD;
            p.C0 = q; p.ldc = DD;
            p.bias0 = bcq + l * DD; p.s0 = SCALE_Q;
            p.M = BT; p.N = DD; p.K = DD;
            launch_g<0, 0>(p, 1, 4);
        }
        {
            float* mir = (l >= LL / 2)
                       ? out_chw + (size_t)(l - LL / 2) * HH * TT * TAA : nullptr;
            flash_kernel<<<dim3(TT / 64, BB * HH, NSPLIT), 128>>>(
                q, nullptr, ckP_l, cv_l, nullptr, mir, TAA, (long)TAA * DD, 0,
                opart, msum, KVCH);
            flash_merge_kernel<<<BT, 256>>>(opart, msum, oP);
        }
        {   // x += o @ Wco + bco
            GemmP p = base_p();
            p.A = oP; p.ldap = DP;
            p.B0 = WcoP + WOFF; p.ldbp = DD;
            p.C0 = x; p.ldc = DD;
            p.bias0 = bco + l * DD;
            p.M = BT; p.N = DD; p.K = DD;
            launch_g<0, 0>(p, 1, 4);
        }

        // ---- MLP ----
        ln_pack_kernel<<<BT, 256>>>(x, hP, ln3_g + l * DD, ln3_b + l * DD);
        {   // hidP (small tiles, packed epilogue)
            GemmP p = base_p();
            p.A = hP; p.ldap = DP;
            p.B0 = W1P + (long)l * DP * 4 * DD; p.ldbp = 4 * DD;
            p.CP = hidP; p.ldc = 4 * DD;
            p.bias0 = b1 + (size_t)l * 4 * DD; p.act = 1;
            p.M = BT; p.N = 4 * DD; p.K = DD;
            launch_g<0, 0>(p, 1);
        }
        {   // x += hid @ W2 + b2 (BIG, split-K 8)
            GemmP p = base_p();
            p.A = hidP; p.ldap = 2 * DD;
            p.B0 = W2P + (long)l * 2 * DD * DD; p.ldbp = DD;
            p.C0 = x; p.ldc = DD;
            p.bias0 = b2 + l * DD;
            p.M = BT; p.N = DD; p.K = 4 * DD;
            launch_g<0, 1>(p, 1, 8);
        }
    }

    // final LN + tied-embedding logits (BIG NT)
    ln_pack_kernel<<<BT, 256>>>(x, hP, lnf_g, lnf_b);
    {
        GemmP p = base_p();
        p.A = hP; p.ldap = DP;
        p.B0 = tokP; p.ldbp = DP;
        p.C0 = out_logits; p.ldc = VV;
        p.M = BT; p.N = VV; p.K = DD;
        launch_g<1, 1>(p, 1);
    }
}